// round 8
// baseline (speedup 1.0000x reference)
#include <cuda_runtime.h>
#include <cstdint>

#define NN     10000
#define NE     320000
#define H      128
#define HID    256
#define KM     336   // 2*H + 64 + 16  (F row width)
#define KX     384   // H + HID
#define KA     464   // H + KM         (fused GEMM K)
#define NSTEP  64
#define NLAYER 4

// ---------------- static device scratch (zero-initialized at load) ----------------
__device__ float g_F[(size_t)NN * KM];             // [cnt*x | Σx_j | Σsoh | Σea]
__device__ float g_xbuf[2][(size_t)NN * H];
__device__ float g_posbuf[2][(size_t)NN * 3];
__device__ int   g_cnt[NN];                        // zero at load; self-cleaned each run
__device__ int   g_rowbeg[NN];
__device__ int   g_cursor[NN];
__device__ int   g_colj[NE];
__device__ int   g_eid[NE];
__device__ float g_cntf[NN];
__device__ int   g_total[1];                       // zero at load; self-cleaned each run
__device__ float g_Wall[(size_t)NLAYER * KA * H];  // [Wx1 ; Wm@Wx2]
__device__ float g_bmx[NLAYER * H];                // bm @ Wx2

__device__ __forceinline__ float leaky(float v) { return v > 0.f ? v : 0.01f * v; }
__device__ __forceinline__ float tf32_rna(float x) {
    float r; asm("cvt.rna.tf32.f32 %0, %1;" : "=f"(r) : "f"(x)); return r;
}
__device__ __forceinline__ void mma8(float* d, const uint32_t* a, const uint32_t* b) {
    asm volatile(
        "mma.sync.aligned.m16n8k8.row.col.f32.tf32.tf32.f32 "
        "{%0,%1,%2,%3}, {%4,%5,%6,%7}, {%8,%9}, {%0,%1,%2,%3};"
        : "+f"(d[0]), "+f"(d[1]), "+f"(d[2]), "+f"(d[3])
        : "r"(a[0]), "r"(a[1]), "r"(a[2]), "r"(a[3]), "r"(b[0]), "r"(b[1]));
}

// ---------------- preamble kernels ----------------
// degree histogram only (ea handled later, atomic-free)
__global__ void cnt_hist(const int* __restrict__ ei, int* __restrict__ cnt) {
    int e = blockIdx.x * blockDim.x + threadIdx.x;
    if (e < NE) atomicAdd(&cnt[ei[e]], 1);
}

// parallel segment allocation: warp scan + one atomic per warp (order-free CSR)
// self-cleaning: resets cnt for the next graph replay
__global__ void alloc_rows(int* __restrict__ cnt, int* __restrict__ rowbeg,
                           int* __restrict__ cursor, float* __restrict__ cntf,
                           int* __restrict__ total) {
    int n = blockIdx.x * blockDim.x + threadIdx.x;
    int lane = threadIdx.x & 31;
    int v = (n < NN) ? cnt[n] : 0;
    int sc = v;
#pragma unroll
    for (int o = 1; o < 32; o <<= 1) {
        int u = __shfl_up_sync(0xffffffffu, sc, o);
        if (lane >= o) sc += u;
    }
    int wsum = __shfl_sync(0xffffffffu, sc, 31);
    int base = 0;
    if (lane == 0) base = atomicAdd(total, wsum);
    base = __shfl_sync(0xffffffffu, base, 0);
    int beg = base + sc - v;
    if (n < NN) {
        rowbeg[n] = beg; cursor[n] = beg; cntf[n] = (float)v;
        cnt[n] = 0;                                  // self-clean
    }
}

// self-cleaning: resets total for the next graph replay
__global__ void build_csr(const int* __restrict__ ei, int* __restrict__ cursor,
                          int* __restrict__ colj, int* __restrict__ eid,
                          int* __restrict__ total) {
    int e = blockIdx.x * blockDim.x + threadIdx.x;
    if (e == 0) total[0] = 0;                        // self-clean (consumed in alloc_rows)
    if (e < NE) {
        int p = atomicAdd(&cursor[ei[e]], 1);
        colj[p] = ei[NE + e];
        eid[p] = e;
    }
}

// atomic-free Σ ea per destination -> F columns [320,336)
__global__ void ea_csr(const int* __restrict__ rowbeg, const float* __restrict__ cntf,
                       const int* __restrict__ eid, const float* __restrict__ ea,
                       float* __restrict__ F) {
    int gw = (blockIdx.x * blockDim.x + threadIdx.x) >> 4;   // 16 lanes per node
    int l = threadIdx.x & 15;
    if (gw >= NN) return;
    int beg = rowbeg[gw], end = beg + (int)cntf[gw];
    float s = 0.f;
    for (int k = beg; k < end; k++) s += ea[(size_t)eid[k] * 16 + l];
    F[(size_t)gw * KM + 320 + l] = s;
}

// fold Wm through Wx2:  Wall[l] = [ Wx1 ; Wm@Wx2 ],  bmx[l] = bm@Wx2
__global__ void prep_weights(const float* __restrict__ Wm, const float* __restrict__ bm,
                             const float* __restrict__ Wx,
                             float* __restrict__ Wall, float* __restrict__ bmx) {
    int l = blockIdx.x, y = blockIdx.y, n = threadIdx.x;
    const float* WxL = Wx + (size_t)l * KX * H;
    float* WallL = Wall + (size_t)l * KA * H;
    if (y < H) {
        WallL[(size_t)y * H + n] = WxL[(size_t)y * H + n];
    } else if (y < KA) {
        int r = y - H;
        const float* wm = Wm + (size_t)l * KM * HID + (size_t)r * HID;
        float s = 0.f;
#pragma unroll 8
        for (int h = 0; h < HID; h++) s += wm[h] * WxL[(size_t)(H + h) * H + n];
        WallL[(size_t)y * H + n] = s;
    } else {
        const float* bmL = bm + (size_t)l * HID;
        float s = 0.f;
#pragma unroll 8
        for (int h = 0; h < HID; h++) s += bmL[h] * WxL[(size_t)(H + h) * H + n];
        bmx[l * H + n] = s;
    }
}

// ---------------- per-layer CSR kernel: one warp per node, 2-edge ILP ----------------
__global__ __launch_bounds__(256) void csr_layer(
    const float* __restrict__ x, const float* __restrict__ pos,
    const int* __restrict__ rowbeg, const int* __restrict__ colj,
    const float* __restrict__ cntf, float* __restrict__ F, float* __restrict__ npos)
{
    int w = (blockIdx.x * blockDim.x + threadIdx.x) >> 5;
    int lane = threadIdx.x & 31;
    if (w >= NN) return;
    int beg = rowbeg[w];
    float cf = cntf[w];
    int end = beg + (int)cf;
    float4 xi = ((const float4*)(x + (size_t)w * H))[lane];
    float4 xs = make_float4(0.f, 0.f, 0.f, 0.f);
    float s0 = 0.f, s1 = 0.f, ps = 0.f;
    const float step = 10.f / 63.f;
    float c0 = (2 * lane) * step, c1 = (2 * lane + 1) * step;

    int k = beg;
    for (; k + 1 < end; k += 2) {
        int j0 = colj[k], j1 = colj[k + 1];
        float4 xa = ((const float4*)(x + (size_t)j0 * H))[lane];
        float4 xb = ((const float4*)(x + (size_t)j1 * H))[lane];
        float pa = 0.f, pb = 0.f;
        if (lane < 3) { pa = pos[j0 * 3 + lane]; pb = pos[j1 * 3 + lane]; }

        float a0 = xi.x - xa.x, a1 = xi.y - xa.y, a2 = xi.z - xa.z, a3 = xi.w - xa.w;
        float e0 = a0 * a0 + a1 * a1 + a2 * a2 + a3 * a3;
        float b0 = xi.x - xb.x, b1 = xi.y - xb.y, b2 = xi.z - xb.z, b3 = xi.w - xb.w;
        float e1 = b0 * b0 + b1 * b1 + b2 * b2 + b3 * b3;
#pragma unroll
        for (int o = 16; o; o >>= 1) {
            e0 += __shfl_xor_sync(0xffffffffu, e0, o);
            e1 += __shfl_xor_sync(0xffffffffu, e1, o);
        }
        float r0 = sqrtf(e0), r1 = sqrtf(e1);
        float u0 = r0 - c0, u1 = r0 - c1, v0 = r1 - c0, v1 = r1 - c1;
        s0 += __expf(-10.f * u0 * u0) + __expf(-10.f * v0 * v0);
        s1 += __expf(-10.f * u1 * u1) + __expf(-10.f * v1 * v1);
        xs.x += xa.x + xb.x; xs.y += xa.y + xb.y;
        xs.z += xa.z + xb.z; xs.w += xa.w + xb.w;
        ps += pa + pb;
    }
    if (k < end) {                                    // odd tail
        int j0 = colj[k];
        float4 xa = ((const float4*)(x + (size_t)j0 * H))[lane];
        float pa = 0.f;
        if (lane < 3) pa = pos[j0 * 3 + lane];
        float a0 = xi.x - xa.x, a1 = xi.y - xa.y, a2 = xi.z - xa.z, a3 = xi.w - xa.w;
        float e0 = a0 * a0 + a1 * a1 + a2 * a2 + a3 * a3;
#pragma unroll
        for (int o = 16; o; o >>= 1) e0 += __shfl_xor_sync(0xffffffffu, e0, o);
        float r0 = sqrtf(e0);
        float u0 = r0 - c0, u1 = r0 - c1;
        s0 += __expf(-10.f * u0 * u0);
        s1 += __expf(-10.f * u1 * u1);
        xs.x += xa.x; xs.y += xa.y; xs.z += xa.z; xs.w += xa.w;
        ps += pa;
    }

    float* Fr = F + (size_t)w * KM;
    ((float4*)Fr)[lane]           = make_float4(cf * xi.x, cf * xi.y, cf * xi.z, cf * xi.w);
    ((float4*)(Fr + H))[lane]     = xs;
    ((float2*)(Fr + 2 * H))[lane] = make_float2(s0, s1);
    if (lane < 3) {
        float p = pos[w * 3 + lane];
        npos[w * 3 + lane] = p + (cf * p - ps) / fmaxf(cf, 1.f);
    }
}

// ---------------- fused layer GEMM (3xTF32 tensor cores) — measured-good R7 form ----------------
// x' = leaky([x|F] @ Wall + bx + cnt*bmx)   [NN,464]@[464,128]
#define NKT 29   // KA/16
__global__ __launch_bounds__(256) void fused_layer_gemm(
    const float* __restrict__ x, const float* __restrict__ F,
    const float* __restrict__ Wall, const float* __restrict__ bx,
    const float* __restrict__ bmx, const float* __restrict__ cntf,
    const float* __restrict__ resid, float* __restrict__ xout)
{
    __shared__ float Ah[64][20], Al[64][20];
    __shared__ float Bh[16][136], Bl[16][136];

    int t = threadIdx.x;
    int m0 = blockIdx.x * 64;
    int wid = t >> 5, lane = t & 31;
    int g = lane >> 2, c = lane & 3;
    int mb = (wid >> 2) * 32, nb = (wid & 3) * 32;

    int am = t & 63, akq = (t >> 6) << 2;
    int bk = t >> 4, bn = (t & 15) << 3;
    int mm = m0 + am; if (mm >= NN) mm = NN - 1;
    const float* rowx = x + (size_t)mm * H;
    const float* rowF = F + (size_t)mm * KM - H;

    float acc[2][4][4];
#pragma unroll
    for (int i = 0; i < 2; i++)
#pragma unroll
        for (int j = 0; j < 4; j++)
#pragma unroll
            for (int q = 0; q < 4; q++) acc[i][j][q] = 0.f;

    float4 aR, bR0, bR1;
    {
        int k = akq;
        aR = *(const float4*)((k < H ? rowx : rowF) + k);
        const float* wsrc = Wall + (size_t)bk * H + bn;
        bR0 = *(const float4*)wsrc;
        bR1 = *(const float4*)(wsrc + 4);
    }

    for (int it = 0; it < NKT; it++) {
        {
            float h0 = tf32_rna(aR.x), h1 = tf32_rna(aR.y),
                  h2 = tf32_rna(aR.z), h3 = tf32_rna(aR.w);
            Ah[am][akq+0] = h0; Ah[am][akq+1] = h1; Ah[am][akq+2] = h2; Ah[am][akq+3] = h3;
            Al[am][akq+0] = tf32_rna(aR.x - h0); Al[am][akq+1] = tf32_rna(aR.y - h1);
            Al[am][akq+2] = tf32_rna(aR.z - h2); Al[am][akq+3] = tf32_rna(aR.w - h3);

            float p0 = tf32_rna(bR0.x), p1 = tf32_rna(bR0.y),
                  p2 = tf32_rna(bR0.z), p3 = tf32_rna(bR0.w);
            float p4 = tf32_rna(bR1.x), p5 = tf32_rna(bR1.y),
                  p6 = tf32_rna(bR1.z), p7 = tf32_rna(bR1.w);
            Bh[bk][bn+0] = p0; Bh[bk][bn+1] = p1; Bh[bk][bn+2] = p2; Bh[bk][bn+3] = p3;
            Bh[bk][bn+4] = p4; Bh[bk][bn+5] = p5; Bh[bk][bn+6] = p6; Bh[bk][bn+7] = p7;
            Bl[bk][bn+0] = tf32_rna(bR0.x - p0); Bl[bk][bn+1] = tf32_rna(bR0.y - p1);
            Bl[bk][bn+2] = tf32_rna(bR0.z - p2); Bl[bk][bn+3] = tf32_rna(bR0.w - p3);
            Bl[bk][bn+4] = tf32_rna(bR1.x - p4); Bl[bk][bn+5] = tf32_rna(bR1.y - p5);
            Bl[bk][bn+6] = tf32_rna(bR1.z - p6); Bl[bk][bn+7] = tf32_rna(bR1.w - p7);
        }
        __syncthreads();

        if (it + 1 < NKT) {
            int k0n = (it + 1) * 16;
            int k = k0n + akq;
            aR = *(const float4*)((k < H ? rowx : rowF) + k);
            const float* wsrc = Wall + (size_t)(k0n + bk) * H + bn;
            bR0 = *(const float4*)wsrc;
            bR1 = *(const float4*)(wsrc + 4);
        }

#pragma unroll
        for (int ks = 0; ks < 16; ks += 8) {
            uint32_t ah[2][4], al[2][4], bhf[4][2], blf[4][2];
#pragma unroll
            for (int mt = 0; mt < 2; mt++) {
                int r0 = mb + mt * 16 + g, r1 = r0 + 8;
                ah[mt][0] = __float_as_uint(Ah[r0][ks + c]);
                ah[mt][1] = __float_as_uint(Ah[r1][ks + c]);
                ah[mt][2] = __float_as_uint(Ah[r0][ks + c + 4]);
                ah[mt][3] = __float_as_uint(Ah[r1][ks + c + 4]);
                al[mt][0] = __float_as_uint(Al[r0][ks + c]);
                al[mt][1] = __float_as_uint(Al[r1][ks + c]);
                al[mt][2] = __float_as_uint(Al[r0][ks + c + 4]);
                al[mt][3] = __float_as_uint(Al[r1][ks + c + 4]);
            }
#pragma unroll
            for (int nt = 0; nt < 4; nt++) {
                int nc = nb + nt * 8 + g;
                bhf[nt][0] = __float_as_uint(Bh[ks + c][nc]);
                bhf[nt][1] = __float_as_uint(Bh[ks + c + 4][nc]);
                blf[nt][0] = __float_as_uint(Bl[ks + c][nc]);
                blf[nt][1] = __float_as_uint(Bl[ks + c + 4][nc]);
            }
#pragma unroll
            for (int mt = 0; mt < 2; mt++)
#pragma unroll
                for (int nt = 0; nt < 4; nt++) {
                    mma8(acc[mt][nt], al[mt], bhf[nt]);
                    mma8(acc[mt][nt], ah[mt], blf[nt]);
                    mma8(acc[mt][nt], ah[mt], bhf[nt]);
                }
        }
        __syncthreads();
    }

#pragma unroll
    for (int mt = 0; mt < 2; mt++) {
        int r0 = m0 + mb + mt * 16 + g;
        int r1 = r0 + 8;
        float cf0 = (r0 < NN) ? cntf[r0] : 0.f;
        float cf1 = (r1 < NN) ? cntf[r1] : 0.f;
#pragma unroll
        for (int nt = 0; nt < 4; nt++) {
            int col = nb + nt * 8 + 2 * c;
            float bx0 = bx[col], bx1 = bx[col + 1];
            float bm0 = bmx[col], bm1 = bmx[col + 1];
            if (r0 < NN) {
                float v0 = leaky(acc[mt][nt][0] + bx0 + cf0 * bm0);
                float v1 = leaky(acc[mt][nt][1] + bx1 + cf0 * bm1);
                if (resid) {
                    v0 = leaky(resid[(size_t)r0 * H + col] + v0);
                    v1 = leaky(resid[(size_t)r0 * H + col + 1] + v1);
                }
                *(float2*)&xout[(size_t)r0 * H + col] = make_float2(v0, v1);
            }
            if (r1 < NN) {
                float v2 = leaky(acc[mt][nt][2] + bx0 + cf1 * bm0);
                float v3 = leaky(acc[mt][nt][3] + bx1 + cf1 * bm1);
                if (resid) {
                    v2 = leaky(resid[(size_t)r1 * H + col] + v2);
                    v3 = leaky(resid[(size_t)r1 * H + col + 1] + v3);
                }
                *(float2*)&xout[(size_t)r1 * H + col] = make_float2(v2, v3);
            }
        }
    }
}

// ---------------- launch ----------------
extern "C" void kernel_launch(void* const* d_in, const int* in_sizes, int n_in,
                              void* d_out, int out_size) {
    const float* x   = (const float*)d_in[0];
    const float* pos = (const float*)d_in[1];
    const int*   ei  = (const int*)d_in[2];
    const float* ea  = (const float*)d_in[3];
    const float* Wm  = (const float*)d_in[4];
    const float* bm  = (const float*)d_in[5];
    // d_in[6] = Wp, d_in[7] = bp : dead code (alpha unused)
    const float* Wx  = (const float*)d_in[8];
    const float* bx  = (const float*)d_in[9];
    float* out = (float*)d_out;

    float *F, *xb, *pb, *cntf, *Wall, *bmx;
    int *cnt, *rowbeg, *cursor, *colj, *eid, *total;
    cudaGetSymbolAddress((void**)&F,      g_F);
    cudaGetSymbolAddress((void**)&xb,     g_xbuf);
    cudaGetSymbolAddress((void**)&pb,     g_posbuf);
    cudaGetSymbolAddress((void**)&cnt,    g_cnt);
    cudaGetSymbolAddress((void**)&rowbeg, g_rowbeg);
    cudaGetSymbolAddress((void**)&cursor, g_cursor);
    cudaGetSymbolAddress((void**)&colj,   g_colj);
    cudaGetSymbolAddress((void**)&eid,    g_eid);
    cudaGetSymbolAddress((void**)&cntf,   g_cntf);
    cudaGetSymbolAddress((void**)&total,  g_total);
    cudaGetSymbolAddress((void**)&Wall,   g_Wall);
    cudaGetSymbolAddress((void**)&bmx,    g_bmx);

    // preamble: CSR build (order-free, self-cleaning state)
    cnt_hist<<<(NE + 255) / 256, 256>>>(ei, cnt);
    alloc_rows<<<(NN + 255) / 256, 256>>>(cnt, rowbeg, cursor, cntf, total);
    build_csr<<<(NE + 255) / 256, 256>>>(ei, cursor, colj, eid, total);

    const float* curx = x;
    const float* curp = pos;
    for (int l = 0; l < NLAYER; l++) {
        bool last = (l == NLAYER - 1);
        float* nx = last ? out : xb + (size_t)(l & 1) * NN * H;
        float* np = last ? out + (size_t)NN * H : pb + (size_t)(l & 1) * NN * 3;

        csr_layer<<<(NN * 32 + 255) / 256, 256>>>(curx, curp, rowbeg, colj, cntf, F, np);
        if (l == 0) {
            // independent of csr_layer; fill F.ea + fold weights before first GEMM
            ea_csr<<<(NN * 16 + 255) / 256, 256>>>(rowbeg, cntf, eid, ea, F);
            dim3 gp(NLAYER, KA + 1);
            prep_weights<<<gp, 128>>>(Wm, bm, Wx, Wall, bmx);
        }
        fused_layer_gemm<<<(NN + 63) / 64, 256>>>(curx, F, Wall + (size_t)l * KA * H,
                                                  bx + (size_t)l * H, bmx + l * H,
                                                  cntf, last ? x : nullptr, nx);
        curx = nx;
        curp = np;
    }
}

// round 9
// speedup vs baseline: 1.5619x; 1.5619x over previous
#include <cuda_runtime.h>
#include <cstdint>

#define NN     10000
#define NE     320000
#define H      128
#define HID    256
#define KM     336   // 2*H + 64 + 16  (F row width)
#define KX     384   // H + HID
#define KA     464   // H + KM         (fused GEMM K)
#define NSTEP  64
#define NLAYER 4

// ---------------- static device scratch ----------------
__device__ float g_F[(size_t)NN * KM];             // [cnt*x | Σx_j | Σsoh | Σea]
__device__ float g_xbuf[2][(size_t)NN * H];
__device__ float g_posbuf[2][(size_t)NN * 3];
__device__ int   g_cnt[NN];
__device__ int   g_rowbeg[NN];
__device__ int   g_cursor[NN];
__device__ int   g_colj[NE];
__device__ float g_cntf[NN];
__device__ int   g_total[1];
__device__ float g_Wall[(size_t)NLAYER * KA * H];  // [Wx1 ; Wm@Wx2]
__device__ float g_bmx[NLAYER * H];                // bm @ Wx2

__device__ __forceinline__ float leaky(float v) { return v > 0.f ? v : 0.01f * v; }
__device__ __forceinline__ float tf32_rna(float x) {
    float r; asm("cvt.rna.tf32.f32 %0, %1;" : "=f"(r) : "f"(x)); return r;
}
__device__ __forceinline__ void mma8(float* d, const uint32_t* a, const uint32_t* b) {
    asm volatile(
        "mma.sync.aligned.m16n8k8.row.col.f32.tf32.tf32.f32 "
        "{%0,%1,%2,%3}, {%4,%5,%6,%7}, {%8,%9}, {%0,%1,%2,%3};"
        : "+f"(d[0]), "+f"(d[1]), "+f"(d[2]), "+f"(d[3])
        : "r"(a[0]), "r"(a[1]), "r"(a[2]), "r"(a[3]), "r"(b[0]), "r"(b[1]));
}

// ---------------- preamble kernels (exact R7 measured-good forms) ----------------
__global__ void zero_init(float* __restrict__ F, int* __restrict__ cnt, int* __restrict__ total) {
    int idx = blockIdx.x * blockDim.x + threadIdx.x;
    if (idx < NN * 16) F[(size_t)(idx >> 4) * KM + 320 + (idx & 15)] = 0.f;
    if (idx < NN) cnt[idx] = 0;
    if (idx == 0) total[0] = 0;
}

__global__ void edge_pre(const int* __restrict__ ei, const float* __restrict__ ea,
                         int* __restrict__ cnt, float* __restrict__ F) {
    int idx = blockIdx.x * blockDim.x + threadIdx.x;
    if (idx < NE * 16) {
        int e = idx >> 4, k = idx & 15;
        int dst = ei[e];
        atomicAdd(&F[(size_t)dst * KM + 320 + k], ea[idx]);
        if (k == 0) atomicAdd(&cnt[dst], 1);
    }
}

__global__ void alloc_rows(const int* __restrict__ cnt, int* __restrict__ rowbeg,
                           int* __restrict__ cursor, float* __restrict__ cntf,
                           int* __restrict__ total) {
    int n = blockIdx.x * blockDim.x + threadIdx.x;
    int lane = threadIdx.x & 31;
    int v = (n < NN) ? cnt[n] : 0;
    int sc = v;
#pragma unroll
    for (int o = 1; o < 32; o <<= 1) {
        int u = __shfl_up_sync(0xffffffffu, sc, o);
        if (lane >= o) sc += u;
    }
    int wsum = __shfl_sync(0xffffffffu, sc, 31);
    int base = 0;
    if (lane == 0) base = atomicAdd(total, wsum);
    base = __shfl_sync(0xffffffffu, base, 0);
    int beg = base + sc - v;
    if (n < NN) { rowbeg[n] = beg; cursor[n] = beg; cntf[n] = (float)v; }
}

__global__ void build_csr(const int* __restrict__ ei, int* __restrict__ cursor,
                          int* __restrict__ colj) {
    int e = blockIdx.x * blockDim.x + threadIdx.x;
    if (e < NE) {
        int p = atomicAdd(&cursor[ei[e]], 1);
        colj[p] = ei[NE + e];
    }
}

// fold Wm through Wx2:  Wall[l] = [ Wx1 ; Wm@Wx2 ],  bmx[l] = bm@Wx2
__global__ void prep_weights(const float* __restrict__ Wm, const float* __restrict__ bm,
                             const float* __restrict__ Wx,
                             float* __restrict__ Wall, float* __restrict__ bmx) {
    int l = blockIdx.x, y = blockIdx.y, n = threadIdx.x;
    const float* WxL = Wx + (size_t)l * KX * H;
    float* WallL = Wall + (size_t)l * KA * H;
    if (y < H) {
        WallL[(size_t)y * H + n] = WxL[(size_t)y * H + n];
    } else if (y < KA) {
        int r = y - H;
        const float* wm = Wm + (size_t)l * KM * HID + (size_t)r * HID;
        float s = 0.f;
#pragma unroll 8
        for (int h = 0; h < HID; h++) s += wm[h] * WxL[(size_t)(H + h) * H + n];
        WallL[(size_t)y * H + n] = s;
    } else {
        const float* bmL = bm + (size_t)l * HID;
        float s = 0.f;
#pragma unroll 8
        for (int h = 0; h < HID; h++) s += bmL[h] * WxL[(size_t)(H + h) * H + n];
        bmx[l * H + n] = s;
    }
}

// ---------------- per-layer CSR kernel: one warp per node ----------------
// 2-edge ILP *with* cross-pair prefetch: pair k+2's colj/x/pos issued while pair k computes
__global__ __launch_bounds__(256) void csr_layer(
    const float* __restrict__ x, const float* __restrict__ pos,
    const int* __restrict__ rowbeg, const int* __restrict__ colj,
    const float* __restrict__ cntf, float* __restrict__ F, float* __restrict__ npos)
{
    int w = (blockIdx.x * blockDim.x + threadIdx.x) >> 5;
    int lane = threadIdx.x & 31;
    if (w >= NN) return;
    int beg = rowbeg[w];
    float cf = cntf[w];
    int end = beg + (int)cf;
    float4 xi = ((const float4*)(x + (size_t)w * H))[lane];
    float4 xs = make_float4(0.f, 0.f, 0.f, 0.f);
    float s0 = 0.f, s1 = 0.f, ps = 0.f;
    const float step = 10.f / 63.f;
    float c0 = (2 * lane) * step, c1 = (2 * lane + 1) * step;

    int kend2 = beg + (((end - beg) >> 1) << 1);   // even portion

    // prefetch pair 0
    float4 xan = make_float4(0.f, 0.f, 0.f, 0.f), xbn = xan;
    float pan = 0.f, pbn = 0.f;
    if (beg < kend2) {
        int j0 = colj[beg], j1 = colj[beg + 1];
        xan = ((const float4*)(x + (size_t)j0 * H))[lane];
        xbn = ((const float4*)(x + (size_t)j1 * H))[lane];
        if (lane < 3) { pan = pos[j0 * 3 + lane]; pbn = pos[j1 * 3 + lane]; }
    }

    for (int k = beg; k < kend2; k += 2) {
        float4 xa = xan, xb = xbn;
        float pa = pan, pb = pbn;
        if (k + 3 < kend2 + 1) {                   // i.e. k+2 < kend2: prefetch next pair
            int j0 = colj[k + 2], j1 = colj[k + 3];
            xan = ((const float4*)(x + (size_t)j0 * H))[lane];
            xbn = ((const float4*)(x + (size_t)j1 * H))[lane];
            if (lane < 3) { pan = pos[j0 * 3 + lane]; pbn = pos[j1 * 3 + lane]; }
        }
        float a0 = xi.x - xa.x, a1 = xi.y - xa.y, a2 = xi.z - xa.z, a3 = xi.w - xa.w;
        float e0 = a0 * a0 + a1 * a1 + a2 * a2 + a3 * a3;
        float b0 = xi.x - xb.x, b1 = xi.y - xb.y, b2 = xi.z - xb.z, b3 = xi.w - xb.w;
        float e1 = b0 * b0 + b1 * b1 + b2 * b2 + b3 * b3;
#pragma unroll
        for (int o = 16; o; o >>= 1) {             // two independent chains interleave
            e0 += __shfl_xor_sync(0xffffffffu, e0, o);
            e1 += __shfl_xor_sync(0xffffffffu, e1, o);
        }
        float r0 = sqrtf(e0), r1 = sqrtf(e1);
        float u0 = r0 - c0, u1 = r0 - c1, v0 = r1 - c0, v1 = r1 - c1;
        s0 += __expf(-10.f * u0 * u0) + __expf(-10.f * v0 * v0);
        s1 += __expf(-10.f * u1 * u1) + __expf(-10.f * v1 * v1);
        xs.x += xa.x + xb.x; xs.y += xa.y + xb.y;
        xs.z += xa.z + xb.z; xs.w += xa.w + xb.w;
        ps += pa + pb;
    }
    if (kend2 < end) {                             // odd tail edge
        int j0 = colj[kend2];
        float4 xa = ((const float4*)(x + (size_t)j0 * H))[lane];
        float pa = 0.f;
        if (lane < 3) pa = pos[j0 * 3 + lane];
        float a0 = xi.x - xa.x, a1 = xi.y - xa.y, a2 = xi.z - xa.z, a3 = xi.w - xa.w;
        float e0 = a0 * a0 + a1 * a1 + a2 * a2 + a3 * a3;
#pragma unroll
        for (int o = 16; o; o >>= 1) e0 += __shfl_xor_sync(0xffffffffu, e0, o);
        float r0 = sqrtf(e0);
        float u0 = r0 - c0, u1 = r0 - c1;
        s0 += __expf(-10.f * u0 * u0);
        s1 += __expf(-10.f * u1 * u1);
        xs.x += xa.x; xs.y += xa.y; xs.z += xa.z; xs.w += xa.w;
        ps += pa;
    }

    float* Fr = F + (size_t)w * KM;
    ((float4*)Fr)[lane]           = make_float4(cf * xi.x, cf * xi.y, cf * xi.z, cf * xi.w);
    ((float4*)(Fr + H))[lane]     = xs;
    ((float2*)(Fr + 2 * H))[lane] = make_float2(s0, s1);
    if (lane < 3) {
        float p = pos[w * 3 + lane];
        npos[w * 3 + lane] = p + (cf * p - ps) / fmaxf(cf, 1.f);
    }
}

// ---------------- fused layer GEMM (3xTF32 tensor cores) — measured-good R7 form ----------------
#define NKT 29   // KA/16
__global__ __launch_bounds__(256) void fused_layer_gemm(
    const float* __restrict__ x, const float* __restrict__ F,
    const float* __restrict__ Wall, const float* __restrict__ bx,
    const float* __restrict__ bmx, const float* __restrict__ cntf,
    const float* __restrict__ resid, float* __restrict__ xout)
{
    __shared__ float Ah[64][20], Al[64][20];
    __shared__ float Bh[16][136], Bl[16][136];

    int t = threadIdx.x;
    int m0 = blockIdx.x * 64;
    int wid = t >> 5, lane = t & 31;
    int g = lane >> 2, c = lane & 3;
    int mb = (wid >> 2) * 32, nb = (wid & 3) * 32;

    int am = t & 63, akq = (t >> 6) << 2;
    int bk = t >> 4, bn = (t & 15) << 3;
    int mm = m0 + am; if (mm >= NN) mm = NN - 1;
    const float* rowx = x + (size_t)mm * H;
    const float* rowF = F + (size_t)mm * KM - H;

    float acc[2][4][4];
#pragma unroll
    for (int i = 0; i < 2; i++)
#pragma unroll
        for (int j = 0; j < 4; j++)
#pragma unroll
            for (int q = 0; q < 4; q++) acc[i][j][q] = 0.f;

    float4 aR, bR0, bR1;
    {
        int k = akq;
        aR = *(const float4*)((k < H ? rowx : rowF) + k);
        const float* wsrc = Wall + (size_t)bk * H + bn;
        bR0 = *(const float4*)wsrc;
        bR1 = *(const float4*)(wsrc + 4);
    }

    for (int it = 0; it < NKT; it++) {
        {
            float h0 = tf32_rna(aR.x), h1 = tf32_rna(aR.y),
                  h2 = tf32_rna(aR.z), h3 = tf32_rna(aR.w);
            Ah[am][akq+0] = h0; Ah[am][akq+1] = h1; Ah[am][akq+2] = h2; Ah[am][akq+3] = h3;
            Al[am][akq+0] = tf32_rna(aR.x - h0); Al[am][akq+1] = tf32_rna(aR.y - h1);
            Al[am][akq+2] = tf32_rna(aR.z - h2); Al[am][akq+3] = tf32_rna(aR.w - h3);

            float p0 = tf32_rna(bR0.x), p1 = tf32_rna(bR0.y),
                  p2 = tf32_rna(bR0.z), p3 = tf32_rna(bR0.w);
            float p4 = tf32_rna(bR1.x), p5 = tf32_rna(bR1.y),
                  p6 = tf32_rna(bR1.z), p7 = tf32_rna(bR1.w);
            Bh[bk][bn+0] = p0; Bh[bk][bn+1] = p1; Bh[bk][bn+2] = p2; Bh[bk][bn+3] = p3;
            Bh[bk][bn+4] = p4; Bh[bk][bn+5] = p5; Bh[bk][bn+6] = p6; Bh[bk][bn+7] = p7;
            Bl[bk][bn+0] = tf32_rna(bR0.x - p0); Bl[bk][bn+1] = tf32_rna(bR0.y - p1);
            Bl[bk][bn+2] = tf32_rna(bR0.z - p2); Bl[bk][bn+3] = tf32_rna(bR0.w - p3);
            Bl[bk][bn+4] = tf32_rna(bR1.x - p4); Bl[bk][bn+5] = tf32_rna(bR1.y - p5);
            Bl[bk][bn+6] = tf32_rna(bR1.z - p6); Bl[bk][bn+7] = tf32_rna(bR1.w - p7);
        }
        __syncthreads();

        if (it + 1 < NKT) {
            int k0n = (it + 1) * 16;
            int k = k0n + akq;
            aR = *(const float4*)((k < H ? rowx : rowF) + k);
            const float* wsrc = Wall + (size_t)(k0n + bk) * H + bn;
            bR0 = *(const float4*)wsrc;
            bR1 = *(const float4*)(wsrc + 4);
        }

#pragma unroll
        for (int ks = 0; ks < 16; ks += 8) {
            uint32_t ah[2][4], al[2][4], bhf[4][2], blf[4][2];
#pragma unroll
            for (int mt = 0; mt < 2; mt++) {
                int r0 = mb + mt * 16 + g, r1 = r0 + 8;
                ah[mt][0] = __float_as_uint(Ah[r0][ks + c]);
                ah[mt][1] = __float_as_uint(Ah[r1][ks + c]);
                ah[mt][2] = __float_as_uint(Ah[r0][ks + c + 4]);
                ah[mt][3] = __float_as_uint(Ah[r1][ks + c + 4]);
                al[mt][0] = __float_as_uint(Al[r0][ks + c]);
                al[mt][1] = __float_as_uint(Al[r1][ks + c]);
                al[mt][2] = __float_as_uint(Al[r0][ks + c + 4]);
                al[mt][3] = __float_as_uint(Al[r1][ks + c + 4]);
            }
#pragma unroll
            for (int nt = 0; nt < 4; nt++) {
                int nc = nb + nt * 8 + g;
                bhf[nt][0] = __float_as_uint(Bh[ks + c][nc]);
                bhf[nt][1] = __float_as_uint(Bh[ks + c + 4][nc]);
                blf[nt][0] = __float_as_uint(Bl[ks + c][nc]);
                blf[nt][1] = __float_as_uint(Bl[ks + c + 4][nc]);
            }
#pragma unroll
            for (int mt = 0; mt < 2; mt++)
#pragma unroll
                for (int nt = 0; nt < 4; nt++) {
                    mma8(acc[mt][nt], al[mt], bhf[nt]);
                    mma8(acc[mt][nt], ah[mt], blf[nt]);
                    mma8(acc[mt][nt], ah[mt], bhf[nt]);
                }
        }
        __syncthreads();
    }

#pragma unroll
    for (int mt = 0; mt < 2; mt++) {
        int r0 = m0 + mb + mt * 16 + g;
        int r1 = r0 + 8;
        float cf0 = (r0 < NN) ? cntf[r0] : 0.f;
        float cf1 = (r1 < NN) ? cntf[r1] : 0.f;
#pragma unroll
        for (int nt = 0; nt < 4; nt++) {
            int col = nb + nt * 8 + 2 * c;
            float bx0 = bx[col], bx1 = bx[col + 1];
            float bm0 = bmx[col], bm1 = bmx[col + 1];
            if (r0 < NN) {
                float v0 = leaky(acc[mt][nt][0] + bx0 + cf0 * bm0);
                float v1 = leaky(acc[mt][nt][1] + bx1 + cf0 * bm1);
                if (resid) {
                    v0 = leaky(resid[(size_t)r0 * H + col] + v0);
                    v1 = leaky(resid[(size_t)r0 * H + col + 1] + v1);
                }
                *(float2*)&xout[(size_t)r0 * H + col] = make_float2(v0, v1);
            }
            if (r1 < NN) {
                float v2 = leaky(acc[mt][nt][2] + bx0 + cf1 * bm0);
                float v3 = leaky(acc[mt][nt][3] + bx1 + cf1 * bm1);
                if (resid) {
                    v2 = leaky(resid[(size_t)r1 * H + col] + v2);
                    v3 = leaky(resid[(size_t)r1 * H + col + 1] + v3);
                }
                *(float2*)&xout[(size_t)r1 * H + col] = make_float2(v2, v3);
            }
        }
    }
}

// ---------------- launch (exact R7 order) ----------------
extern "C" void kernel_launch(void* const* d_in, const int* in_sizes, int n_in,
                              void* d_out, int out_size) {
    const float* x   = (const float*)d_in[0];
    const float* pos = (const float*)d_in[1];
    const int*   ei  = (const int*)d_in[2];
    const float* ea  = (const float*)d_in[3];
    const float* Wm  = (const float*)d_in[4];
    const float* bm  = (const float*)d_in[5];
    // d_in[6] = Wp, d_in[7] = bp : dead code (alpha unused)
    const float* Wx  = (const float*)d_in[8];
    const float* bx  = (const float*)d_in[9];
    float* out = (float*)d_out;

    float *F, *xb, *pb, *cntf, *Wall, *bmx;
    int *cnt, *rowbeg, *cursor, *colj, *total;
    cudaGetSymbolAddress((void**)&F,      g_F);
    cudaGetSymbolAddress((void**)&xb,     g_xbuf);
    cudaGetSymbolAddress((void**)&pb,     g_posbuf);
    cudaGetSymbolAddress((void**)&cnt,    g_cnt);
    cudaGetSymbolAddress((void**)&rowbeg, g_rowbeg);
    cudaGetSymbolAddress((void**)&cursor, g_cursor);
    cudaGetSymbolAddress((void**)&colj,   g_colj);
    cudaGetSymbolAddress((void**)&cntf,   g_cntf);
    cudaGetSymbolAddress((void**)&total,  g_total);
    cudaGetSymbolAddress((void**)&Wall,   g_Wall);
    cudaGetSymbolAddress((void**)&bmx,    g_bmx);

    zero_init<<<(NN * 16 + 255) / 256, 256>>>(F, cnt, total);
    edge_pre<<<(NE * 16 + 255) / 256, 256>>>(ei, ea, cnt, F);
    alloc_rows<<<(NN + 255) / 256, 256>>>(cnt, rowbeg, cursor, cntf, total);
    build_csr<<<(NE + 255) / 256, 256>>>(ei, cursor, colj);
    {
        dim3 gp(NLAYER, KA + 1);
        prep_weights<<<gp, 128>>>(Wm, bm, Wx, Wall, bmx);
    }

    const float* curx = x;
    const float* curp = pos;
    for (int l = 0; l < NLAYER; l++) {
        bool last = (l == NLAYER - 1);
        float* nx = last ? out : xb + (size_t)(l & 1) * NN * H;
        float* np = last ? out + (size_t)NN * H : pb + (size_t)(l & 1) * NN * 3;

        csr_layer<<<(NN * 32 + 255) / 256, 256>>>(curx, curp, rowbeg, colj, cntf, F, np);
        fused_layer_gemm<<<(NN + 63) / 64, 256>>>(curx, F, Wall + (size_t)l * KA * H,
                                                  bx + (size_t)l * H, bmx + l * H,
                                                  cntf, last ? x : nullptr, nx);
        curx = nx;
        curp = np;
    }
}

// round 10
// speedup vs baseline: 1.5654x; 1.0022x over previous
#include <cuda_runtime.h>
#include <cstdint>

#define NN     10000
#define NE     320000
#define H      128
#define HID    256
#define KM     336   // 2*H + 64 + 16  (F row width)
#define KX     384   // H + HID
#define KA     464   // H + KM         (fused GEMM K)
#define NSTEP  64
#define NLAYER 4

// ---------------- static device scratch ----------------
__device__ float g_F[(size_t)NN * KM];             // [cnt*x | Σx_j | Σsoh | Σea]
__device__ float g_xbuf[2][(size_t)NN * H];
__device__ float g_posbuf[2][(size_t)NN * 3];
__device__ int   g_cnt[NN];
__device__ int   g_rowbeg[NN];
__device__ int   g_cursor[NN];
__device__ int   g_colj[NE];
__device__ float g_cntf[NN];
__device__ int   g_total[1];
__device__ float g_Wall[(size_t)NLAYER * KA * H];  // [Wx1 ; Wm@Wx2]
__device__ float g_bmx[NLAYER * H];                // bm @ Wx2

__device__ __forceinline__ float leaky(float v) { return v > 0.f ? v : 0.01f * v; }
__device__ __forceinline__ float tf32_rna(float x) {
    float r; asm("cvt.rna.tf32.f32 %0, %1;" : "=f"(r) : "f"(x)); return r;
}
__device__ __forceinline__ void mma8(float* d, const uint32_t* a, const uint32_t* b) {
    asm volatile(
        "mma.sync.aligned.m16n8k8.row.col.f32.tf32.tf32.f32 "
        "{%0,%1,%2,%3}, {%4,%5,%6,%7}, {%8,%9}, {%0,%1,%2,%3};"
        : "+f"(d[0]), "+f"(d[1]), "+f"(d[2]), "+f"(d[3])
        : "r"(a[0]), "r"(a[1]), "r"(a[2]), "r"(a[3]), "r"(b[0]), "r"(b[1]));
}

// ---------------- preamble kernels (measured-good forms) ----------------
__global__ void zero_init(float* __restrict__ F, int* __restrict__ cnt, int* __restrict__ total) {
    int idx = blockIdx.x * blockDim.x + threadIdx.x;
    if (idx < NN * 16) F[(size_t)(idx >> 4) * KM + 320 + (idx & 15)] = 0.f;
    if (idx < NN) cnt[idx] = 0;
    if (idx == 0) total[0] = 0;
}

__global__ void edge_pre(const int* __restrict__ ei, const float* __restrict__ ea,
                         int* __restrict__ cnt, float* __restrict__ F) {
    int idx = blockIdx.x * blockDim.x + threadIdx.x;
    if (idx < NE * 16) {
        int e = idx >> 4, k = idx & 15;
        int dst = ei[e];
        atomicAdd(&F[(size_t)dst * KM + 320 + k], ea[idx]);
        if (k == 0) atomicAdd(&cnt[dst], 1);
    }
}

__global__ void alloc_rows(const int* __restrict__ cnt, int* __restrict__ rowbeg,
                           int* __restrict__ cursor, float* __restrict__ cntf,
                           int* __restrict__ total) {
    int n = blockIdx.x * blockDim.x + threadIdx.x;
    int lane = threadIdx.x & 31;
    int v = (n < NN) ? cnt[n] : 0;
    int sc = v;
#pragma unroll
    for (int o = 1; o < 32; o <<= 1) {
        int u = __shfl_up_sync(0xffffffffu, sc, o);
        if (lane >= o) sc += u;
    }
    int wsum = __shfl_sync(0xffffffffu, sc, 31);
    int base = 0;
    if (lane == 0) base = atomicAdd(total, wsum);
    base = __shfl_sync(0xffffffffu, base, 0);
    int beg = base + sc - v;
    if (n < NN) { rowbeg[n] = beg; cursor[n] = beg; cntf[n] = (float)v; }
}

__global__ void build_csr(const int* __restrict__ ei, int* __restrict__ cursor,
                          int* __restrict__ colj) {
    int e = blockIdx.x * blockDim.x + threadIdx.x;
    if (e < NE) {
        int p = atomicAdd(&cursor[ei[e]], 1);
        colj[p] = ei[NE + e];
    }
}

__global__ void prep_weights(const float* __restrict__ Wm, const float* __restrict__ bm,
                             const float* __restrict__ Wx,
                             float* __restrict__ Wall, float* __restrict__ bmx) {
    int l = blockIdx.x, y = blockIdx.y, n = threadIdx.x;
    const float* WxL = Wx + (size_t)l * KX * H;
    float* WallL = Wall + (size_t)l * KA * H;
    if (y < H) {
        WallL[(size_t)y * H + n] = WxL[(size_t)y * H + n];
    } else if (y < KA) {
        int r = y - H;
        const float* wm = Wm + (size_t)l * KM * HID + (size_t)r * HID;
        float s = 0.f;
#pragma unroll 8
        for (int h = 0; h < HID; h++) s += wm[h] * WxL[(size_t)(H + h) * H + n];
        WallL[(size_t)y * H + n] = s;
    } else {
        const float* bmL = bm + (size_t)l * HID;
        float s = 0.f;
#pragma unroll 8
        for (int h = 0; h < HID; h++) s += bmL[h] * WxL[(size_t)(H + h) * H + n];
        bmx[l * H + n] = s;
    }
}

// ---------------- per-layer CSR kernel (measured-good R9 form) ----------------
__global__ __launch_bounds__(256) void csr_layer(
    const float* __restrict__ x, const float* __restrict__ pos,
    const int* __restrict__ rowbeg, const int* __restrict__ colj,
    const float* __restrict__ cntf, float* __restrict__ F, float* __restrict__ npos)
{
    int w = (blockIdx.x * blockDim.x + threadIdx.x) >> 5;
    int lane = threadIdx.x & 31;
    if (w >= NN) return;
    int beg = rowbeg[w];
    float cf = cntf[w];
    int end = beg + (int)cf;
    float4 xi = ((const float4*)(x + (size_t)w * H))[lane];
    float4 xs = make_float4(0.f, 0.f, 0.f, 0.f);
    float s0 = 0.f, s1 = 0.f, ps = 0.f;
    const float step = 10.f / 63.f;
    float c0 = (2 * lane) * step, c1 = (2 * lane + 1) * step;

    int kend2 = beg + (((end - beg) >> 1) << 1);

    float4 xan = make_float4(0.f, 0.f, 0.f, 0.f), xbn = xan;
    float pan = 0.f, pbn = 0.f;
    if (beg < kend2) {
        int j0 = colj[beg], j1 = colj[beg + 1];
        xan = ((const float4*)(x + (size_t)j0 * H))[lane];
        xbn = ((const float4*)(x + (size_t)j1 * H))[lane];
        if (lane < 3) { pan = pos[j0 * 3 + lane]; pbn = pos[j1 * 3 + lane]; }
    }

    for (int k = beg; k < kend2; k += 2) {
        float4 xa = xan, xb = xbn;
        float pa = pan, pb = pbn;
        if (k + 3 < kend2 + 1) {
            int j0 = colj[k + 2], j1 = colj[k + 3];
            xan = ((const float4*)(x + (size_t)j0 * H))[lane];
            xbn = ((const float4*)(x + (size_t)j1 * H))[lane];
            if (lane < 3) { pan = pos[j0 * 3 + lane]; pbn = pos[j1 * 3 + lane]; }
        }
        float a0 = xi.x - xa.x, a1 = xi.y - xa.y, a2 = xi.z - xa.z, a3 = xi.w - xa.w;
        float e0 = a0 * a0 + a1 * a1 + a2 * a2 + a3 * a3;
        float b0 = xi.x - xb.x, b1 = xi.y - xb.y, b2 = xi.z - xb.z, b3 = xi.w - xb.w;
        float e1 = b0 * b0 + b1 * b1 + b2 * b2 + b3 * b3;
#pragma unroll
        for (int o = 16; o; o >>= 1) {
            e0 += __shfl_xor_sync(0xffffffffu, e0, o);
            e1 += __shfl_xor_sync(0xffffffffu, e1, o);
        }
        float r0 = sqrtf(e0), r1 = sqrtf(e1);
        float u0 = r0 - c0, u1 = r0 - c1, v0 = r1 - c0, v1 = r1 - c1;
        s0 += __expf(-10.f * u0 * u0) + __expf(-10.f * v0 * v0);
        s1 += __expf(-10.f * u1 * u1) + __expf(-10.f * v1 * v1);
        xs.x += xa.x + xb.x; xs.y += xa.y + xb.y;
        xs.z += xa.z + xb.z; xs.w += xa.w + xb.w;
        ps += pa + pb;
    }
    if (kend2 < end) {
        int j0 = colj[kend2];
        float4 xa = ((const float4*)(x + (size_t)j0 * H))[lane];
        float pa = 0.f;
        if (lane < 3) pa = pos[j0 * 3 + lane];
        float a0 = xi.x - xa.x, a1 = xi.y - xa.y, a2 = xi.z - xa.z, a3 = xi.w - xa.w;
        float e0 = a0 * a0 + a1 * a1 + a2 * a2 + a3 * a3;
#pragma unroll
        for (int o = 16; o; o >>= 1) e0 += __shfl_xor_sync(0xffffffffu, e0, o);
        float r0 = sqrtf(e0);
        float u0 = r0 - c0, u1 = r0 - c1;
        s0 += __expf(-10.f * u0 * u0);
        s1 += __expf(-10.f * u1 * u1);
        xs.x += xa.x; xs.y += xa.y; xs.z += xa.z; xs.w += xa.w;
        ps += pa;
    }

    float* Fr = F + (size_t)w * KM;
    ((float4*)Fr)[lane]           = make_float4(cf * xi.x, cf * xi.y, cf * xi.z, cf * xi.w);
    ((float4*)(Fr + H))[lane]     = xs;
    ((float2*)(Fr + 2 * H))[lane] = make_float2(s0, s1);
    if (lane < 3) {
        float p = pos[w * 3 + lane];
        npos[w * 3 + lane] = p + (cf * p - ps) / fmaxf(cf, 1.f);
    }
}

// ---------------- fused layer GEMM: 3xTF32, fragment-major smem, double-buffered ----------------
// x' = leaky([x|F] @ Wall + bx + cnt*bmx)   [NN,464]@[464,128]
// BM=64 BN=128 BK=16, 256 thr, 8 warps (2x4), warp tile 32x32
#define NKT 29   // KA/16
// A frag smem: [buf][ks][mt(4)][rp(2)][lane(33 pad)][sub(2)]
#define AIDX(buf,ks,mt,rp,lane,sub) ((((((buf)*2+(ks))*4+(mt))*2+(rp))*33 + (lane))*2 + (sub))
// B frag smem: [buf][ks][nt(16)][lane(33 pad)][reg(2)]
#define BIDX(buf,ks,nt,lane,reg)    (((((buf)*2+(ks))*16+(nt))*33 + (lane))*2 + (reg))
__global__ __launch_bounds__(256) void fused_layer_gemm(
    const float* __restrict__ x, const float* __restrict__ F,
    const float* __restrict__ Wall, const float* __restrict__ bx,
    const float* __restrict__ bmx, const float* __restrict__ cntf,
    const float* __restrict__ resid, float* __restrict__ xout)
{
    __shared__ float AH[2 * 2 * 4 * 2 * 33 * 2], AL[2 * 2 * 4 * 2 * 33 * 2];
    __shared__ float BH[2 * 2 * 16 * 33 * 2],    BL[2 * 2 * 16 * 33 * 2];

    int t = threadIdx.x;
    int m0 = blockIdx.x * 64;
    int wid = t >> 5, lane = t & 31;
    int mtg0 = (wid >> 2) * 2;          // warp's first m16-tile (0..3)
    int ntg0 = (wid & 3) * 4;           // warp's first n8-tile  (0..15)

    // ---- loader coords ----
    int am = t & 63, akq = (t >> 6) << 2;        // A: row am, k = akq..akq+3
    int aks = akq >> 3, arp = (akq >> 2) & 1;    // ks half, reg-pair (const per thread)
    int amt = am >> 4, asub = (am >> 3) & 1, alb = (am & 7) << 2;
    int bk = t >> 4, bnt = t & 15;               // B: k-row bk, n8-tile bnt
    int bks = bk >> 3, breg = (bk >> 2) & 1, blb = bk & 3;
    int mm = m0 + am; if (mm >= NN) mm = NN - 1;
    const float* rowx = x + (size_t)mm * H;
    const float* rowF = F + (size_t)mm * KM - H;     // rowF[k] = F[m][k-128]

    float acc[2][4][4];
#pragma unroll
    for (int i = 0; i < 2; i++)
#pragma unroll
        for (int j = 0; j < 4; j++)
#pragma unroll
            for (int q = 0; q < 4; q++) acc[i][j][q] = 0.f;

    float4 aR, bR0, bR1;
    // load tile 0
    {
        int k = akq;
        aR = *(const float4*)((k < H ? rowx : rowF) + k);
        const float* wsrc = Wall + (size_t)bk * H + bnt * 8;
        bR0 = *(const float4*)wsrc;
        bR1 = *(const float4*)(wsrc + 4);
    }
    // split + store tile 0 into buf 0
    {
        int ab = AIDX(0, aks, amt, arp, alb, asub);
        float h0 = tf32_rna(aR.x), h1 = tf32_rna(aR.y), h2 = tf32_rna(aR.z), h3 = tf32_rna(aR.w);
        AH[ab + 0] = h0; AH[ab + 2] = h1; AH[ab + 4] = h2; AH[ab + 6] = h3;
        AL[ab + 0] = tf32_rna(aR.x - h0); AL[ab + 2] = tf32_rna(aR.y - h1);
        AL[ab + 4] = tf32_rna(aR.z - h2); AL[ab + 6] = tf32_rna(aR.w - h3);
        int bb = BIDX(0, bks, bnt, blb, breg);
        float p0 = tf32_rna(bR0.x), p1 = tf32_rna(bR0.y), p2 = tf32_rna(bR0.z), p3 = tf32_rna(bR0.w);
        float p4 = tf32_rna(bR1.x), p5 = tf32_rna(bR1.y), p6 = tf32_rna(bR1.z), p7 = tf32_rna(bR1.w);
        BH[bb + 0] = p0; BH[bb + 8] = p1; BH[bb + 16] = p2; BH[bb + 24] = p3;
        BH[bb + 32] = p4; BH[bb + 40] = p5; BH[bb + 48] = p6; BH[bb + 56] = p7;
        BL[bb + 0]  = tf32_rna(bR0.x - p0); BL[bb + 8]  = tf32_rna(bR0.y - p1);
        BL[bb + 16] = tf32_rna(bR0.z - p2); BL[bb + 24] = tf32_rna(bR0.w - p3);
        BL[bb + 32] = tf32_rna(bR1.x - p4); BL[bb + 40] = tf32_rna(bR1.y - p5);
        BL[bb + 48] = tf32_rna(bR1.z - p6); BL[bb + 56] = tf32_rna(bR1.w - p7);
    }
    __syncthreads();

    for (int it = 0; it < NKT; it++) {
        int cur = it & 1;
        // prefetch next tile (12 live regs, as in measured-good R7)
        if (it + 1 < NKT) {
            int k0n = (it + 1) * 16;
            int k = k0n + akq;
            aR = *(const float4*)((k < H ? rowx : rowF) + k);
            const float* wsrc = Wall + (size_t)(k0n + bk) * H + bnt * 8;
            bR0 = *(const float4*)wsrc;
            bR1 = *(const float4*)(wsrc + 4);
        }

        // compute on buf cur: 2 k8 sub-steps, vector fragment loads
#pragma unroll
        for (int ks = 0; ks < 2; ks++) {
            uint32_t ah[2][4], al[2][4], bh[4][2], bl[4][2];
#pragma unroll
            for (int mt = 0; mt < 2; mt++) {
                float2 h0 = *(const float2*)&AH[AIDX(cur, ks, mtg0 + mt, 0, lane, 0)];
                float2 h1 = *(const float2*)&AH[AIDX(cur, ks, mtg0 + mt, 1, lane, 0)];
                float2 l0 = *(const float2*)&AL[AIDX(cur, ks, mtg0 + mt, 0, lane, 0)];
                float2 l1 = *(const float2*)&AL[AIDX(cur, ks, mtg0 + mt, 1, lane, 0)];
                ah[mt][0] = __float_as_uint(h0.x); ah[mt][1] = __float_as_uint(h0.y);
                ah[mt][2] = __float_as_uint(h1.x); ah[mt][3] = __float_as_uint(h1.y);
                al[mt][0] = __float_as_uint(l0.x); al[mt][1] = __float_as_uint(l0.y);
                al[mt][2] = __float_as_uint(l1.x); al[mt][3] = __float_as_uint(l1.y);
            }
#pragma unroll
            for (int nt = 0; nt < 4; nt++) {
                float2 wh = *(const float2*)&BH[BIDX(cur, ks, ntg0 + nt, lane, 0)];
                float2 wl = *(const float2*)&BL[BIDX(cur, ks, ntg0 + nt, lane, 0)];
                bh[nt][0] = __float_as_uint(wh.x); bh[nt][1] = __float_as_uint(wh.y);
                bl[nt][0] = __float_as_uint(wl.x); bl[nt][1] = __float_as_uint(wl.y);
            }
#pragma unroll
            for (int mt = 0; mt < 2; mt++)
#pragma unroll
                for (int nt = 0; nt < 4; nt++) {
                    mma8(acc[mt][nt], al[mt], bh[nt]);   // lo*hi
                    mma8(acc[mt][nt], ah[mt], bl[nt]);   // hi*lo
                    mma8(acc[mt][nt], ah[mt], bh[nt]);   // hi*hi
                }
        }

        // split + store next tile into alternate buffer; single sync per tile
        if (it + 1 < NKT) {
            int nxt = cur ^ 1;
            int ab = AIDX(nxt, aks, amt, arp, alb, asub);
            float h0 = tf32_rna(aR.x), h1 = tf32_rna(aR.y), h2 = tf32_rna(aR.z), h3 = tf32_rna(aR.w);
            AH[ab + 0] = h0; AH[ab + 2] = h1; AH[ab + 4] = h2; AH[ab + 6] = h3;
            AL[ab + 0] = tf32_rna(aR.x - h0); AL[ab + 2] = tf32_rna(aR.y - h1);
            AL[ab + 4] = tf32_rna(aR.z - h2); AL[ab + 6] = tf32_rna(aR.w - h3);
            int bb = BIDX(nxt, bks, bnt, blb, breg);
            float p0 = tf32_rna(bR0.x), p1 = tf32_rna(bR0.y), p2 = tf32_rna(bR0.z), p3 = tf32_rna(bR0.w);
            float p4 = tf32_rna(bR1.x), p5 = tf32_rna(bR1.y), p6 = tf32_rna(bR1.z), p7 = tf32_rna(bR1.w);
            BH[bb + 0] = p0; BH[bb + 8] = p1; BH[bb + 16] = p2; BH[bb + 24] = p3;
            BH[bb + 32] = p4; BH[bb + 40] = p5; BH[bb + 48] = p6; BH[bb + 56] = p7;
            BL[bb + 0]  = tf32_rna(bR0.x - p0); BL[bb + 8]  = tf32_rna(bR0.y - p1);
            BL[bb + 16] = tf32_rna(bR0.z - p2); BL[bb + 24] = tf32_rna(bR0.w - p3);
            BL[bb + 32] = tf32_rna(bR1.x - p4); BL[bb + 40] = tf32_rna(bR1.y - p5);
            BL[bb + 48] = tf32_rna(bR1.z - p6); BL[bb + 56] = tf32_rna(bR1.w - p7);
            __syncthreads();
        }
    }

    // epilogue (identical to measured-good form)
    int g = lane >> 2, c = lane & 3;
    int mb = (wid >> 2) * 32, nb = (wid & 3) * 32;
#pragma unroll
    for (int mt = 0; mt < 2; mt++) {
        int r0 = m0 + mb + mt * 16 + g;
        int r1 = r0 + 8;
        float cf0 = (r0 < NN) ? cntf[r0] : 0.f;
        float cf1 = (r1 < NN) ? cntf[r1] : 0.f;
#pragma unroll
        for (int nt = 0; nt < 4; nt++) {
            int col = nb + nt * 8 + 2 * c;
            float bx0 = bx[col], bx1 = bx[col + 1];
            float bm0 = bmx[col], bm1 = bmx[col + 1];
            if (r0 < NN) {
                float v0 = leaky(acc[mt][nt][0] + bx0 + cf0 * bm0);
                float v1 = leaky(acc[mt][nt][1] + bx1 + cf0 * bm1);
                if (resid) {
                    v0 = leaky(resid[(size_t)r0 * H + col] + v0);
                    v1 = leaky(resid[(size_t)r0 * H + col + 1] + v1);
                }
                *(float2*)&xout[(size_t)r0 * H + col] = make_float2(v0, v1);
            }
            if (r1 < NN) {
                float v2 = leaky(acc[mt][nt][2] + bx0 + cf1 * bm0);
                float v3 = leaky(acc[mt][nt][3] + bx1 + cf1 * bm1);
                if (resid) {
                    v2 = leaky(resid[(size_t)r1 * H + col] + v2);
                    v3 = leaky(resid[(size_t)r1 * H + col + 1] + v3);
                }
                *(float2*)&xout[(size_t)r1 * H + col] = make_float2(v2, v3);
            }
        }
    }
}

// ---------------- launch (identical to R9) ----------------
extern "C" void kernel_launch(void* const* d_in, const int* in_sizes, int n_in,
                              void* d_out, int out_size) {
    const float* x   = (const float*)d_in[0];
    const float* pos = (const float*)d_in[1];
    const int*   ei  = (const int*)d_in[2];
    const float* ea  = (const float*)d_in[3];
    const float* Wm  = (const float*)d_in[4];
    const float* bm  = (const float*)d_in[5];
    // d_in[6] = Wp, d_in[7] = bp : dead code (alpha unused)
    const float* Wx  = (const float*)d_in[8];
    const float* bx  = (const float*)d_in[9];
    float* out = (float*)d_out;

    float *F, *xb, *pb, *cntf, *Wall, *bmx;
    int *cnt, *rowbeg, *cursor, *colj, *total;
    cudaGetSymbolAddress((void**)&F,      g_F);
    cudaGetSymbolAddress((void**)&xb,     g_xbuf);
    cudaGetSymbolAddress((void**)&pb,     g_posbuf);
    cudaGetSymbolAddress((void**)&cnt,    g_cnt);
    cudaGetSymbolAddress((void**)&rowbeg, g_rowbeg);
    cudaGetSymbolAddress((void**)&cursor, g_cursor);
    cudaGetSymbolAddress((void**)&colj,   g_colj);
    cudaGetSymbolAddress((void**)&cntf,   g_cntf);
    cudaGetSymbolAddress((void**)&total,  g_total);
    cudaGetSymbolAddress((void**)&Wall,   g_Wall);
    cudaGetSymbolAddress((void**)&bmx,    g_bmx);

    zero_init<<<(NN * 16 + 255) / 256, 256>>>(F, cnt, total);
    edge_pre<<<(NE * 16 + 255) / 256, 256>>>(ei, ea, cnt, F);
    alloc_rows<<<(NN + 255) / 256, 256>>>(cnt, rowbeg, cursor, cntf, total);
    build_csr<<<(NE + 255) / 256, 256>>>(ei, cursor, colj);
    {
        dim3 gp(NLAYER, KA + 1);
        prep_weights<<<gp, 128>>>(Wm, bm, Wx, Wall, bmx);
    }

    const float* curx = x;
    const float* curp = pos;
    for (int l = 0; l < NLAYER; l++) {
        bool last = (l == NLAYER - 1);
        float* nx = last ? out : xb + (size_t)(l & 1) * NN * H;
        float* np = last ? out + (size_t)NN * H : pb + (size_t)(l & 1) * NN * 3;

        csr_layer<<<(NN * 32 + 255) / 256, 256>>>(curx, curp, rowbeg, colj, cntf, F, np);
        fused_layer_gemm<<<(NN + 63) / 64, 256>>>(curx, F, Wall + (size_t)l * KA * H,
                                                  bx + (size_t)l * H, bmx + l * H,
                                                  cntf, last ? x : nullptr, nx);
        curx = nx;
        curp = np;
    }
}

// round 11
// speedup vs baseline: 1.5901x; 1.0158x over previous
#include <cuda_runtime.h>
#include <cstdint>

#define NN     10000
#define NE     320000
#define H      128
#define HID    256
#define KM     336   // 2*H + 64 + 16  (F row width)
#define KX     384   // H + HID
#define KA     464   // H + KM         (fused GEMM K)
#define NSTEP  64
#define NLAYER 4
#define NKT    29    // KA/16

// ---------------- static device scratch ----------------
__device__ float g_F[(size_t)NN * KM];             // [cnt*x | Σx_j | Σsoh | Σea]
__device__ float g_xbuf[2][(size_t)NN * H];
__device__ float g_posbuf[2][(size_t)NN * 3];
__device__ int   g_cnt[NN];
__device__ int   g_rowbeg[NN];
__device__ int   g_cursor[NN];
__device__ int   g_colj[NE];
__device__ float g_cntf[NN];
__device__ int   g_total[1];
// pre-split fragment-major weights: [l][kt][plane(hi=0,lo=1)][ks][nt][lane][reg]
// per (l,kt,plane,ks): 16 nt * 64 = 1024 floats
__device__ float g_Wsplit[(size_t)NLAYER * NKT * 4 * 1024];
__device__ float g_bmx[NLAYER * H];                // bm @ Wx2

__device__ __forceinline__ float leaky(float v) { return v > 0.f ? v : 0.01f * v; }
__device__ __forceinline__ float tf32_rna(float x) {
    float r; asm("cvt.rna.tf32.f32 %0, %1;" : "=f"(r) : "f"(x)); return r;
}
__device__ __forceinline__ void mma8(float* d, const uint32_t* a, const uint32_t* b) {
    asm volatile(
        "mma.sync.aligned.m16n8k8.row.col.f32.tf32.tf32.f32 "
        "{%0,%1,%2,%3}, {%4,%5,%6,%7}, {%8,%9}, {%0,%1,%2,%3};"
        : "+f"(d[0]), "+f"(d[1]), "+f"(d[2]), "+f"(d[3])
        : "r"(a[0]), "r"(a[1]), "r"(a[2]), "r"(a[3]), "r"(b[0]), "r"(b[1]));
}
__device__ __forceinline__ void cp16(uint32_t smem, const float* gmem) {
    asm volatile("cp.async.cg.shared.global [%0], [%1], 16;" :: "r"(smem), "l"(gmem) : "memory");
}
__device__ __forceinline__ void cp_commit() {
    asm volatile("cp.async.commit_group;" ::: "memory");
}
__device__ __forceinline__ void cp_wait0() {
    asm volatile("cp.async.wait_group 0;" ::: "memory");
}

// ---------------- preamble kernels ----------------
__global__ void zero_init(float* __restrict__ F, int* __restrict__ cnt, int* __restrict__ total) {
    int idx = blockIdx.x * blockDim.x + threadIdx.x;
    if (idx < NN * 16) F[(size_t)(idx >> 4) * KM + 320 + (idx & 15)] = 0.f;
    if (idx < NN) cnt[idx] = 0;
    if (idx == 0) total[0] = 0;
}

__global__ void edge_pre(const int* __restrict__ ei, const float* __restrict__ ea,
                         int* __restrict__ cnt, float* __restrict__ F) {
    int idx = blockIdx.x * blockDim.x + threadIdx.x;
    if (idx < NE * 16) {
        int e = idx >> 4, k = idx & 15;
        int dst = ei[e];
        atomicAdd(&F[(size_t)dst * KM + 320 + k], ea[idx]);
        if (k == 0) atomicAdd(&cnt[dst], 1);
    }
}

__global__ void alloc_rows(const int* __restrict__ cnt, int* __restrict__ rowbeg,
                           int* __restrict__ cursor, float* __restrict__ cntf,
                           int* __restrict__ total) {
    int n = blockIdx.x * blockDim.x + threadIdx.x;
    int lane = threadIdx.x & 31;
    int v = (n < NN) ? cnt[n] : 0;
    int sc = v;
#pragma unroll
    for (int o = 1; o < 32; o <<= 1) {
        int u = __shfl_up_sync(0xffffffffu, sc, o);
        if (lane >= o) sc += u;
    }
    int wsum = __shfl_sync(0xffffffffu, sc, 31);
    int base = 0;
    if (lane == 0) base = atomicAdd(total, wsum);
    base = __shfl_sync(0xffffffffu, base, 0);
    int beg = base + sc - v;
    if (n < NN) { rowbeg[n] = beg; cursor[n] = beg; cntf[n] = (float)v; }
}

__global__ void build_csr(const int* __restrict__ ei, int* __restrict__ cursor,
                          int* __restrict__ colj) {
    int e = blockIdx.x * blockDim.x + threadIdx.x;
    if (e < NE) {
        int p = atomicAdd(&cursor[ei[e]], 1);
        colj[p] = ei[NE + e];
    }
}

// fold Wm through Wx2, tf32-split, and store in fragment-major layout.
// grid (NLAYER, KA+1), block 128 (n = output col)
__global__ void prep_weights(const float* __restrict__ Wm, const float* __restrict__ bm,
                             const float* __restrict__ Wx,
                             float* __restrict__ Wsplit, float* __restrict__ bmx) {
    int l = blockIdx.x, y = blockIdx.y, n = threadIdx.x;
    const float* WxL = Wx + (size_t)l * KX * H;
    if (y < KA) {
        float w;
        if (y < H) {
            w = WxL[(size_t)y * H + n];
        } else {
            int r = y - H;
            const float* wm = Wm + (size_t)l * KM * HID + (size_t)r * HID;
            float s = 0.f;
#pragma unroll 8
            for (int h = 0; h < HID; h++) s += wm[h] * WxL[(size_t)(H + h) * H + n];
            w = s;
        }
        float hi = tf32_rna(w);
        float lo = tf32_rna(w - hi);
        int kt = y >> 4, kin = y & 15;
        int ks = kin >> 3, kk = kin & 7;
        int lane = ((n & 7) << 2) | (kk & 3);
        int reg = kk >> 2;
        int nt = n >> 3;
        size_t base = (((size_t)l * NKT + kt) * 4 + ks) * 1024 + nt * 64 + lane * 2 + reg;
        Wsplit[base] = hi;                 // plane 0 (hi): +0
        Wsplit[base + 2048] = lo;          // plane 1 (lo): +2*1024
    } else {
        const float* bmL = bm + (size_t)l * HID;
        float s = 0.f;
#pragma unroll 8
        for (int h = 0; h < HID; h++) s += bmL[h] * WxL[(size_t)(H + h) * H + n];
        bmx[l * H + n] = s;
    }
}

// ---------------- per-layer CSR kernel (R9 form + 7-shfl reduction) ----------------
__global__ __launch_bounds__(256) void csr_layer(
    const float* __restrict__ x, const float* __restrict__ pos,
    const int* __restrict__ rowbeg, const int* __restrict__ colj,
    const float* __restrict__ cntf, float* __restrict__ F, float* __restrict__ npos)
{
    int w = (blockIdx.x * blockDim.x + threadIdx.x) >> 5;
    int lane = threadIdx.x & 31;
    if (w >= NN) return;
    int beg = rowbeg[w];
    float cf = cntf[w];
    int end = beg + (int)cf;
    float4 xi = ((const float4*)(x + (size_t)w * H))[lane];
    float4 xs = make_float4(0.f, 0.f, 0.f, 0.f);
    float s0 = 0.f, s1 = 0.f, ps = 0.f;
    const float step = 10.f / 63.f;
    float c0 = (2 * lane) * step, c1 = (2 * lane + 1) * step;

    int kend2 = beg + (((end - beg) >> 1) << 1);

    float4 xan = make_float4(0.f, 0.f, 0.f, 0.f), xbn = xan;
    float pan = 0.f, pbn = 0.f;
    if (beg < kend2) {
        int j0 = colj[beg], j1 = colj[beg + 1];
        xan = ((const float4*)(x + (size_t)j0 * H))[lane];
        xbn = ((const float4*)(x + (size_t)j1 * H))[lane];
        if (lane < 3) { pan = pos[j0 * 3 + lane]; pbn = pos[j1 * 3 + lane]; }
    }

    for (int k = beg; k < kend2; k += 2) {
        float4 xa = xan, xb = xbn;
        float pa = pan, pb = pbn;
        if (k + 3 < kend2 + 1) {
            int j0 = colj[k + 2], j1 = colj[k + 3];
            xan = ((const float4*)(x + (size_t)j0 * H))[lane];
            xbn = ((const float4*)(x + (size_t)j1 * H))[lane];
            if (lane < 3) { pan = pos[j0 * 3 + lane]; pbn = pos[j1 * 3 + lane]; }
        }
        float a0 = xi.x - xa.x, a1 = xi.y - xa.y, a2 = xi.z - xa.z, a3 = xi.w - xa.w;
        float e0 = a0 * a0 + a1 * a1 + a2 * a2 + a3 * a3;
        float b0 = xi.x - xb.x, b1 = xi.y - xb.y, b2 = xi.z - xb.z, b3 = xi.w - xb.w;
        float e1 = b0 * b0 + b1 * b1 + b2 * b2 + b3 * b3;
        // cross-half shared reduction: 7 shfl for both sums
        e0 += __shfl_xor_sync(0xffffffffu, e0, 16);
        e1 += __shfl_xor_sync(0xffffffffu, e1, 16);
        float v = (lane & 16) ? e1 : e0;
        v += __shfl_xor_sync(0xffffffffu, v, 8);
        v += __shfl_xor_sync(0xffffffffu, v, 4);
        v += __shfl_xor_sync(0xffffffffu, v, 2);
        v += __shfl_xor_sync(0xffffffffu, v, 1);
        float vo = __shfl_xor_sync(0xffffffffu, v, 16);
        float sum0 = (lane & 16) ? vo : v;
        float sum1 = (lane & 16) ? v : vo;
        float r0 = sqrtf(sum0), r1 = sqrtf(sum1);
        float u0 = r0 - c0, u1 = r0 - c1, v0 = r1 - c0, v1 = r1 - c1;
        s0 += __expf(-10.f * u0 * u0) + __expf(-10.f * v0 * v0);
        s1 += __expf(-10.f * u1 * u1) + __expf(-10.f * v1 * v1);
        xs.x += xa.x + xb.x; xs.y += xa.y + xb.y;
        xs.z += xa.z + xb.z; xs.w += xa.w + xb.w;
        ps += pa + pb;
    }
    if (kend2 < end) {
        int j0 = colj[kend2];
        float4 xa = ((const float4*)(x + (size_t)j0 * H))[lane];
        float pa = 0.f;
        if (lane < 3) pa = pos[j0 * 3 + lane];
        float a0 = xi.x - xa.x, a1 = xi.y - xa.y, a2 = xi.z - xa.z, a3 = xi.w - xa.w;
        float e0 = a0 * a0 + a1 * a1 + a2 * a2 + a3 * a3;
#pragma unroll
        for (int o = 16; o; o >>= 1) e0 += __shfl_xor_sync(0xffffffffu, e0, o);
        float r0 = sqrtf(e0);
        float u0 = r0 - c0, u1 = r0 - c1;
        s0 += __expf(-10.f * u0 * u0);
        s1 += __expf(-10.f * u1 * u1);
        xs.x += xa.x; xs.y += xa.y; xs.z += xa.z; xs.w += xa.w;
        ps += pa;
    }

    float* Fr = F + (size_t)w * KM;
    ((float4*)Fr)[lane]           = make_float4(cf * xi.x, cf * xi.y, cf * xi.z, cf * xi.w);
    ((float4*)(Fr + H))[lane]     = xs;
    ((float2*)(Fr + 2 * H))[lane] = make_float2(s0, s1);
    if (lane < 3) {
        float p = pos[w * 3 + lane];
        npos[w * 3 + lane] = p + (cf * p - ps) / fmaxf(cf, 1.f);
    }
}

// ---------------- fused layer GEMM: 3xTF32, frag-major smem, cp.async B loader ----------------
// x' = leaky([x|F] @ W + bx + cnt*bmx)   [NN,464]@[464,128]
// A frag smem: [buf][ks][mt(4)][rp(2)][lane(33 pad)][sub(2)]
#define AIDX(buf,ks,mt,rp,lane,sub) ((((((buf)*2+(ks))*4+(mt))*2+(rp))*33 + (lane))*2 + (sub))
// B frag smem: [buf][ks][nt(16)] blocks of 68 floats (64 data + 4 pad, 272B = 17*16B)
#define BIDX2(buf,ks,nt,lane,reg)   ((((buf)*2+(ks))*16+(nt))*68 + (lane)*2 + (reg))
__global__ __launch_bounds__(256) void fused_layer_gemm(
    const float* __restrict__ x, const float* __restrict__ F,
    const float* __restrict__ Wsp,   // layer base of g_Wsplit
    const float* __restrict__ bx,
    const float* __restrict__ bmx, const float* __restrict__ cntf,
    const float* __restrict__ resid, float* __restrict__ xout)
{
    __shared__ __align__(16) float AH[2 * 2 * 4 * 2 * 33 * 2], AL[2 * 2 * 4 * 2 * 33 * 2];
    __shared__ __align__(16) float BH[2 * 2 * 16 * 68],        BL[2 * 2 * 16 * 68];

    int t = threadIdx.x;
    int m0 = blockIdx.x * 64;
    int wid = t >> 5, lane = t & 31;
    int mtg0 = (wid >> 2) * 2;          // warp's first m16-tile (0..3)
    int ntg0 = (wid & 3) * 4;           // warp's first n8-tile  (0..15)

    // ---- A loader coords ----
    int am = t & 63, akq = (t >> 6) << 2;
    int aks = akq >> 3, arp = (akq >> 2) & 1;
    int amt = am >> 4, asub = (am >> 3) & 1, alb = (am & 7) << 2;
    int mm = m0 + am; if (mm >= NN) mm = NN - 1;
    const float* rowx = x + (size_t)mm * H;
    const float* rowF = F + (size_t)mm * KM - H;

    // ---- B loader coords: thread copies 4x16B chunks {hi,lo}x{ks0,ks1} ----
    int bnt = (t >> 4) & 15, bpair = t & 15;
    uint32_t sBH = (uint32_t)__cvta_generic_to_shared(BH);
    uint32_t sBL = (uint32_t)__cvta_generic_to_shared(BL);
    // smem chunk offsets (bytes), parameterized by buf at use site
    // BIDX2(buf,ks,bnt,bpair*2,0)*4
    uint32_t smo[2][2];   // [ks][buf]
#pragma unroll
    for (int ks = 0; ks < 2; ks++)
#pragma unroll
        for (int b = 0; b < 2; b++)
            smo[ks][b] = (uint32_t)(BIDX2(b, ks, bnt, bpair * 2, 0) * 4);
    // gmem chunk offsets within layer for tile kt: ((kt*4 + plane*2 + ks)*1024 + bnt*64 + bpair*4)
    int gbase = bnt * 64 + bpair * 4;

    float acc[2][4][4];
#pragma unroll
    for (int i = 0; i < 2; i++)
#pragma unroll
        for (int j = 0; j < 4; j++)
#pragma unroll
            for (int q = 0; q < 4; q++) acc[i][j][q] = 0.f;

    // ---- preload tile 0 ----
    float4 aR;
    {
        cp16(sBH + smo[0][0], Wsp + (0 * 4 + 0) * 1024 + gbase);
        cp16(sBH + smo[1][0], Wsp + (0 * 4 + 1) * 1024 + gbase);
        cp16(sBL + smo[0][0], Wsp + (0 * 4 + 2) * 1024 + gbase);
        cp16(sBL + smo[1][0], Wsp + (0 * 4 + 3) * 1024 + gbase);
        cp_commit();
        aR = *(const float4*)((akq < H ? rowx : rowF) + akq);
        int ab = AIDX(0, aks, amt, arp, alb, asub);
        float h0 = tf32_rna(aR.x), h1 = tf32_rna(aR.y), h2 = tf32_rna(aR.z), h3 = tf32_rna(aR.w);
        AH[ab + 0] = h0; AH[ab + 2] = h1; AH[ab + 4] = h2; AH[ab + 6] = h3;
        AL[ab + 0] = tf32_rna(aR.x - h0); AL[ab + 2] = tf32_rna(aR.y - h1);
        AL[ab + 4] = tf32_rna(aR.z - h2); AL[ab + 6] = tf32_rna(aR.w - h3);
        cp_wait0();
    }
    __syncthreads();

    for (int it = 0; it < NKT; it++) {
        int cur = it & 1;
        if (it + 1 < NKT) {
            int nxt = cur ^ 1;
            int kt = it + 1;
            cp16(sBH + smo[0][nxt], Wsp + (kt * 4 + 0) * 1024 + gbase);
            cp16(sBH + smo[1][nxt], Wsp + (kt * 4 + 1) * 1024 + gbase);
            cp16(sBL + smo[0][nxt], Wsp + (kt * 4 + 2) * 1024 + gbase);
            cp16(sBL + smo[1][nxt], Wsp + (kt * 4 + 3) * 1024 + gbase);
            cp_commit();
            int k = kt * 16 + akq;
            aR = *(const float4*)((k < H ? rowx : rowF) + k);
        }

        // compute on buf cur
#pragma unroll
        for (int ks = 0; ks < 2; ks++) {
            uint32_t ah[2][4], al[2][4], bh[4][2], bl[4][2];
#pragma unroll
            for (int mt = 0; mt < 2; mt++) {
                float2 h0 = *(const float2*)&AH[AIDX(cur, ks, mtg0 + mt, 0, lane, 0)];
                float2 h1 = *(const float2*)&AH[AIDX(cur, ks, mtg0 + mt, 1, lane, 0)];
                float2 l0 = *(const float2*)&AL[AIDX(cur, ks, mtg0 + mt, 0, lane, 0)];
                float2 l1 = *(const float2*)&AL[AIDX(cur, ks, mtg0 + mt, 1, lane, 0)];
                ah[mt][0] = __float_as_uint(h0.x); ah[mt][1] = __float_as_uint(h0.y);
                ah[mt][2] = __float_as_uint(h1.x); ah[mt][3] = __float_as_uint(h1.y);
                al[mt][0] = __float_as_uint(l0.x); al[mt][1] = __float_as_uint(l0.y);
                al[mt][2] = __float_as_uint(l1.x); al[mt][3] = __float_as_uint(l1.y);
            }
#pragma unroll
            for (int nt = 0; nt < 4; nt++) {
                float2 wh = *(const float2*)&BH[BIDX2(cur, ks, ntg0 + nt, lane, 0)];
                float2 wl = *(const float2*)&BL[BIDX2(cur, ks, ntg0 + nt, lane, 0)];
                bh[nt][0] = __float_as_uint(wh.x); bh[nt][1] = __float_as_uint(wh.y);
                bl[nt][0] = __float_as_uint(wl.x); bl[nt][1] = __float_as_uint(wl.y);
            }
#pragma unroll
            for (int mt = 0; mt < 2; mt++)
#pragma unroll
                for (int nt = 0; nt < 4; nt++) {
                    mma8(acc[mt][nt], al[mt], bh[nt]);   // lo*hi
                    mma8(acc[mt][nt], ah[mt], bl[nt]);   // hi*lo
                    mma8(acc[mt][nt], ah[mt], bh[nt]);   // hi*hi
                }
        }

        if (it + 1 < NKT) {
            int nxt = cur ^ 1;
            int ab = AIDX(nxt, aks, amt, arp, alb, asub);
            float h0 = tf32_rna(aR.x), h1 = tf32_rna(aR.y), h2 = tf32_rna(aR.z), h3 = tf32_rna(aR.w);
            AH[ab + 0] = h0; AH[ab + 2] = h1; AH[ab + 4] = h2; AH[ab + 6] = h3;
            AL[ab + 0] = tf32_rna(aR.x - h0); AL[ab + 2] = tf32_rna(aR.y - h1);
            AL[ab + 4] = tf32_rna(aR.z - h2); AL[ab + 6] = tf32_rna(aR.w - h3);
            cp_wait0();
            __syncthreads();
        }
    }

    // epilogue
    int g = lane >> 2, c = lane & 3;
    int mb = (wid >> 2) * 32, nb = (wid & 3) * 32;
#pragma unroll
    for (int mt = 0; mt < 2; mt++) {
        int r0 = m0 + mb + mt * 16 + g;
        int r1 = r0 + 8;
        float cf0 = (r0 < NN) ? cntf[r0] : 0.f;
        float cf1 = (r1 < NN) ? cntf[r1] : 0.f;
#pragma unroll
        for (int nt = 0; nt < 4; nt++) {
            int col = nb + nt * 8 + 2 * c;
            float bx0 = bx[col], bx1 = bx[col + 1];
            float bm0 = bmx[col], bm1 = bmx[col + 1];
            if (r0 < NN) {
                float v0 = leaky(acc[mt][nt][0] + bx0 + cf0 * bm0);
                float v1 = leaky(acc[mt][nt][1] + bx1 + cf0 * bm1);
                if (resid) {
                    v0 = leaky(resid[(size_t)r0 * H + col] + v0);
                    v1 = leaky(resid[(size_t)r0 * H + col + 1] + v1);
                }
                *(float2*)&xout[(size_t)r0 * H + col] = make_float2(v0, v1);
            }
            if (r1 < NN) {
                float v2 = leaky(acc[mt][nt][2] + bx0 + cf1 * bm0);
                float v3 = leaky(acc[mt][nt][3] + bx1 + cf1 * bm1);
                if (resid) {
                    v2 = leaky(resid[(size_t)r1 * H + col] + v2);
                    v3 = leaky(resid[(size_t)r1 * H + col + 1] + v3);
                }
                *(float2*)&xout[(size_t)r1 * H + col] = make_float2(v2, v3);
            }
        }
    }
}

// ---------------- launch ----------------
extern "C" void kernel_launch(void* const* d_in, const int* in_sizes, int n_in,
                              void* d_out, int out_size) {
    const float* x   = (const float*)d_in[0];
    const float* pos = (const float*)d_in[1];
    const int*   ei  = (const int*)d_in[2];
    const float* ea  = (const float*)d_in[3];
    const float* Wm  = (const float*)d_in[4];
    const float* bm  = (const float*)d_in[5];
    // d_in[6] = Wp, d_in[7] = bp : dead code (alpha unused)
    const float* Wx  = (const float*)d_in[8];
    const float* bx  = (const float*)d_in[9];
    float* out = (float*)d_out;

    float *F, *xb, *pb, *cntf, *Wsp, *bmx;
    int *cnt, *rowbeg, *cursor, *colj, *total;
    cudaGetSymbolAddress((void**)&F,      g_F);
    cudaGetSymbolAddress((void**)&xb,     g_xbuf);
    cudaGetSymbolAddress((void**)&pb,     g_posbuf);
    cudaGetSymbolAddress((void**)&cnt,    g_cnt);
    cudaGetSymbolAddress((void**)&rowbeg, g_rowbeg);
    cudaGetSymbolAddress((void**)&cursor, g_cursor);
    cudaGetSymbolAddress((void**)&colj,   g_colj);
    cudaGetSymbolAddress((void**)&cntf,   g_cntf);
    cudaGetSymbolAddress((void**)&total,  g_total);
    cudaGetSymbolAddress((void**)&Wsp,    g_Wsplit);
    cudaGetSymbolAddress((void**)&bmx,    g_bmx);

    zero_init<<<(NN * 16 + 255) / 256, 256>>>(F, cnt, total);
    edge_pre<<<(NE * 16 + 255) / 256, 256>>>(ei, ea, cnt, F);
    alloc_rows<<<(NN + 255) / 256, 256>>>(cnt, rowbeg, cursor, cntf, total);
    build_csr<<<(NE + 255) / 256, 256>>>(ei, cursor, colj);
    {
        dim3 gp(NLAYER, KA + 1);
        prep_weights<<<gp, 128>>>(Wm, bm, Wx, Wsp, bmx);
    }

    const size_t WLS = (size_t)NKT * 4 * 1024;   // per-layer Wsplit stride
    const float* curx = x;
    const float* curp = pos;
    for (int l = 0; l < NLAYER; l++) {
        bool last = (l == NLAYER - 1);
        float* nx = last ? out : xb + (size_t)(l & 1) * NN * H;
        float* np = last ? out + (size_t)NN * H : pb + (size_t)(l & 1) * NN * 3;

        csr_layer<<<(NN * 32 + 255) / 256, 256>>>(curx, curp, rowbeg, colj, cntf, F, np);
        fused_layer_gemm<<<(NN + 63) / 64, 256>>>(curx, F, Wsp + (size_t)l * WLS,
                                                  bx + (size_t)l * H, bmx + l * H,
                                                  cntf, last ? x : nullptr, nx);
        curx = nx;
        curp = np;
    }
}

// round 12
// speedup vs baseline: 1.6069x; 1.0106x over previous
#include <cuda_runtime.h>
#include <cstdint>

#define NN     10000
#define NE     320000
#define H      128
#define HID    256
#define KM     336   // 2*H + 64 + 16  (F row width)
#define KX     384   // H + HID
#define KA     464   // H + KM         (fused GEMM K)
#define NSTEP  64
#define NLAYER 4
#define NKT    29    // KA/16

// ---------------- static device scratch (zero at load; self-cleaned per run) ----------------
__device__ float g_F[(size_t)NN * KM];             // [cnt*x | Σx_j | Σsoh | Σea]
__device__ float g_xbuf[2][(size_t)NN * H];
__device__ float g_posbuf[2][(size_t)NN * 3];
__device__ int   g_cnt[NN];                        // zero at load; self-cleaned
__device__ int   g_rowbeg[NN];
__device__ int   g_cursor[NN];
__device__ int   g_colj[NE];
__device__ int   g_eid[NE];
__device__ float g_cntf[NN];
__device__ int   g_total[1];                       // zero at load; self-cleaned
// pre-split fragment-major weights: [l][kt][plane(hi=0,lo=1)][ks][nt][lane][reg]
__device__ float g_Wsplit[(size_t)NLAYER * NKT * 4 * 1024];
__device__ float g_bmx[NLAYER * H];                // bm @ Wx2

__device__ __forceinline__ float leaky(float v) { return v > 0.f ? v : 0.01f * v; }
__device__ __forceinline__ float tf32_rna(float x) {
    float r; asm("cvt.rna.tf32.f32 %0, %1;" : "=f"(r) : "f"(x)); return r;
}
__device__ __forceinline__ void mma8(float* d, const uint32_t* a, const uint32_t* b) {
    asm volatile(
        "mma.sync.aligned.m16n8k8.row.col.f32.tf32.tf32.f32 "
        "{%0,%1,%2,%3}, {%4,%5,%6,%7}, {%8,%9}, {%0,%1,%2,%3};"
        : "+f"(d[0]), "+f"(d[1]), "+f"(d[2]), "+f"(d[3])
        : "r"(a[0]), "r"(a[1]), "r"(a[2]), "r"(a[3]), "r"(b[0]), "r"(b[1]));
}
__device__ __forceinline__ void cp16(uint32_t smem, const float* gmem) {
    asm volatile("cp.async.cg.shared.global [%0], [%1], 16;" :: "r"(smem), "l"(gmem) : "memory");
}
__device__ __forceinline__ void cp_commit() {
    asm volatile("cp.async.commit_group;" ::: "memory");
}
__device__ __forceinline__ void cp_wait0() {
    asm volatile("cp.async.wait_group 0;" ::: "memory");
}

// ---------------- preamble kernels ----------------
// degree histogram (320k atomics; ea handled atomic-free later)
__global__ void cnt_hist(const int* __restrict__ ei, int* __restrict__ cnt) {
    int e = blockIdx.x * blockDim.x + threadIdx.x;
    if (e < NE) atomicAdd(&cnt[ei[e]], 1);
}

// warp scan + one atomic per warp; self-cleans cnt for next replay
__global__ void alloc_rows(int* __restrict__ cnt, int* __restrict__ rowbeg,
                           int* __restrict__ cursor, float* __restrict__ cntf,
                           int* __restrict__ total) {
    int n = blockIdx.x * blockDim.x + threadIdx.x;
    int lane = threadIdx.x & 31;
    int v = (n < NN) ? cnt[n] : 0;
    int sc = v;
#pragma unroll
    for (int o = 1; o < 32; o <<= 1) {
        int u = __shfl_up_sync(0xffffffffu, sc, o);
        if (lane >= o) sc += u;
    }
    int wsum = __shfl_sync(0xffffffffu, sc, 31);
    int base = 0;
    if (lane == 0) base = atomicAdd(total, wsum);
    base = __shfl_sync(0xffffffffu, base, 0);
    int beg = base + sc - v;
    if (n < NN) {
        rowbeg[n] = beg; cursor[n] = beg; cntf[n] = (float)v;
        cnt[n] = 0;                                  // self-clean
    }
}

// self-cleans total (consumed by alloc_rows, unused here)
__global__ void build_csr(const int* __restrict__ ei, int* __restrict__ cursor,
                          int* __restrict__ colj, int* __restrict__ eid,
                          int* __restrict__ total) {
    int e = blockIdx.x * blockDim.x + threadIdx.x;
    if (e == 0) total[0] = 0;
    if (e < NE) {
        int p = atomicAdd(&cursor[ei[e]], 1);
        colj[p] = ei[NE + e];
        eid[p] = e;
    }
}

// atomic-free Σ ea per destination -> F columns [320,336), written with '='
__global__ void ea_csr(const int* __restrict__ rowbeg, const float* __restrict__ cntf,
                       const int* __restrict__ eid, const float* __restrict__ ea,
                       float* __restrict__ F) {
    int gw = (blockIdx.x * blockDim.x + threadIdx.x) >> 4;   // 16 lanes per node
    int l = threadIdx.x & 15;
    if (gw >= NN) return;
    int beg = rowbeg[gw], end = beg + (int)cntf[gw];
    float s = 0.f;
    int en = (beg < end) ? eid[beg] : 0;
    for (int k = beg; k < end; k++) {
        int e = en;
        if (k + 1 < end) en = eid[k + 1];
        s += ea[(size_t)e * 16 + l];
    }
    F[(size_t)gw * KM + 320 + l] = s;
}

// fold Wm through Wx2, tf32-split, fragment-major store
__global__ void prep_weights(const float* __restrict__ Wm, const float* __restrict__ bm,
                             const float* __restrict__ Wx,
                             float* __restrict__ Wsplit, float* __restrict__ bmx) {
    int l = blockIdx.x, y = blockIdx.y, n = threadIdx.x;
    const float* WxL = Wx + (size_t)l * KX * H;
    if (y < KA) {
        float w;
        if (y < H) {
            w = WxL[(size_t)y * H + n];
        } else {
            int r = y - H;
            const float* wm = Wm + (size_t)l * KM * HID + (size_t)r * HID;
            float s = 0.f;
#pragma unroll 8
            for (int h = 0; h < HID; h++) s += wm[h] * WxL[(size_t)(H + h) * H + n];
            w = s;
        }
        float hi = tf32_rna(w);
        float lo = tf32_rna(w - hi);
        int kt = y >> 4, kin = y & 15;
        int ks = kin >> 3, kk = kin & 7;
        int lane = ((n & 7) << 2) | (kk & 3);
        int reg = kk >> 2;
        int nt = n >> 3;
        size_t base = (((size_t)l * NKT + kt) * 4 + ks) * 1024 + nt * 64 + lane * 2 + reg;
        Wsplit[base] = hi;
        Wsplit[base + 2048] = lo;
    } else {
        const float* bmL = bm + (size_t)l * HID;
        float s = 0.f;
#pragma unroll 8
        for (int h = 0; h < HID; h++) s += bmL[h] * WxL[(size_t)(H + h) * H + n];
        bmx[l * H + n] = s;
    }
}

// ---------------- per-layer CSR kernel (measured-good R11 form, untouched) ----------------
__global__ __launch_bounds__(256) void csr_layer(
    const float* __restrict__ x, const float* __restrict__ pos,
    const int* __restrict__ rowbeg, const int* __restrict__ colj,
    const float* __restrict__ cntf, float* __restrict__ F, float* __restrict__ npos)
{
    int w = (blockIdx.x * blockDim.x + threadIdx.x) >> 5;
    int lane = threadIdx.x & 31;
    if (w >= NN) return;
    int beg = rowbeg[w];
    float cf = cntf[w];
    int end = beg + (int)cf;
    float4 xi = ((const float4*)(x + (size_t)w * H))[lane];
    float4 xs = make_float4(0.f, 0.f, 0.f, 0.f);
    float s0 = 0.f, s1 = 0.f, ps = 0.f;
    const float step = 10.f / 63.f;
    float c0 = (2 * lane) * step, c1 = (2 * lane + 1) * step;

    int kend2 = beg + (((end - beg) >> 1) << 1);

    float4 xan = make_float4(0.f, 0.f, 0.f, 0.f), xbn = xan;
    float pan = 0.f, pbn = 0.f;
    if (beg < kend2) {
        int j0 = colj[beg], j1 = colj[beg + 1];
        xan = ((const float4*)(x + (size_t)j0 * H))[lane];
        xbn = ((const float4*)(x + (size_t)j1 * H))[lane];
        if (lane < 3) { pan = pos[j0 * 3 + lane]; pbn = pos[j1 * 3 + lane]; }
    }

    for (int k = beg; k < kend2; k += 2) {
        float4 xa = xan, xb = xbn;
        float pa = pan, pb = pbn;
        if (k + 3 < kend2 + 1) {
            int j0 = colj[k + 2], j1 = colj[k + 3];
            xan = ((const float4*)(x + (size_t)j0 * H))[lane];
            xbn = ((const float4*)(x + (size_t)j1 * H))[lane];
            if (lane < 3) { pan = pos[j0 * 3 + lane]; pbn = pos[j1 * 3 + lane]; }
        }
        float a0 = xi.x - xa.x, a1 = xi.y - xa.y, a2 = xi.z - xa.z, a3 = xi.w - xa.w;
        float e0 = a0 * a0 + a1 * a1 + a2 * a2 + a3 * a3;
        float b0 = xi.x - xb.x, b1 = xi.y - xb.y, b2 = xi.z - xb.z, b3 = xi.w - xb.w;
        float e1 = b0 * b0 + b1 * b1 + b2 * b2 + b3 * b3;
        e0 += __shfl_xor_sync(0xffffffffu, e0, 16);
        e1 += __shfl_xor_sync(0xffffffffu, e1, 16);
        float v = (lane & 16) ? e1 : e0;
        v += __shfl_xor_sync(0xffffffffu, v, 8);
        v += __shfl_xor_sync(0xffffffffu, v, 4);
        v += __shfl_xor_sync(0xffffffffu, v, 2);
        v += __shfl_xor_sync(0xffffffffu, v, 1);
        float vo = __shfl_xor_sync(0xffffffffu, v, 16);
        float sum0 = (lane & 16) ? vo : v;
        float sum1 = (lane & 16) ? v : vo;
        float r0 = sqrtf(sum0), r1 = sqrtf(sum1);
        float u0 = r0 - c0, u1 = r0 - c1, v0 = r1 - c0, v1 = r1 - c1;
        s0 += __expf(-10.f * u0 * u0) + __expf(-10.f * v0 * v0);
        s1 += __expf(-10.f * u1 * u1) + __expf(-10.f * v1 * v1);
        xs.x += xa.x + xb.x; xs.y += xa.y + xb.y;
        xs.z += xa.z + xb.z; xs.w += xa.w + xb.w;
        ps += pa + pb;
    }
    if (kend2 < end) {
        int j0 = colj[kend2];
        float4 xa = ((const float4*)(x + (size_t)j0 * H))[lane];
        float pa = 0.f;
        if (lane < 3) pa = pos[j0 * 3 + lane];
        float a0 = xi.x - xa.x, a1 = xi.y - xa.y, a2 = xi.z - xa.z, a3 = xi.w - xa.w;
        float e0 = a0 * a0 + a1 * a1 + a2 * a2 + a3 * a3;
#pragma unroll
        for (int o = 16; o; o >>= 1) e0 += __shfl_xor_sync(0xffffffffu, e0, o);
        float r0 = sqrtf(e0);
        float u0 = r0 - c0, u1 = r0 - c1;
        s0 += __expf(-10.f * u0 * u0);
        s1 += __expf(-10.f * u1 * u1);
        xs.x += xa.x; xs.y += xa.y; xs.z += xa.z; xs.w += xa.w;
        ps += pa;
    }

    float* Fr = F + (size_t)w * KM;
    ((float4*)Fr)[lane]           = make_float4(cf * xi.x, cf * xi.y, cf * xi.z, cf * xi.w);
    ((float4*)(Fr + H))[lane]     = xs;
    ((float2*)(Fr + 2 * H))[lane] = make_float2(s0, s1);
    if (lane < 3) {
        float p = pos[w * 3 + lane];
        npos[w * 3 + lane] = p + (cf * p - ps) / fmaxf(cf, 1.f);
    }
}

// ---------------- fused layer GEMM: 3xTF32, frag-major, cp.async B; 2 CTAs/SM ----------------
#define AIDX(buf,ks,mt,rp,lane,sub) ((((((buf)*2+(ks))*4+(mt))*2+(rp))*33 + (lane))*2 + (sub))
#define BIDX2(buf,ks,nt,lane,reg)   ((((buf)*2+(ks))*16+(nt))*68 + (lane)*2 + (reg))
__global__ __launch_bounds__(256, 2) void fused_layer_gemm(
    const float* __restrict__ x, const float* __restrict__ F,
    const float* __restrict__ Wsp,
    const float* __restrict__ bx,
    const float* __restrict__ bmx, const float* __restrict__ cntf,
    const float* __restrict__ resid, float* __restrict__ xout)
{
    __shared__ __align__(16) float AH[2 * 2 * 4 * 2 * 33 * 2], AL[2 * 2 * 4 * 2 * 33 * 2];
    __shared__ __align__(16) float BH[2 * 2 * 16 * 68],        BL[2 * 2 * 16 * 68];

    int t = threadIdx.x;
    int m0 = blockIdx.x * 64;
    int wid = t >> 5, lane = t & 31;
    int mtg0 = (wid >> 2) * 2;
    int ntg0 = (wid & 3) * 4;

    int am = t & 63, akq = (t >> 6) << 2;
    int aks = akq >> 3, arp = (akq >> 2) & 1;
    int amt = am >> 4, asub = (am >> 3) & 1, alb = (am & 7) << 2;
    int mm = m0 + am; if (mm >= NN) mm = NN - 1;
    const float* rowx = x + (size_t)mm * H;
    const float* rowF = F + (size_t)mm * KM - H;

    int bnt = (t >> 4) & 15, bpair = t & 15;
    uint32_t sBH = (uint32_t)__cvta_generic_to_shared(BH);
    uint32_t sBL = (uint32_t)__cvta_generic_to_shared(BL);
    uint32_t smo[2][2];
#pragma unroll
    for (int ks = 0; ks < 2; ks++)
#pragma unroll
        for (int b = 0; b < 2; b++)
            smo[ks][b] = (uint32_t)(BIDX2(b, ks, bnt, bpair * 2, 0) * 4);
    int gbase = bnt * 64 + bpair * 4;

    float acc[2][4][4];
#pragma unroll
    for (int i = 0; i < 2; i++)
#pragma unroll
        for (int j = 0; j < 4; j++)
#pragma unroll
            for (int q = 0; q < 4; q++) acc[i][j][q] = 0.f;

    float4 aR;
    {
        cp16(sBH + smo[0][0], Wsp + 0 * 1024 + gbase);
        cp16(sBH + smo[1][0], Wsp + 1 * 1024 + gbase);
        cp16(sBL + smo[0][0], Wsp + 2 * 1024 + gbase);
        cp16(sBL + smo[1][0], Wsp + 3 * 1024 + gbase);
        cp_commit();
        aR = *(const float4*)((akq < H ? rowx : rowF) + akq);
        int ab = AIDX(0, aks, amt, arp, alb, asub);
        float h0 = tf32_rna(aR.x), h1 = tf32_rna(aR.y), h2 = tf32_rna(aR.z), h3 = tf32_rna(aR.w);
        AH[ab + 0] = h0; AH[ab + 2] = h1; AH[ab + 4] = h2; AH[ab + 6] = h3;
        AL[ab + 0] = tf32_rna(aR.x - h0); AL[ab + 2] = tf32_rna(aR.y - h1);
        AL[ab + 4] = tf32_rna(aR.z - h2); AL[ab + 6] = tf32_rna(aR.w - h3);
        cp_wait0();
    }
    __syncthreads();

    for (int it = 0; it < NKT; it++) {
        int cur = it & 1;
        if (it + 1 < NKT) {
            int nxt = cur ^ 1;
            int kt = it + 1;
            cp16(sBH + smo[0][nxt], Wsp + (kt * 4 + 0) * 1024 + gbase);
            cp16(sBH + smo[1][nxt], Wsp + (kt * 4 + 1) * 1024 + gbase);
            cp16(sBL + smo[0][nxt], Wsp + (kt * 4 + 2) * 1024 + gbase);
            cp16(sBL + smo[1][nxt], Wsp + (kt * 4 + 3) * 1024 + gbase);
            cp_commit();
            int k = kt * 16 + akq;
            aR = *(const float4*)((k < H ? rowx : rowF) + k);
        }

#pragma unroll
        for (int ks = 0; ks < 2; ks++) {
            uint32_t ah[2][4], al[2][4], bh[4][2], bl[4][2];
#pragma unroll
            for (int mt = 0; mt < 2; mt++) {
                float2 h0 = *(const float2*)&AH[AIDX(cur, ks, mtg0 + mt, 0, lane, 0)];
                float2 h1 = *(const float2*)&AH[AIDX(cur, ks, mtg0 + mt, 1, lane, 0)];
                float2 l0 = *(const float2*)&AL[AIDX(cur, ks, mtg0 + mt, 0, lane, 0)];
                float2 l1 = *(const float2*)&AL[AIDX(cur, ks, mtg0 + mt, 1, lane, 0)];
                ah[mt][0] = __float_as_uint(h0.x); ah[mt][1] = __float_as_uint(h0.y);
                ah[mt][2] = __float_as_uint(h1.x); ah[mt][3] = __float_as_uint(h1.y);
                al[mt][0] = __float_as_uint(l0.x); al[mt][1] = __float_as_uint(l0.y);
                al[mt][2] = __float_as_uint(l1.x); al[mt][3] = __float_as_uint(l1.y);
            }
#pragma unroll
            for (int nt = 0; nt < 4; nt++) {
                float2 wh = *(const float2*)&BH[BIDX2(cur, ks, ntg0 + nt, lane, 0)];
                float2 wl = *(const float2*)&BL[BIDX2(cur, ks, ntg0 + nt, lane, 0)];
                bh[nt][0] = __float_as_uint(wh.x); bh[nt][1] = __float_as_uint(wh.y);
                bl[nt][0] = __float_as_uint(wl.x); bl[nt][1] = __float_as_uint(wl.y);
            }
#pragma unroll
            for (int mt = 0; mt < 2; mt++)
#pragma unroll
                for (int nt = 0; nt < 4; nt++) {
                    mma8(acc[mt][nt], al[mt], bh[nt]);
                    mma8(acc[mt][nt], ah[mt], bl[nt]);
                    mma8(acc[mt][nt], ah[mt], bh[nt]);
                }
        }

        if (it + 1 < NKT) {
            int nxt = cur ^ 1;
            int ab = AIDX(nxt, aks, amt, arp, alb, asub);
            float h0 = tf32_rna(aR.x), h1 = tf32_rna(aR.y), h2 = tf32_rna(aR.z), h3 = tf32_rna(aR.w);
            AH[ab + 0] = h0; AH[ab + 2] = h1; AH[ab + 4] = h2; AH[ab + 6] = h3;
            AL[ab + 0] = tf32_rna(aR.x - h0); AL[ab + 2] = tf32_rna(aR.y - h1);
            AL[ab + 4] = tf32_rna(aR.z - h2); AL[ab + 6] = tf32_rna(aR.w - h3);
            cp_wait0();
            __syncthreads();
        }
    }

    int g = lane >> 2, c = lane & 3;
    int mb = (wid >> 2) * 32, nb = (wid & 3) * 32;
#pragma unroll
    for (int mt = 0; mt < 2; mt++) {
        int r0 = m0 + mb + mt * 16 + g;
        int r1 = r0 + 8;
        float cf0 = (r0 < NN) ? cntf[r0] : 0.f;
        float cf1 = (r1 < NN) ? cntf[r1] : 0.f;
#pragma unroll
        for (int nt = 0; nt < 4; nt++) {
            int col = nb + nt * 8 + 2 * c;
            float bx0 = bx[col], bx1 = bx[col + 1];
            float bm0 = bmx[col], bm1 = bmx[col + 1];
            if (r0 < NN) {
                float v0 = leaky(acc[mt][nt][0] + bx0 + cf0 * bm0);
                float v1 = leaky(acc[mt][nt][1] + bx1 + cf0 * bm1);
                if (resid) {
                    v0 = leaky(resid[(size_t)r0 * H + col] + v0);
                    v1 = leaky(resid[(size_t)r0 * H + col + 1] + v1);
                }
                *(float2*)&xout[(size_t)r0 * H + col] = make_float2(v0, v1);
            }
            if (r1 < NN) {
                float v2 = leaky(acc[mt][nt][2] + bx0 + cf1 * bm0);
                float v3 = leaky(acc[mt][nt][3] + bx1 + cf1 * bm1);
                if (resid) {
                    v2 = leaky(resid[(size_t)r1 * H + col] + v2);
                    v3 = leaky(resid[(size_t)r1 * H + col + 1] + v3);
                }
                *(float2*)&xout[(size_t)r1 * H + col] = make_float2(v2, v3);
            }
        }
    }
}

// ---------------- launch ----------------
extern "C" void kernel_launch(void* const* d_in, const int* in_sizes, int n_in,
                              void* d_out, int out_size) {
    const float* x   = (const float*)d_in[0];
    const float* pos = (const float*)d_in[1];
    const int*   ei  = (const int*)d_in[2];
    const float* ea  = (const float*)d_in[3];
    const float* Wm  = (const float*)d_in[4];
    const float* bm  = (const float*)d_in[5];
    // d_in[6] = Wp, d_in[7] = bp : dead code (alpha unused)
    const float* Wx  = (const float*)d_in[8];
    const float* bx  = (const float*)d_in[9];
    float* out = (float*)d_out;

    float *F, *xb, *pb, *cntf, *Wsp, *bmx;
    int *cnt, *rowbeg, *cursor, *colj, *eid, *total;
    cudaGetSymbolAddress((void**)&F,      g_F);
    cudaGetSymbolAddress((void**)&xb,     g_xbuf);
    cudaGetSymbolAddress((void**)&pb,     g_posbuf);
    cudaGetSymbolAddress((void**)&cnt,    g_cnt);
    cudaGetSymbolAddress((void**)&rowbeg, g_rowbeg);
    cudaGetSymbolAddress((void**)&cursor, g_cursor);
    cudaGetSymbolAddress((void**)&colj,   g_colj);
    cudaGetSymbolAddress((void**)&eid,    g_eid);
    cudaGetSymbolAddress((void**)&cntf,   g_cntf);
    cudaGetSymbolAddress((void**)&total,  g_total);
    cudaGetSymbolAddress((void**)&Wsp,    g_Wsplit);
    cudaGetSymbolAddress((void**)&bmx,    g_bmx);

    // preamble: CSR build (self-cleaning state, atomic-light)
    cnt_hist<<<(NE + 255) / 256, 256>>>(ei, cnt);
    alloc_rows<<<(NN + 255) / 256, 256>>>(cnt, rowbeg, cursor, cntf, total);
    build_csr<<<(NE + 255) / 256, 256>>>(ei, cursor, colj, eid, total);
    ea_csr<<<(NN * 16 + 255) / 256, 256>>>(rowbeg, cntf, eid, ea, F);
    {
        dim3 gp(NLAYER, KA + 1);
        prep_weights<<<gp, 128>>>(Wm, bm, Wx, Wsp, bmx);
    }

    const size_t WLS = (size_t)NKT * 4 * 1024;
    const float* curx = x;
    const float* curp = pos;
    for (int l = 0; l < NLAYER; l++) {
        bool last = (l == NLAYER - 1);
        float* nx = last ? out : xb + (size_t)(l & 1) * NN * H;
        float* np = last ? out + (size_t)NN * H : pb + (size_t)(l & 1) * NN * 3;

        csr_layer<<<(NN * 32 + 255) / 256, 256>>>(curx, curp, rowbeg, colj, cntf, F, np);
        fused_layer_gemm<<<(NN + 63) / 64, 256>>>(curx, F, Wsp + (size_t)l * WLS,
                                                  bx + (size_t)l * H, bmx + l * H,
                                                  cntf, last ? x : nullptr, nx);
        curx = nx;
        curp = np;
    }
}

// round 13
// speedup vs baseline: 1.6459x; 1.0243x over previous
#include <cuda_runtime.h>
#include <cstdint>

#define NN     10000
#define NE     320000
#define H      128
#define HID    256
#define KM     336   // 2*H + 64 + 16  (F row width)
#define KX     384   // H + HID
#define KA     464   // H + KM         (fused GEMM K)
#define NSTEP  64
#define NLAYER 4
#define NKT    29    // KA/16

// ---------------- static device scratch (zero at load; self-cleaned per run) ----------------
__device__ float g_F[(size_t)NN * KM];             // [cnt*x | Σx_j | Σsoh | Σea]
__device__ float g_xbuf[2][(size_t)NN * H];
__device__ float g_posbuf[2][(size_t)NN * 3];
__device__ int   g_cnt[NN];                        // zero at load; self-cleaned
__device__ int   g_rowbeg[NN];
__device__ int   g_cursor[NN];
__device__ int   g_colj[NE];
__device__ int   g_eid[NE];
__device__ float g_cntf[NN];
__device__ int   g_total[1];                       // zero at load; self-cleaned
// pre-split fragment-major weights: [l][kt][plane(hi=0,lo=1)][ks][nt][lane][reg]
__device__ float g_Wsplit[(size_t)NLAYER * NKT * 4 * 1024];
__device__ float g_bmx[NLAYER * H];                // bm @ Wx2

__device__ __forceinline__ float leaky(float v) { return v > 0.f ? v : 0.01f * v; }
__device__ __forceinline__ float tf32_rna(float x) {
    float r; asm("cvt.rna.tf32.f32 %0, %1;" : "=f"(r) : "f"(x)); return r;
}
__device__ __forceinline__ void mma8(float* d, const uint32_t* a, const uint32_t* b) {
    asm volatile(
        "mma.sync.aligned.m16n8k8.row.col.f32.tf32.tf32.f32 "
        "{%0,%1,%2,%3}, {%4,%5,%6,%7}, {%8,%9}, {%0,%1,%2,%3};"
        : "+f"(d[0]), "+f"(d[1]), "+f"(d[2]), "+f"(d[3])
        : "r"(a[0]), "r"(a[1]), "r"(a[2]), "r"(a[3]), "r"(b[0]), "r"(b[1]));
}
__device__ __forceinline__ void cp16(uint32_t smem, const float* gmem) {
    asm volatile("cp.async.cg.shared.global [%0], [%1], 16;" :: "r"(smem), "l"(gmem) : "memory");
}
__device__ __forceinline__ void cp_commit() {
    asm volatile("cp.async.commit_group;" ::: "memory");
}
__device__ __forceinline__ void cp_wait0() {
    asm volatile("cp.async.wait_group 0;" ::: "memory");
}

// ---------------- preamble kernels ----------------
__global__ void cnt_hist(const int* __restrict__ ei, int* __restrict__ cnt) {
    int e = blockIdx.x * blockDim.x + threadIdx.x;
    if (e < NE) atomicAdd(&cnt[ei[e]], 1);
}

__global__ void alloc_rows(int* __restrict__ cnt, int* __restrict__ rowbeg,
                           int* __restrict__ cursor, float* __restrict__ cntf,
                           int* __restrict__ total) {
    int n = blockIdx.x * blockDim.x + threadIdx.x;
    int lane = threadIdx.x & 31;
    int v = (n < NN) ? cnt[n] : 0;
    int sc = v;
#pragma unroll
    for (int o = 1; o < 32; o <<= 1) {
        int u = __shfl_up_sync(0xffffffffu, sc, o);
        if (lane >= o) sc += u;
    }
    int wsum = __shfl_sync(0xffffffffu, sc, 31);
    int base = 0;
    if (lane == 0) base = atomicAdd(total, wsum);
    base = __shfl_sync(0xffffffffu, base, 0);
    int beg = base + sc - v;
    if (n < NN) {
        rowbeg[n] = beg; cursor[n] = beg; cntf[n] = (float)v;
        cnt[n] = 0;                                  // self-clean
    }
}

__global__ void build_csr(const int* __restrict__ ei, int* __restrict__ cursor,
                          int* __restrict__ colj, int* __restrict__ eid,
                          int* __restrict__ total) {
    int e = blockIdx.x * blockDim.x + threadIdx.x;
    if (e == 0) total[0] = 0;
    if (e < NE) {
        int p = atomicAdd(&cursor[ei[e]], 1);
        colj[p] = ei[NE + e];
        eid[p] = e;
    }
}

// atomic-free Σ ea per destination; 2-deep value prefetch breaks eid->ea chain
__global__ void ea_csr(const int* __restrict__ rowbeg, const float* __restrict__ cntf,
                       const int* __restrict__ eid, const float* __restrict__ ea,
                       float* __restrict__ F) {
    int gw = (blockIdx.x * blockDim.x + threadIdx.x) >> 4;   // 16 lanes per node
    int l = threadIdx.x & 15;
    if (gw >= NN) return;
    int beg = rowbeg[gw], end = beg + (int)cntf[gw];
    float s = 0.f;
    float v0 = 0.f, v1 = 0.f;
    if (beg < end)     v0 = ea[(size_t)eid[beg] * 16 + l];
    if (beg + 1 < end) v1 = ea[(size_t)eid[beg + 1] * 16 + l];
    for (int k = beg; k < end; k++) {
        float v = v0;
        v0 = v1;
        v1 = (k + 2 < end) ? ea[(size_t)eid[k + 2] * 16 + l] : 0.f;
        s += v;
    }
    F[(size_t)gw * KM + 320 + l] = s;
}

// fold Wm through Wx2, tf32-split, fragment-major store
__global__ void prep_weights(const float* __restrict__ Wm, const float* __restrict__ bm,
                             const float* __restrict__ Wx,
                             float* __restrict__ Wsplit, float* __restrict__ bmx) {
    int l = blockIdx.x, y = blockIdx.y, n = threadIdx.x;
    const float* WxL = Wx + (size_t)l * KX * H;
    if (y < KA) {
        float w;
        if (y < H) {
            w = WxL[(size_t)y * H + n];
        } else {
            int r = y - H;
            const float* wm = Wm + (size_t)l * KM * HID + (size_t)r * HID;
            float s = 0.f;
#pragma unroll 8
            for (int h = 0; h < HID; h++) s += wm[h] * WxL[(size_t)(H + h) * H + n];
            w = s;
        }
        float hi = tf32_rna(w);
        float lo = tf32_rna(w - hi);
        int kt = y >> 4, kin = y & 15;
        int ks = kin >> 3, kk = kin & 7;
        int lane = ((n & 7) << 2) | (kk & 3);
        int reg = kk >> 2;
        int nt = n >> 3;
        size_t base = (((size_t)l * NKT + kt) * 4 + ks) * 1024 + nt * 64 + lane * 2 + reg;
        Wsplit[base] = hi;
        Wsplit[base + 2048] = lo;
    } else {
        const float* bmL = bm + (size_t)l * HID;
        float s = 0.f;
#pragma unroll 8
        for (int h = 0; h < HID; h++) s += bmL[h] * WxL[(size_t)(H + h) * H + n];
        bmx[l * H + n] = s;
    }
}

// ---------------- per-layer CSR kernel (R11 inner loop; block 128 for tail balance) ----------------
__global__ __launch_bounds__(128) void csr_layer(
    const float* __restrict__ x, const float* __restrict__ pos,
    const int* __restrict__ rowbeg, const int* __restrict__ colj,
    const float* __restrict__ cntf, float* __restrict__ F, float* __restrict__ npos)
{
    int w = (blockIdx.x * blockDim.x + threadIdx.x) >> 5;
    int lane = threadIdx.x & 31;
    if (w >= NN) return;
    int beg = rowbeg[w];
    float cf = cntf[w];
    int end = beg + (int)cf;
    float4 xi = ((const float4*)(x + (size_t)w * H))[lane];
    float4 xs = make_float4(0.f, 0.f, 0.f, 0.f);
    float s0 = 0.f, s1 = 0.f, ps = 0.f;
    const float step = 10.f / 63.f;
    float c0 = (2 * lane) * step, c1 = (2 * lane + 1) * step;

    int kend2 = beg + (((end - beg) >> 1) << 1);

    float4 xan = make_float4(0.f, 0.f, 0.f, 0.f), xbn = xan;
    float pan = 0.f, pbn = 0.f;
    if (beg < kend2) {
        int j0 = colj[beg], j1 = colj[beg + 1];
        xan = ((const float4*)(x + (size_t)j0 * H))[lane];
        xbn = ((const float4*)(x + (size_t)j1 * H))[lane];
        if (lane < 3) { pan = pos[j0 * 3 + lane]; pbn = pos[j1 * 3 + lane]; }
    }

    for (int k = beg; k < kend2; k += 2) {
        float4 xa = xan, xb = xbn;
        float pa = pan, pb = pbn;
        if (k + 3 < kend2 + 1) {
            int j0 = colj[k + 2], j1 = colj[k + 3];
            xan = ((const float4*)(x + (size_t)j0 * H))[lane];
            xbn = ((const float4*)(x + (size_t)j1 * H))[lane];
            if (lane < 3) { pan = pos[j0 * 3 + lane]; pbn = pos[j1 * 3 + lane]; }
        }
        float a0 = xi.x - xa.x, a1 = xi.y - xa.y, a2 = xi.z - xa.z, a3 = xi.w - xa.w;
        float e0 = a0 * a0 + a1 * a1 + a2 * a2 + a3 * a3;
        float b0 = xi.x - xb.x, b1 = xi.y - xb.y, b2 = xi.z - xb.z, b3 = xi.w - xb.w;
        float e1 = b0 * b0 + b1 * b1 + b2 * b2 + b3 * b3;
        e0 += __shfl_xor_sync(0xffffffffu, e0, 16);
        e1 += __shfl_xor_sync(0xffffffffu, e1, 16);
        float v = (lane & 16) ? e1 : e0;
        v += __shfl_xor_sync(0xffffffffu, v, 8);
        v += __shfl_xor_sync(0xffffffffu, v, 4);
        v += __shfl_xor_sync(0xffffffffu, v, 2);
        v += __shfl_xor_sync(0xffffffffu, v, 1);
        float vo = __shfl_xor_sync(0xffffffffu, v, 16);
        float sum0 = (lane & 16) ? vo : v;
        float sum1 = (lane & 16) ? v : vo;
        float r0 = sqrtf(sum0), r1 = sqrtf(sum1);
        float u0 = r0 - c0, u1 = r0 - c1, v0 = r1 - c0, v1 = r1 - c1;
        s0 += __expf(-10.f * u0 * u0) + __expf(-10.f * v0 * v0);
        s1 += __expf(-10.f * u1 * u1) + __expf(-10.f * v1 * v1);
        xs.x += xa.x + xb.x; xs.y += xa.y + xb.y;
        xs.z += xa.z + xb.z; xs.w += xa.w + xb.w;
        ps += pa + pb;
    }
    if (kend2 < end) {
        int j0 = colj[kend2];
        float4 xa = ((const float4*)(x + (size_t)j0 * H))[lane];
        float pa = 0.f;
        if (lane < 3) pa = pos[j0 * 3 + lane];
        float a0 = xi.x - xa.x, a1 = xi.y - xa.y, a2 = xi.z - xa.z, a3 = xi.w - xa.w;
        float e0 = a0 * a0 + a1 * a1 + a2 * a2 + a3 * a3;
#pragma unroll
        for (int o = 16; o; o >>= 1) e0 += __shfl_xor_sync(0xffffffffu, e0, o);
        float r0 = sqrtf(e0);
        float u0 = r0 - c0, u1 = r0 - c1;
        s0 += __expf(-10.f * u0 * u0);
        s1 += __expf(-10.f * u1 * u1);
        xs.x += xa.x; xs.y += xa.y; xs.z += xa.z; xs.w += xa.w;
        ps += pa;
    }

    float* Fr = F + (size_t)w * KM;
    ((float4*)Fr)[lane]           = make_float4(cf * xi.x, cf * xi.y, cf * xi.z, cf * xi.w);
    ((float4*)(Fr + H))[lane]     = xs;
    ((float2*)(Fr + 2 * H))[lane] = make_float2(s0, s1);
    if (lane < 3) {
        float p = pos[w * 3 + lane];
        npos[w * 3 + lane] = p + (cf * p - ps) / fmaxf(cf, 1.f);
    }
}

// ---------------- fused layer GEMM (measured-good R12 form, untouched) ----------------
#define AIDX(buf,ks,mt,rp,lane,sub) ((((((buf)*2+(ks))*4+(mt))*2+(rp))*33 + (lane))*2 + (sub))
#define BIDX2(buf,ks,nt,lane,reg)   ((((buf)*2+(ks))*16+(nt))*68 + (lane)*2 + (reg))
__global__ __launch_bounds__(256, 2) void fused_layer_gemm(
    const float* __restrict__ x, const float* __restrict__ F,
    const float* __restrict__ Wsp,
    const float* __restrict__ bx,
    const float* __restrict__ bmx, const float* __restrict__ cntf,
    const float* __restrict__ resid, float* __restrict__ xout)
{
    __shared__ __align__(16) float AH[2 * 2 * 4 * 2 * 33 * 2], AL[2 * 2 * 4 * 2 * 33 * 2];
    __shared__ __align__(16) float BH[2 * 2 * 16 * 68],        BL[2 * 2 * 16 * 68];

    int t = threadIdx.x;
    int m0 = blockIdx.x * 64;
    int wid = t >> 5, lane = t & 31;
    int mtg0 = (wid >> 2) * 2;
    int ntg0 = (wid & 3) * 4;

    int am = t & 63, akq = (t >> 6) << 2;
    int aks = akq >> 3, arp = (akq >> 2) & 1;
    int amt = am >> 4, asub = (am >> 3) & 1, alb = (am & 7) << 2;
    int mm = m0 + am; if (mm >= NN) mm = NN - 1;
    const float* rowx = x + (size_t)mm * H;
    const float* rowF = F + (size_t)mm * KM - H;

    int bnt = (t >> 4) & 15, bpair = t & 15;
    uint32_t sBH = (uint32_t)__cvta_generic_to_shared(BH);
    uint32_t sBL = (uint32_t)__cvta_generic_to_shared(BL);
    uint32_t smo[2][2];
#pragma unroll
    for (int ks = 0; ks < 2; ks++)
#pragma unroll
        for (int b = 0; b < 2; b++)
            smo[ks][b] = (uint32_t)(BIDX2(b, ks, bnt, bpair * 2, 0) * 4);
    int gbase = bnt * 64 + bpair * 4;

    float acc[2][4][4];
#pragma unroll
    for (int i = 0; i < 2; i++)
#pragma unroll
        for (int j = 0; j < 4; j++)
#pragma unroll
            for (int q = 0; q < 4; q++) acc[i][j][q] = 0.f;

    float4 aR;
    {
        cp16(sBH + smo[0][0], Wsp + 0 * 1024 + gbase);
        cp16(sBH + smo[1][0], Wsp + 1 * 1024 + gbase);
        cp16(sBL + smo[0][0], Wsp + 2 * 1024 + gbase);
        cp16(sBL + smo[1][0], Wsp + 3 * 1024 + gbase);
        cp_commit();
        aR = *(const float4*)((akq < H ? rowx : rowF) + akq);
        int ab = AIDX(0, aks, amt, arp, alb, asub);
        float h0 = tf32_rna(aR.x), h1 = tf32_rna(aR.y), h2 = tf32_rna(aR.z), h3 = tf32_rna(aR.w);
        AH[ab + 0] = h0; AH[ab + 2] = h1; AH[ab + 4] = h2; AH[ab + 6] = h3;
        AL[ab + 0] = tf32_rna(aR.x - h0); AL[ab + 2] = tf32_rna(aR.y - h1);
        AL[ab + 4] = tf32_rna(aR.z - h2); AL[ab + 6] = tf32_rna(aR.w - h3);
        cp_wait0();
    }
    __syncthreads();

    for (int it = 0; it < NKT; it++) {
        int cur = it & 1;
        if (it + 1 < NKT) {
            int nxt = cur ^ 1;
            int kt = it + 1;
            cp16(sBH + smo[0][nxt], Wsp + (kt * 4 + 0) * 1024 + gbase);
            cp16(sBH + smo[1][nxt], Wsp + (kt * 4 + 1) * 1024 + gbase);
            cp16(sBL + smo[0][nxt], Wsp + (kt * 4 + 2) * 1024 + gbase);
            cp16(sBL + smo[1][nxt], Wsp + (kt * 4 + 3) * 1024 + gbase);
            cp_commit();
            int k = kt * 16 + akq;
            aR = *(const float4*)((k < H ? rowx : rowF) + k);
        }

#pragma unroll
        for (int ks = 0; ks < 2; ks++) {
            uint32_t ah[2][4], al[2][4], bh[4][2], bl[4][2];
#pragma unroll
            for (int mt = 0; mt < 2; mt++) {
                float2 h0 = *(const float2*)&AH[AIDX(cur, ks, mtg0 + mt, 0, lane, 0)];
                float2 h1 = *(const float2*)&AH[AIDX(cur, ks, mtg0 + mt, 1, lane, 0)];
                float2 l0 = *(const float2*)&AL[AIDX(cur, ks, mtg0 + mt, 0, lane, 0)];
                float2 l1 = *(const float2*)&AL[AIDX(cur, ks, mtg0 + mt, 1, lane, 0)];
                ah[mt][0] = __float_as_uint(h0.x); ah[mt][1] = __float_as_uint(h0.y);
                ah[mt][2] = __float_as_uint(h1.x); ah[mt][3] = __float_as_uint(h1.y);
                al[mt][0] = __float_as_uint(l0.x); al[mt][1] = __float_as_uint(l0.y);
                al[mt][2] = __float_as_uint(l1.x); al[mt][3] = __float_as_uint(l1.y);
            }
#pragma unroll
            for (int nt = 0; nt < 4; nt++) {
                float2 wh = *(const float2*)&BH[BIDX2(cur, ks, ntg0 + nt, lane, 0)];
                float2 wl = *(const float2*)&BL[BIDX2(cur, ks, ntg0 + nt, lane, 0)];
                bh[nt][0] = __float_as_uint(wh.x); bh[nt][1] = __float_as_uint(wh.y);
                bl[nt][0] = __float_as_uint(wl.x); bl[nt][1] = __float_as_uint(wl.y);
            }
#pragma unroll
            for (int mt = 0; mt < 2; mt++)
#pragma unroll
                for (int nt = 0; nt < 4; nt++) {
                    mma8(acc[mt][nt], al[mt], bh[nt]);
                    mma8(acc[mt][nt], ah[mt], bl[nt]);
                    mma8(acc[mt][nt], ah[mt], bh[nt]);
                }
        }

        if (it + 1 < NKT) {
            int nxt = cur ^ 1;
            int ab = AIDX(nxt, aks, amt, arp, alb, asub);
            float h0 = tf32_rna(aR.x), h1 = tf32_rna(aR.y), h2 = tf32_rna(aR.z), h3 = tf32_rna(aR.w);
            AH[ab + 0] = h0; AH[ab + 2] = h1; AH[ab + 4] = h2; AH[ab + 6] = h3;
            AL[ab + 0] = tf32_rna(aR.x - h0); AL[ab + 2] = tf32_rna(aR.y - h1);
            AL[ab + 4] = tf32_rna(aR.z - h2); AL[ab + 6] = tf32_rna(aR.w - h3);
            cp_wait0();
            __syncthreads();
        }
    }

    int g = lane >> 2, c = lane & 3;
    int mb = (wid >> 2) * 32, nb = (wid & 3) * 32;
#pragma unroll
    for (int mt = 0; mt < 2; mt++) {
        int r0 = m0 + mb + mt * 16 + g;
        int r1 = r0 + 8;
        float cf0 = (r0 < NN) ? cntf[r0] : 0.f;
        float cf1 = (r1 < NN) ? cntf[r1] : 0.f;
#pragma unroll
        for (int nt = 0; nt < 4; nt++) {
            int col = nb + nt * 8 + 2 * c;
            float bx0 = bx[col], bx1 = bx[col + 1];
            float bm0 = bmx[col], bm1 = bmx[col + 1];
            if (r0 < NN) {
                float v0 = leaky(acc[mt][nt][0] + bx0 + cf0 * bm0);
                float v1 = leaky(acc[mt][nt][1] + bx1 + cf0 * bm1);
                if (resid) {
                    v0 = leaky(resid[(size_t)r0 * H + col] + v0);
                    v1 = leaky(resid[(size_t)r0 * H + col + 1] + v1);
                }
                *(float2*)&xout[(size_t)r0 * H + col] = make_float2(v0, v1);
            }
            if (r1 < NN) {
                float v2 = leaky(acc[mt][nt][2] + bx0 + cf1 * bm0);
                float v3 = leaky(acc[mt][nt][3] + bx1 + cf1 * bm1);
                if (resid) {
                    v2 = leaky(resid[(size_t)r1 * H + col] + v2);
                    v3 = leaky(resid[(size_t)r1 * H + col + 1] + v3);
                }
                *(float2*)&xout[(size_t)r1 * H + col] = make_float2(v2, v3);
            }
        }
    }
}

// ---------------- launch (csr_layer l0 moved to 4th slot for ncu visibility) ----------------
extern "C" void kernel_launch(void* const* d_in, const int* in_sizes, int n_in,
                              void* d_out, int out_size) {
    const float* x   = (const float*)d_in[0];
    const float* pos = (const float*)d_in[1];
    const int*   ei  = (const int*)d_in[2];
    const float* ea  = (const float*)d_in[3];
    const float* Wm  = (const float*)d_in[4];
    const float* bm  = (const float*)d_in[5];
    // d_in[6] = Wp, d_in[7] = bp : dead code (alpha unused)
    const float* Wx  = (const float*)d_in[8];
    const float* bx  = (const float*)d_in[9];
    float* out = (float*)d_out;

    float *F, *xb, *pb, *cntf, *Wsp, *bmx;
    int *cnt, *rowbeg, *cursor, *colj, *eid, *total;
    cudaGetSymbolAddress((void**)&F,      g_F);
    cudaGetSymbolAddress((void**)&xb,     g_xbuf);
    cudaGetSymbolAddress((void**)&pb,     g_posbuf);
    cudaGetSymbolAddress((void**)&cnt,    g_cnt);
    cudaGetSymbolAddress((void**)&rowbeg, g_rowbeg);
    cudaGetSymbolAddress((void**)&cursor, g_cursor);
    cudaGetSymbolAddress((void**)&colj,   g_colj);
    cudaGetSymbolAddress((void**)&eid,    g_eid);
    cudaGetSymbolAddress((void**)&cntf,   g_cntf);
    cudaGetSymbolAddress((void**)&total,  g_total);
    cudaGetSymbolAddress((void**)&Wsp,    g_Wsplit);
    cudaGetSymbolAddress((void**)&bmx,    g_bmx);

    // preamble + layer 0 front (csr_layer 4th → lands in ncu capture window)
    cnt_hist<<<(NE + 255) / 256, 256>>>(ei, cnt);
    alloc_rows<<<(NN + 255) / 256, 256>>>(cnt, rowbeg, cursor, cntf, total);
    build_csr<<<(NE + 255) / 256, 256>>>(ei, cursor, colj, eid, total);

    const size_t WLS = (size_t)NKT * 4 * 1024;
    const float* curx = x;
    const float* curp = pos;
    for (int l = 0; l < NLAYER; l++) {
        bool last = (l == NLAYER - 1);
        float* nx = last ? out : xb + (size_t)(l & 1) * NN * H;
        float* np = last ? out + (size_t)NN * H : pb + (size_t)(l & 1) * NN * 3;

        csr_layer<<<(NN * 32 + 127) / 128, 128>>>(curx, curp, rowbeg, colj, cntf, F, np);
        if (l == 0) {
            // independent of csr_layer l0 (touches only F.ea cols / weights)
            ea_csr<<<(NN * 16 + 255) / 256, 256>>>(rowbeg, cntf, eid, ea, F);
            dim3 gp(NLAYER, KA + 1);
            prep_weights<<<gp, 128>>>(Wm, bm, Wx, Wsp, bmx);
        }
        fused_layer_gemm<<<(NN + 63) / 64, 256>>>(curx, F, Wsp + (size_t)l * WLS,
                                                  bx + (size_t)l * H, bmx + l * H,
                                                  cntf, last ? x : nullptr, nx);
        curx = nx;
        curp = np;
    }
}

// round 14
// speedup vs baseline: 1.8310x; 1.1124x over previous
#include <cuda_runtime.h>
#include <cstdint>

#define NN     10000
#define NE     320000
#define H      128
#define HID    256
#define KM     336   // 2*H + 64 + 16  (F row width)
#define KX     384   // H + HID
#define KA     464   // H + KM         (fused GEMM K)
#define NSTEP  64
#define NLAYER 4
#define NKT    29    // KA/16
#define KSPLIT0 15   // K-tiles in half 0 (half 1 gets 14)

// ---------------- static device scratch ----------------
__device__ float g_F[(size_t)NN * KM];             // [cnt*x | Σx_j | Σsoh | Σea]
__device__ float g_xbuf[2][(size_t)NN * H];
__device__ float g_posbuf[2][(size_t)NN * 3];
__device__ float g_part[2][(size_t)NN * H];        // split-K partials
__device__ int   g_cnt[NN];
__device__ int   g_rowbeg[NN];
__device__ int   g_cursor[NN];
__device__ int   g_colj[NE];
__device__ int   g_eid[NE];
__device__ float g_cntf[NN];
__device__ int   g_total[1];
// pre-split fragment-major weights: [l][kt][plane(hi=0,lo=1)][ks][nt][lane][reg]
__device__ float g_Wsplit[(size_t)NLAYER * NKT * 4 * 1024];
__device__ float g_bmx[NLAYER * H];                // bm @ Wx2

__device__ __forceinline__ float leaky(float v) { return v > 0.f ? v : 0.01f * v; }
__device__ __forceinline__ float tf32_rna(float x) {
    float r; asm("cvt.rna.tf32.f32 %0, %1;" : "=f"(r) : "f"(x)); return r;
}
__device__ __forceinline__ void mma8(float* d, const uint32_t* a, const uint32_t* b) {
    asm volatile(
        "mma.sync.aligned.m16n8k8.row.col.f32.tf32.tf32.f32 "
        "{%0,%1,%2,%3}, {%4,%5,%6,%7}, {%8,%9}, {%0,%1,%2,%3};"
        : "+f"(d[0]), "+f"(d[1]), "+f"(d[2]), "+f"(d[3])
        : "r"(a[0]), "r"(a[1]), "r"(a[2]), "r"(a[3]), "r"(b[0]), "r"(b[1]));
}
__device__ __forceinline__ void cp16(uint32_t smem, const float* gmem) {
    asm volatile("cp.async.cg.shared.global [%0], [%1], 16;" :: "r"(smem), "l"(gmem) : "memory");
}
__device__ __forceinline__ void cp_commit() {
    asm volatile("cp.async.commit_group;" ::: "memory");
}
__device__ __forceinline__ void cp_wait0() {
    asm volatile("cp.async.wait_group 0;" ::: "memory");
}

// ---------------- preamble kernels ----------------
__global__ void cnt_hist(const int* __restrict__ ei, int* __restrict__ cnt) {
    int e = blockIdx.x * blockDim.x + threadIdx.x;
    if (e < NE) atomicAdd(&cnt[ei[e]], 1);
}

__global__ void alloc_rows(int* __restrict__ cnt, int* __restrict__ rowbeg,
                           int* __restrict__ cursor, float* __restrict__ cntf,
                           int* __restrict__ total) {
    int n = blockIdx.x * blockDim.x + threadIdx.x;
    int lane = threadIdx.x & 31;
    int v = (n < NN) ? cnt[n] : 0;
    int sc = v;
#pragma unroll
    for (int o = 1; o < 32; o <<= 1) {
        int u = __shfl_up_sync(0xffffffffu, sc, o);
        if (lane >= o) sc += u;
    }
    int wsum = __shfl_sync(0xffffffffu, sc, 31);
    int base = 0;
    if (lane == 0) base = atomicAdd(total, wsum);
    base = __shfl_sync(0xffffffffu, base, 0);
    int beg = base + sc - v;
    if (n < NN) {
        rowbeg[n] = beg; cursor[n] = beg; cntf[n] = (float)v;
        cnt[n] = 0;                                  // self-clean
    }
}

__global__ void build_csr(const int* __restrict__ ei, int* __restrict__ cursor,
                          int* __restrict__ colj, int* __restrict__ eid,
                          int* __restrict__ total) {
    int e = blockIdx.x * blockDim.x + threadIdx.x;
    if (e == 0) total[0] = 0;
    if (e < NE) {
        int p = atomicAdd(&cursor[ei[e]], 1);
        colj[p] = ei[NE + e];
        eid[p] = e;
    }
}

__global__ void ea_csr(const int* __restrict__ rowbeg, const float* __restrict__ cntf,
                       const int* __restrict__ eid, const float* __restrict__ ea,
                       float* __restrict__ F) {
    int gw = (blockIdx.x * blockDim.x + threadIdx.x) >> 4;
    int l = threadIdx.x & 15;
    if (gw >= NN) return;
    int beg = rowbeg[gw], end = beg + (int)cntf[gw];
    float s = 0.f;
    float v0 = 0.f, v1 = 0.f;
    if (beg < end)     v0 = ea[(size_t)eid[beg] * 16 + l];
    if (beg + 1 < end) v1 = ea[(size_t)eid[beg + 1] * 16 + l];
    for (int k = beg; k < end; k++) {
        float v = v0;
        v0 = v1;
        v1 = (k + 2 < end) ? ea[(size_t)eid[k + 2] * 16 + l] : 0.f;
        s += v;
    }
    F[(size_t)gw * KM + 320 + l] = s;
}

__global__ void prep_weights(const float* __restrict__ Wm, const float* __restrict__ bm,
                             const float* __restrict__ Wx,
                             float* __restrict__ Wsplit, float* __restrict__ bmx) {
    int l = blockIdx.x, y = blockIdx.y, n = threadIdx.x;
    const float* WxL = Wx + (size_t)l * KX * H;
    if (y < KA) {
        float w;
        if (y < H) {
            w = WxL[(size_t)y * H + n];
        } else {
            int r = y - H;
            const float* wm = Wm + (size_t)l * KM * HID + (size_t)r * HID;
            float s = 0.f;
#pragma unroll 8
            for (int h = 0; h < HID; h++) s += wm[h] * WxL[(size_t)(H + h) * H + n];
            w = s;
        }
        float hi = tf32_rna(w);
        float lo = tf32_rna(w - hi);
        int kt = y >> 4, kin = y & 15;
        int ks = kin >> 3, kk = kin & 7;
        int lane = ((n & 7) << 2) | (kk & 3);
        int reg = kk >> 2;
        int nt = n >> 3;
        size_t base = (((size_t)l * NKT + kt) * 4 + ks) * 1024 + nt * 64 + lane * 2 + reg;
        Wsplit[base] = hi;
        Wsplit[base + 2048] = lo;
    } else {
        const float* bmL = bm + (size_t)l * HID;
        float s = 0.f;
#pragma unroll 8
        for (int h = 0; h < HID; h++) s += bmL[h] * WxL[(size_t)(H + h) * H + n];
        bmx[l * H + n] = s;
    }
}

// ---------------- per-layer CSR kernel (measured-good R13 form, untouched) ----------------
__global__ __launch_bounds__(128) void csr_layer(
    const float* __restrict__ x, const float* __restrict__ pos,
    const int* __restrict__ rowbeg, const int* __restrict__ colj,
    const float* __restrict__ cntf, float* __restrict__ F, float* __restrict__ npos)
{
    int w = (blockIdx.x * blockDim.x + threadIdx.x) >> 5;
    int lane = threadIdx.x & 31;
    if (w >= NN) return;
    int beg = rowbeg[w];
    float cf = cntf[w];
    int end = beg + (int)cf;
    float4 xi = ((const float4*)(x + (size_t)w * H))[lane];
    float4 xs = make_float4(0.f, 0.f, 0.f, 0.f);
    float s0 = 0.f, s1 = 0.f, ps = 0.f;
    const float step = 10.f / 63.f;
    float c0 = (2 * lane) * step, c1 = (2 * lane + 1) * step;

    int kend2 = beg + (((end - beg) >> 1) << 1);

    float4 xan = make_float4(0.f, 0.f, 0.f, 0.f), xbn = xan;
    float pan = 0.f, pbn = 0.f;
    if (beg < kend2) {
        int j0 = colj[beg], j1 = colj[beg + 1];
        xan = ((const float4*)(x + (size_t)j0 * H))[lane];
        xbn = ((const float4*)(x + (size_t)j1 * H))[lane];
        if (lane < 3) { pan = pos[j0 * 3 + lane]; pbn = pos[j1 * 3 + lane]; }
    }

    for (int k = beg; k < kend2; k += 2) {
        float4 xa = xan, xb = xbn;
        float pa = pan, pb = pbn;
        if (k + 3 < kend2 + 1) {
            int j0 = colj[k + 2], j1 = colj[k + 3];
            xan = ((const float4*)(x + (size_t)j0 * H))[lane];
            xbn = ((const float4*)(x + (size_t)j1 * H))[lane];
            if (lane < 3) { pan = pos[j0 * 3 + lane]; pbn = pos[j1 * 3 + lane]; }
        }
        float a0 = xi.x - xa.x, a1 = xi.y - xa.y, a2 = xi.z - xa.z, a3 = xi.w - xa.w;
        float e0 = a0 * a0 + a1 * a1 + a2 * a2 + a3 * a3;
        float b0 = xi.x - xb.x, b1 = xi.y - xb.y, b2 = xi.z - xb.z, b3 = xi.w - xb.w;
        float e1 = b0 * b0 + b1 * b1 + b2 * b2 + b3 * b3;
        e0 += __shfl_xor_sync(0xffffffffu, e0, 16);
        e1 += __shfl_xor_sync(0xffffffffu, e1, 16);
        float v = (lane & 16) ? e1 : e0;
        v += __shfl_xor_sync(0xffffffffu, v, 8);
        v += __shfl_xor_sync(0xffffffffu, v, 4);
        v += __shfl_xor_sync(0xffffffffu, v, 2);
        v += __shfl_xor_sync(0xffffffffu, v, 1);
        float vo = __shfl_xor_sync(0xffffffffu, v, 16);
        float sum0 = (lane & 16) ? vo : v;
        float sum1 = (lane & 16) ? v : vo;
        float r0 = sqrtf(sum0), r1 = sqrtf(sum1);
        float u0 = r0 - c0, u1 = r0 - c1, v0 = r1 - c0, v1 = r1 - c1;
        s0 += __expf(-10.f * u0 * u0) + __expf(-10.f * v0 * v0);
        s1 += __expf(-10.f * u1 * u1) + __expf(-10.f * v1 * v1);
        xs.x += xa.x + xb.x; xs.y += xa.y + xb.y;
        xs.z += xa.z + xb.z; xs.w += xa.w + xb.w;
        ps += pa + pb;
    }
    if (kend2 < end) {
        int j0 = colj[kend2];
        float4 xa = ((const float4*)(x + (size_t)j0 * H))[lane];
        float pa = 0.f;
        if (lane < 3) pa = pos[j0 * 3 + lane];
        float a0 = xi.x - xa.x, a1 = xi.y - xa.y, a2 = xi.z - xa.z, a3 = xi.w - xa.w;
        float e0 = a0 * a0 + a1 * a1 + a2 * a2 + a3 * a3;
#pragma unroll
        for (int o = 16; o; o >>= 1) e0 += __shfl_xor_sync(0xffffffffu, e0, o);
        float r0 = sqrtf(e0);
        float u0 = r0 - c0, u1 = r0 - c1;
        s0 += __expf(-10.f * u0 * u0);
        s1 += __expf(-10.f * u1 * u1);
        xs.x += xa.x; xs.y += xa.y; xs.z += xa.z; xs.w += xa.w;
        ps += pa;
    }

    float* Fr = F + (size_t)w * KM;
    ((float4*)Fr)[lane]           = make_float4(cf * xi.x, cf * xi.y, cf * xi.z, cf * xi.w);
    ((float4*)(Fr + H))[lane]     = xs;
    ((float2*)(Fr + 2 * H))[lane] = make_float2(s0, s1);
    if (lane < 3) {
        float p = pos[w * 3 + lane];
        npos[w * 3 + lane] = p + (cf * p - ps) / fmaxf(cf, 1.f);
    }
}

// ---------------- fused layer GEMM: 3xTF32, split-K=2 (grid.y = half) ----------------
#define AIDX(buf,ks,mt,rp,lane,sub) ((((((buf)*2+(ks))*4+(mt))*2+(rp))*33 + (lane))*2 + (sub))
#define BIDX2(buf,ks,nt,lane,reg)   ((((buf)*2+(ks))*16+(nt))*68 + (lane)*2 + (reg))
__global__ __launch_bounds__(256, 2) void fused_layer_gemm(
    const float* __restrict__ x, const float* __restrict__ F,
    const float* __restrict__ Wsp, float* __restrict__ part)
{
    __shared__ __align__(16) float AH[2 * 2 * 4 * 2 * 33 * 2], AL[2 * 2 * 4 * 2 * 33 * 2];
    __shared__ __align__(16) float BH[2 * 2 * 16 * 68],        BL[2 * 2 * 16 * 68];

    int t = threadIdx.x;
    int m0 = blockIdx.x * 64;
    int ktb = blockIdx.y;
    int kt0 = ktb ? KSPLIT0 : 0;
    int nkt = ktb ? (NKT - KSPLIT0) : KSPLIT0;
    float* myart = part + (size_t)ktb * NN * H;

    int wid = t >> 5, lane = t & 31;
    int mtg0 = (wid >> 2) * 2;
    int ntg0 = (wid & 3) * 4;

    int am = t & 63, akq = (t >> 6) << 2;
    int aks = akq >> 3, arp = (akq >> 2) & 1;
    int amt = am >> 4, asub = (am >> 3) & 1, alb = (am & 7) << 2;
    int mm = m0 + am; if (mm >= NN) mm = NN - 1;
    const float* rowx = x + (size_t)mm * H;
    const float* rowF = F + (size_t)mm * KM - H;

    int bnt = (t >> 4) & 15, bpair = t & 15;
    uint32_t sBH = (uint32_t)__cvta_generic_to_shared(BH);
    uint32_t sBL = (uint32_t)__cvta_generic_to_shared(BL);
    uint32_t smo[2][2];
#pragma unroll
    for (int ks = 0; ks < 2; ks++)
#pragma unroll
        for (int b = 0; b < 2; b++)
            smo[ks][b] = (uint32_t)(BIDX2(b, ks, bnt, bpair * 2, 0) * 4);
    int gbase = bnt * 64 + bpair * 4;

    float acc[2][4][4];
#pragma unroll
    for (int i = 0; i < 2; i++)
#pragma unroll
        for (int j = 0; j < 4; j++)
#pragma unroll
            for (int q = 0; q < 4; q++) acc[i][j][q] = 0.f;

    float4 aR;
    {
        cp16(sBH + smo[0][0], Wsp + (kt0 * 4 + 0) * 1024 + gbase);
        cp16(sBH + smo[1][0], Wsp + (kt0 * 4 + 1) * 1024 + gbase);
        cp16(sBL + smo[0][0], Wsp + (kt0 * 4 + 2) * 1024 + gbase);
        cp16(sBL + smo[1][0], Wsp + (kt0 * 4 + 3) * 1024 + gbase);
        cp_commit();
        int k = kt0 * 16 + akq;
        aR = *(const float4*)((k < H ? rowx : rowF) + k);
        int ab = AIDX(0, aks, amt, arp, alb, asub);
        float h0 = tf32_rna(aR.x), h1 = tf32_rna(aR.y), h2 = tf32_rna(aR.z), h3 = tf32_rna(aR.w);
        AH[ab + 0] = h0; AH[ab + 2] = h1; AH[ab + 4] = h2; AH[ab + 6] = h3;
        AL[ab + 0] = tf32_rna(aR.x - h0); AL[ab + 2] = tf32_rna(aR.y - h1);
        AL[ab + 4] = tf32_rna(aR.z - h2); AL[ab + 6] = tf32_rna(aR.w - h3);
        cp_wait0();
    }
    __syncthreads();

    for (int it = 0; it < nkt; it++) {
        int cur = it & 1;
        if (it + 1 < nkt) {
            int nxt = cur ^ 1;
            int kt = kt0 + it + 1;
            cp16(sBH + smo[0][nxt], Wsp + (kt * 4 + 0) * 1024 + gbase);
            cp16(sBH + smo[1][nxt], Wsp + (kt * 4 + 1) * 1024 + gbase);
            cp16(sBL + smo[0][nxt], Wsp + (kt * 4 + 2) * 1024 + gbase);
            cp16(sBL + smo[1][nxt], Wsp + (kt * 4 + 3) * 1024 + gbase);
            cp_commit();
            int k = kt * 16 + akq;
            aR = *(const float4*)((k < H ? rowx : rowF) + k);
        }

#pragma unroll
        for (int ks = 0; ks < 2; ks++) {
            uint32_t ah[2][4], al[2][4], bh[4][2], bl[4][2];
#pragma unroll
            for (int mt = 0; mt < 2; mt++) {
                float2 h0 = *(const float2*)&AH[AIDX(cur, ks, mtg0 + mt, 0, lane, 0)];
                float2 h1 = *(const float2*)&AH[AIDX(cur, ks, mtg0 + mt, 1, lane, 0)];
                float2 l0 = *(const float2*)&AL[AIDX(cur, ks, mtg0 + mt, 0, lane, 0)];
                float2 l1 = *(const float2*)&AL[AIDX(cur, ks, mtg0 + mt, 1, lane, 0)];
                ah[mt][0] = __float_as_uint(h0.x); ah[mt][1] = __float_as_uint(h0.y);
                ah[mt][2] = __float_as_uint(h1.x); ah[mt][3] = __float_as_uint(h1.y);
                al[mt][0] = __float_as_uint(l0.x); al[mt][1] = __float_as_uint(l0.y);
                al[mt][2] = __float_as_uint(l1.x); al[mt][3] = __float_as_uint(l1.y);
            }
#pragma unroll
            for (int nt = 0; nt < 4; nt++) {
                float2 wh = *(const float2*)&BH[BIDX2(cur, ks, ntg0 + nt, lane, 0)];
                float2 wl = *(const float2*)&BL[BIDX2(cur, ks, ntg0 + nt, lane, 0)];
                bh[nt][0] = __float_as_uint(wh.x); bh[nt][1] = __float_as_uint(wh.y);
                bl[nt][0] = __float_as_uint(wl.x); bl[nt][1] = __float_as_uint(wl.y);
            }
#pragma unroll
            for (int mt = 0; mt < 2; mt++)
#pragma unroll
                for (int nt = 0; nt < 4; nt++) {
                    mma8(acc[mt][nt], al[mt], bh[nt]);
                    mma8(acc[mt][nt], ah[mt], bl[nt]);
                    mma8(acc[mt][nt], ah[mt], bh[nt]);
                }
        }

        if (it + 1 < nkt) {
            int nxt = cur ^ 1;
            int ab = AIDX(nxt, aks, amt, arp, alb, asub);
            float h0 = tf32_rna(aR.x), h1 = tf32_rna(aR.y), h2 = tf32_rna(aR.z), h3 = tf32_rna(aR.w);
            AH[ab + 0] = h0; AH[ab + 2] = h1; AH[ab + 4] = h2; AH[ab + 6] = h3;
            AL[ab + 0] = tf32_rna(aR.x - h0); AL[ab + 2] = tf32_rna(aR.y - h1);
            AL[ab + 4] = tf32_rna(aR.z - h2); AL[ab + 6] = tf32_rna(aR.w - h3);
            cp_wait0();
            __syncthreads();
        }
    }

    // epilogue: write raw partials
    int g = lane >> 2, c = lane & 3;
    int mb = (wid >> 2) * 32, nb = (wid & 3) * 32;
#pragma unroll
    for (int mt = 0; mt < 2; mt++) {
        int r0 = m0 + mb + mt * 16 + g;
        int r1 = r0 + 8;
#pragma unroll
        for (int nt = 0; nt < 4; nt++) {
            int col = nb + nt * 8 + 2 * c;
            if (r0 < NN)
                *(float2*)&myart[(size_t)r0 * H + col] = make_float2(acc[mt][nt][0], acc[mt][nt][1]);
            if (r1 < NN)
                *(float2*)&myart[(size_t)r1 * H + col] = make_float2(acc[mt][nt][2], acc[mt][nt][3]);
        }
    }
}

// ---------------- reduce: out = leaky(p0+p1+bx+cnt*bmx) [+resid] ----------------
__global__ void reduce_out(const float* __restrict__ part,
                           const float* __restrict__ bx, const float* __restrict__ bmx,
                           const float* __restrict__ cntf, const float* __restrict__ resid,
                           float* __restrict__ xout)
{
    int idx = blockIdx.x * blockDim.x + threadIdx.x;   // over NN*H/4
    if (idx >= NN * (H / 4)) return;
    int n = idx >> 5;                                   // 32 float4 per row
    int c4 = (idx & 31) << 2;
    float cf = cntf[n];
    float4 p0 = ((const float4*)part)[idx];
    float4 p1 = ((const float4*)(part + (size_t)NN * H))[idx];
    float4 b  = *(const float4*)&bx[c4];
    float4 bm = *(const float4*)&bmx[c4];
    float4 o;
    o.x = leaky(p0.x + p1.x + b.x + cf * bm.x);
    o.y = leaky(p0.y + p1.y + b.y + cf * bm.y);
    o.z = leaky(p0.z + p1.z + b.z + cf * bm.z);
    o.w = leaky(p0.w + p1.w + b.w + cf * bm.w);
    if (resid) {
        float4 r = ((const float4*)resid)[idx];
        o.x = leaky(r.x + o.x); o.y = leaky(r.y + o.y);
        o.z = leaky(r.z + o.z); o.w = leaky(r.w + o.w);
    }
    ((float4*)xout)[idx] = o;
}

// ---------------- launch ----------------
extern "C" void kernel_launch(void* const* d_in, const int* in_sizes, int n_in,
                              void* d_out, int out_size) {
    const float* x   = (const float*)d_in[0];
    const float* pos = (const float*)d_in[1];
    const int*   ei  = (const int*)d_in[2];
    const float* ea  = (const float*)d_in[3];
    const float* Wm  = (const float*)d_in[4];
    const float* bm  = (const float*)d_in[5];
    // d_in[6] = Wp, d_in[7] = bp : dead code (alpha unused)
    const float* Wx  = (const float*)d_in[8];
    const float* bx  = (const float*)d_in[9];
    float* out = (float*)d_out;

    float *F, *xb, *pb, *part, *cntf, *Wsp, *bmx;
    int *cnt, *rowbeg, *cursor, *colj, *eid, *total;
    cudaGetSymbolAddress((void**)&F,      g_F);
    cudaGetSymbolAddress((void**)&xb,     g_xbuf);
    cudaGetSymbolAddress((void**)&pb,     g_posbuf);
    cudaGetSymbolAddress((void**)&part,   g_part);
    cudaGetSymbolAddress((void**)&cnt,    g_cnt);
    cudaGetSymbolAddress((void**)&rowbeg, g_rowbeg);
    cudaGetSymbolAddress((void**)&cursor, g_cursor);
    cudaGetSymbolAddress((void**)&colj,   g_colj);
    cudaGetSymbolAddress((void**)&eid,    g_eid);
    cudaGetSymbolAddress((void**)&cntf,   g_cntf);
    cudaGetSymbolAddress((void**)&total,  g_total);
    cudaGetSymbolAddress((void**)&Wsp,    g_Wsplit);
    cudaGetSymbolAddress((void**)&bmx,    g_bmx);

    cnt_hist<<<(NE + 255) / 256, 256>>>(ei, cnt);
    alloc_rows<<<(NN + 255) / 256, 256>>>(cnt, rowbeg, cursor, cntf, total);
    build_csr<<<(NE + 255) / 256, 256>>>(ei, cursor, colj, eid, total);

    const size_t WLS = (size_t)NKT * 4 * 1024;
    const float* curx = x;
    const float* curp = pos;
    for (int l = 0; l < NLAYER; l++) {
        bool last = (l == NLAYER - 1);
        float* nx = last ? out : xb + (size_t)(l & 1) * NN * H;
        float* np = last ? out + (size_t)NN * H : pb + (size_t)(l & 1) * NN * 3;

        csr_layer<<<(NN * 32 + 127) / 128, 128>>>(curx, curp, rowbeg, colj, cntf, F, np);
        if (l == 0) {
            ea_csr<<<(NN * 16 + 255) / 256, 256>>>(rowbeg, cntf, eid, ea, F);
            dim3 gp(NLAYER, KA + 1);
            prep_weights<<<gp, 128>>>(Wm, bm, Wx, Wsp, bmx);
        }
        dim3 gg((NN + 63) / 64, 2);
        fused_layer_gemm<<<gg, 256>>>(curx, F, Wsp + (size_t)l * WLS, part);
        reduce_out<<<(NN * (H / 4) + 255) / 256, 256>>>(part, bx + (size_t)l * H,
                                                        bmx + l * H, cntf,
                                                        last ? x : nullptr, nx);
        curx = nx;
        curp = np;
    }
}

// round 15
// speedup vs baseline: 1.8680x; 1.0202x over previous
#include <cuda_runtime.h>
#include <cstdint>

#define NN     10000
#define NE     320000
#define H      128
#define HID    256
#define KM     336   // 2*H + 64 + 16  (F row width)
#define KX     384   // H + HID
#define KA     464   // H + KM         (fused GEMM K)
#define NSTEP  64
#define NLAYER 4
#define NKT    29    // KA/16
#define NSPLIT 4     // split-K factor

// ---------------- static device scratch ----------------
__device__ float g_F[(size_t)NN * KM];             // [cnt*x | Σx_j | Σsoh | Σea]
__device__ float g_xbuf[2][(size_t)NN * H];
__device__ float g_posbuf[2][(size_t)NN * 3];
__device__ float g_part[NSPLIT][(size_t)NN * H];   // split-K partials
__device__ int   g_cnt[NN];
__device__ int   g_rowbeg[NN];
__device__ int   g_cursor[NN];
__device__ int   g_colj[NE];
__device__ int   g_eid[NE];
__device__ float g_cntf[NN];
__device__ int   g_total[1];
// pre-split fragment-major weights: [l][kt][plane(hi=0,lo=1)][ks][nt][lane][reg]
__device__ float g_Wsplit[(size_t)NLAYER * NKT * 4 * 1024];
__device__ float g_bmx[NLAYER * H];                // bm @ Wx2

// K-tile split boundaries for NKT=29 over 4 blocks: 8,7,7,7
__constant__ int c_kt0[NSPLIT + 1] = {0, 8, 15, 22, 29};

__device__ __forceinline__ float leaky(float v) { return v > 0.f ? v : 0.01f * v; }
__device__ __forceinline__ float tf32_rna(float x) {
    float r; asm("cvt.rna.tf32.f32 %0, %1;" : "=f"(r) : "f"(x)); return r;
}
__device__ __forceinline__ void mma8(float* d, const uint32_t* a, const uint32_t* b) {
    asm volatile(
        "mma.sync.aligned.m16n8k8.row.col.f32.tf32.tf32.f32 "
        "{%0,%1,%2,%3}, {%4,%5,%6,%7}, {%8,%9}, {%0,%1,%2,%3};"
        : "+f"(d[0]), "+f"(d[1]), "+f"(d[2]), "+f"(d[3])
        : "r"(a[0]), "r"(a[1]), "r"(a[2]), "r"(a[3]), "r"(b[0]), "r"(b[1]));
}
__device__ __forceinline__ void cp16(uint32_t smem, const float* gmem) {
    asm volatile("cp.async.cg.shared.global [%0], [%1], 16;" :: "r"(smem), "l"(gmem) : "memory");
}
__device__ __forceinline__ void cp_commit() {
    asm volatile("cp.async.commit_group;" ::: "memory");
}
__device__ __forceinline__ void cp_wait0() {
    asm volatile("cp.async.wait_group 0;" ::: "memory");
}

// ---------------- preamble kernels ----------------
__global__ void cnt_hist(const int* __restrict__ ei, int* __restrict__ cnt) {
    int e = blockIdx.x * blockDim.x + threadIdx.x;
    if (e < NE) atomicAdd(&cnt[ei[e]], 1);
}

__global__ void alloc_rows(int* __restrict__ cnt, int* __restrict__ rowbeg,
                           int* __restrict__ cursor, float* __restrict__ cntf,
                           int* __restrict__ total) {
    int n = blockIdx.x * blockDim.x + threadIdx.x;
    int lane = threadIdx.x & 31;
    int v = (n < NN) ? cnt[n] : 0;
    int sc = v;
#pragma unroll
    for (int o = 1; o < 32; o <<= 1) {
        int u = __shfl_up_sync(0xffffffffu, sc, o);
        if (lane >= o) sc += u;
    }
    int wsum = __shfl_sync(0xffffffffu, sc, 31);
    int base = 0;
    if (lane == 0) base = atomicAdd(total, wsum);
    base = __shfl_sync(0xffffffffu, base, 0);
    int beg = base + sc - v;
    if (n < NN) {
        rowbeg[n] = beg; cursor[n] = beg; cntf[n] = (float)v;
        cnt[n] = 0;                                  // self-clean
    }
}

__global__ void build_csr(const int* __restrict__ ei, int* __restrict__ cursor,
                          int* __restrict__ colj, int* __restrict__ eid,
                          int* __restrict__ total) {
    int e = blockIdx.x * blockDim.x + threadIdx.x;
    if (e == 0) total[0] = 0;
    if (e < NE) {
        int p = atomicAdd(&cursor[ei[e]], 1);
        colj[p] = ei[NE + e];
        eid[p] = e;
    }
}

__global__ void ea_csr(const int* __restrict__ rowbeg, const float* __restrict__ cntf,
                       const int* __restrict__ eid, const float* __restrict__ ea,
                       float* __restrict__ F) {
    int gw = (blockIdx.x * blockDim.x + threadIdx.x) >> 4;
    int l = threadIdx.x & 15;
    if (gw >= NN) return;
    int beg = rowbeg[gw], end = beg + (int)cntf[gw];
    float s = 0.f;
    float v0 = 0.f, v1 = 0.f;
    if (beg < end)     v0 = ea[(size_t)eid[beg] * 16 + l];
    if (beg + 1 < end) v1 = ea[(size_t)eid[beg + 1] * 16 + l];
    for (int k = beg; k < end; k++) {
        float v = v0;
        v0 = v1;
        v1 = (k + 2 < end) ? ea[(size_t)eid[k + 2] * 16 + l] : 0.f;
        s += v;
    }
    F[(size_t)gw * KM + 320 + l] = s;
}

__global__ void prep_weights(const float* __restrict__ Wm, const float* __restrict__ bm,
                             const float* __restrict__ Wx,
                             float* __restrict__ Wsplit, float* __restrict__ bmx) {
    int l = blockIdx.x, y = blockIdx.y, n = threadIdx.x;
    const float* WxL = Wx + (size_t)l * KX * H;
    if (y < KA) {
        float w;
        if (y < H) {
            w = WxL[(size_t)y * H + n];
        } else {
            int r = y - H;
            const float* wm = Wm + (size_t)l * KM * HID + (size_t)r * HID;
            float s = 0.f;
#pragma unroll 8
            for (int h = 0; h < HID; h++) s += wm[h] * WxL[(size_t)(H + h) * H + n];
            w = s;
        }
        float hi = tf32_rna(w);
        float lo = tf32_rna(w - hi);
        int kt = y >> 4, kin = y & 15;
        int ks = kin >> 3, kk = kin & 7;
        int lane = ((n & 7) << 2) | (kk & 3);
        int reg = kk >> 2;
        int nt = n >> 3;
        size_t base = (((size_t)l * NKT + kt) * 4 + ks) * 1024 + nt * 64 + lane * 2 + reg;
        Wsplit[base] = hi;
        Wsplit[base + 2048] = lo;
    } else {
        const float* bmL = bm + (size_t)l * HID;
        float s = 0.f;
#pragma unroll 8
        for (int h = 0; h < HID; h++) s += bmL[h] * WxL[(size_t)(H + h) * H + n];
        bmx[l * H + n] = s;
    }
}

// ---------------- per-layer CSR kernel (measured-good R13 form, untouched) ----------------
__global__ __launch_bounds__(128) void csr_layer(
    const float* __restrict__ x, const float* __restrict__ pos,
    const int* __restrict__ rowbeg, const int* __restrict__ colj,
    const float* __restrict__ cntf, float* __restrict__ F, float* __restrict__ npos)
{
    int w = (blockIdx.x * blockDim.x + threadIdx.x) >> 5;
    int lane = threadIdx.x & 31;
    if (w >= NN) return;
    int beg = rowbeg[w];
    float cf = cntf[w];
    int end = beg + (int)cf;
    float4 xi = ((const float4*)(x + (size_t)w * H))[lane];
    float4 xs = make_float4(0.f, 0.f, 0.f, 0.f);
    float s0 = 0.f, s1 = 0.f, ps = 0.f;
    const float step = 10.f / 63.f;
    float c0 = (2 * lane) * step, c1 = (2 * lane + 1) * step;

    int kend2 = beg + (((end - beg) >> 1) << 1);

    float4 xan = make_float4(0.f, 0.f, 0.f, 0.f), xbn = xan;
    float pan = 0.f, pbn = 0.f;
    if (beg < kend2) {
        int j0 = colj[beg], j1 = colj[beg + 1];
        xan = ((const float4*)(x + (size_t)j0 * H))[lane];
        xbn = ((const float4*)(x + (size_t)j1 * H))[lane];
        if (lane < 3) { pan = pos[j0 * 3 + lane]; pbn = pos[j1 * 3 + lane]; }
    }

    for (int k = beg; k < kend2; k += 2) {
        float4 xa = xan, xb = xbn;
        float pa = pan, pb = pbn;
        if (k + 3 < kend2 + 1) {
            int j0 = colj[k + 2], j1 = colj[k + 3];
            xan = ((const float4*)(x + (size_t)j0 * H))[lane];
            xbn = ((const float4*)(x + (size_t)j1 * H))[lane];
            if (lane < 3) { pan = pos[j0 * 3 + lane]; pbn = pos[j1 * 3 + lane]; }
        }
        float a0 = xi.x - xa.x, a1 = xi.y - xa.y, a2 = xi.z - xa.z, a3 = xi.w - xa.w;
        float e0 = a0 * a0 + a1 * a1 + a2 * a2 + a3 * a3;
        float b0 = xi.x - xb.x, b1 = xi.y - xb.y, b2 = xi.z - xb.z, b3 = xi.w - xb.w;
        float e1 = b0 * b0 + b1 * b1 + b2 * b2 + b3 * b3;
        e0 += __shfl_xor_sync(0xffffffffu, e0, 16);
        e1 += __shfl_xor_sync(0xffffffffu, e1, 16);
        float v = (lane & 16) ? e1 : e0;
        v += __shfl_xor_sync(0xffffffffu, v, 8);
        v += __shfl_xor_sync(0xffffffffu, v, 4);
        v += __shfl_xor_sync(0xffffffffu, v, 2);
        v += __shfl_xor_sync(0xffffffffu, v, 1);
        float vo = __shfl_xor_sync(0xffffffffu, v, 16);
        float sum0 = (lane & 16) ? vo : v;
        float sum1 = (lane & 16) ? v : vo;
        float r0 = sqrtf(sum0), r1 = sqrtf(sum1);
        float u0 = r0 - c0, u1 = r0 - c1, v0 = r1 - c0, v1 = r1 - c1;
        s0 += __expf(-10.f * u0 * u0) + __expf(-10.f * v0 * v0);
        s1 += __expf(-10.f * u1 * u1) + __expf(-10.f * v1 * v1);
        xs.x += xa.x + xb.x; xs.y += xa.y + xb.y;
        xs.z += xa.z + xb.z; xs.w += xa.w + xb.w;
        ps += pa + pb;
    }
    if (kend2 < end) {
        int j0 = colj[kend2];
        float4 xa = ((const float4*)(x + (size_t)j0 * H))[lane];
        float pa = 0.f;
        if (lane < 3) pa = pos[j0 * 3 + lane];
        float a0 = xi.x - xa.x, a1 = xi.y - xa.y, a2 = xi.z - xa.z, a3 = xi.w - xa.w;
        float e0 = a0 * a0 + a1 * a1 + a2 * a2 + a3 * a3;
#pragma unroll
        for (int o = 16; o; o >>= 1) e0 += __shfl_xor_sync(0xffffffffu, e0, o);
        float r0 = sqrtf(e0);
        float u0 = r0 - c0, u1 = r0 - c1;
        s0 += __expf(-10.f * u0 * u0);
        s1 += __expf(-10.f * u1 * u1);
        xs.x += xa.x; xs.y += xa.y; xs.z += xa.z; xs.w += xa.w;
        ps += pa;
    }

    float* Fr = F + (size_t)w * KM;
    ((float4*)Fr)[lane]           = make_float4(cf * xi.x, cf * xi.y, cf * xi.z, cf * xi.w);
    ((float4*)(Fr + H))[lane]     = xs;
    ((float2*)(Fr + 2 * H))[lane] = make_float2(s0, s1);
    if (lane < 3) {
        float p = pos[w * 3 + lane];
        npos[w * 3 + lane] = p + (cf * p - ps) / fmaxf(cf, 1.f);
    }
}

// ---------------- fused layer GEMM: 3xTF32, split-K=4 (grid.y = quarter) ----------------
#define AIDX(buf,ks,mt,rp,lane,sub) ((((((buf)*2+(ks))*4+(mt))*2+(rp))*33 + (lane))*2 + (sub))
#define BIDX2(buf,ks,nt,lane,reg)   ((((buf)*2+(ks))*16+(nt))*68 + (lane)*2 + (reg))
__global__ __launch_bounds__(256, 2) void fused_layer_gemm(
    const float* __restrict__ x, const float* __restrict__ F,
    const float* __restrict__ Wsp, float* __restrict__ part)
{
    __shared__ __align__(16) float AH[2 * 2 * 4 * 2 * 33 * 2], AL[2 * 2 * 4 * 2 * 33 * 2];
    __shared__ __align__(16) float BH[2 * 2 * 16 * 68],        BL[2 * 2 * 16 * 68];

    int t = threadIdx.x;
    int m0 = blockIdx.x * 64;
    int ktb = blockIdx.y;
    int kt0 = c_kt0[ktb];
    int nkt = c_kt0[ktb + 1] - kt0;
    float* myart = part + (size_t)ktb * NN * H;

    int wid = t >> 5, lane = t & 31;
    int mtg0 = (wid >> 2) * 2;
    int ntg0 = (wid & 3) * 4;

    int am = t & 63, akq = (t >> 6) << 2;
    int aks = akq >> 3, arp = (akq >> 2) & 1;
    int amt = am >> 4, asub = (am >> 3) & 1, alb = (am & 7) << 2;
    int mm = m0 + am; if (mm >= NN) mm = NN - 1;
    const float* rowx = x + (size_t)mm * H;
    const float* rowF = F + (size_t)mm * KM - H;

    int bnt = (t >> 4) & 15, bpair = t & 15;
    uint32_t sBH = (uint32_t)__cvta_generic_to_shared(BH);
    uint32_t sBL = (uint32_t)__cvta_generic_to_shared(BL);
    uint32_t smo[2][2];
#pragma unroll
    for (int ks = 0; ks < 2; ks++)
#pragma unroll
        for (int b = 0; b < 2; b++)
            smo[ks][b] = (uint32_t)(BIDX2(b, ks, bnt, bpair * 2, 0) * 4);
    int gbase = bnt * 64 + bpair * 4;

    float acc[2][4][4];
#pragma unroll
    for (int i = 0; i < 2; i++)
#pragma unroll
        for (int j = 0; j < 4; j++)
#pragma unroll
            for (int q = 0; q < 4; q++) acc[i][j][q] = 0.f;

    float4 aR;
    {
        cp16(sBH + smo[0][0], Wsp + (kt0 * 4 + 0) * 1024 + gbase);
        cp16(sBH + smo[1][0], Wsp + (kt0 * 4 + 1) * 1024 + gbase);
        cp16(sBL + smo[0][0], Wsp + (kt0 * 4 + 2) * 1024 + gbase);
        cp16(sBL + smo[1][0], Wsp + (kt0 * 4 + 3) * 1024 + gbase);
        cp_commit();
        int k = kt0 * 16 + akq;
        aR = *(const float4*)((k < H ? rowx : rowF) + k);
        int ab = AIDX(0, aks, amt, arp, alb, asub);
        float h0 = tf32_rna(aR.x), h1 = tf32_rna(aR.y), h2 = tf32_rna(aR.z), h3 = tf32_rna(aR.w);
        AH[ab + 0] = h0; AH[ab + 2] = h1; AH[ab + 4] = h2; AH[ab + 6] = h3;
        AL[ab + 0] = tf32_rna(aR.x - h0); AL[ab + 2] = tf32_rna(aR.y - h1);
        AL[ab + 4] = tf32_rna(aR.z - h2); AL[ab + 6] = tf32_rna(aR.w - h3);
        cp_wait0();
    }
    __syncthreads();

    for (int it = 0; it < nkt; it++) {
        int cur = it & 1;
        if (it + 1 < nkt) {
            int nxt = cur ^ 1;
            int kt = kt0 + it + 1;
            cp16(sBH + smo[0][nxt], Wsp + (kt * 4 + 0) * 1024 + gbase);
            cp16(sBH + smo[1][nxt], Wsp + (kt * 4 + 1) * 1024 + gbase);
            cp16(sBL + smo[0][nxt], Wsp + (kt * 4 + 2) * 1024 + gbase);
            cp16(sBL + smo[1][nxt], Wsp + (kt * 4 + 3) * 1024 + gbase);
            cp_commit();
            int k = kt * 16 + akq;
            aR = *(const float4*)((k < H ? rowx : rowF) + k);
        }

#pragma unroll
        for (int ks = 0; ks < 2; ks++) {
            uint32_t ah[2][4], al[2][4], bh[4][2], bl[4][2];
#pragma unroll
            for (int mt = 0; mt < 2; mt++) {
                float2 h0 = *(const float2*)&AH[AIDX(cur, ks, mtg0 + mt, 0, lane, 0)];
                float2 h1 = *(const float2*)&AH[AIDX(cur, ks, mtg0 + mt, 1, lane, 0)];
                float2 l0 = *(const float2*)&AL[AIDX(cur, ks, mtg0 + mt, 0, lane, 0)];
                float2 l1 = *(const float2*)&AL[AIDX(cur, ks, mtg0 + mt, 1, lane, 0)];
                ah[mt][0] = __float_as_uint(h0.x); ah[mt][1] = __float_as_uint(h0.y);
                ah[mt][2] = __float_as_uint(h1.x); ah[mt][3] = __float_as_uint(h1.y);
                al[mt][0] = __float_as_uint(l0.x); al[mt][1] = __float_as_uint(l0.y);
                al[mt][2] = __float_as_uint(l1.x); al[mt][3] = __float_as_uint(l1.y);
            }
#pragma unroll
            for (int nt = 0; nt < 4; nt++) {
                float2 wh = *(const float2*)&BH[BIDX2(cur, ks, ntg0 + nt, lane, 0)];
                float2 wl = *(const float2*)&BL[BIDX2(cur, ks, ntg0 + nt, lane, 0)];
                bh[nt][0] = __float_as_uint(wh.x); bh[nt][1] = __float_as_uint(wh.y);
                bl[nt][0] = __float_as_uint(wl.x); bl[nt][1] = __float_as_uint(wl.y);
            }
#pragma unroll
            for (int mt = 0; mt < 2; mt++)
#pragma unroll
                for (int nt = 0; nt < 4; nt++) {
                    mma8(acc[mt][nt], al[mt], bh[nt]);
                    mma8(acc[mt][nt], ah[mt], bl[nt]);
                    mma8(acc[mt][nt], ah[mt], bh[nt]);
                }
        }

        if (it + 1 < nkt) {
            int nxt = cur ^ 1;
            int ab = AIDX(nxt, aks, amt, arp, alb, asub);
            float h0 = tf32_rna(aR.x), h1 = tf32_rna(aR.y), h2 = tf32_rna(aR.z), h3 = tf32_rna(aR.w);
            AH[ab + 0] = h0; AH[ab + 2] = h1; AH[ab + 4] = h2; AH[ab + 6] = h3;
            AL[ab + 0] = tf32_rna(aR.x - h0); AL[ab + 2] = tf32_rna(aR.y - h1);
            AL[ab + 4] = tf32_rna(aR.z - h2); AL[ab + 6] = tf32_rna(aR.w - h3);
            cp_wait0();
            __syncthreads();
        }
    }

    // epilogue: write raw partials
    int g = lane >> 2, c = lane & 3;
    int mb = (wid >> 2) * 32, nb = (wid & 3) * 32;
#pragma unroll
    for (int mt = 0; mt < 2; mt++) {
        int r0 = m0 + mb + mt * 16 + g;
        int r1 = r0 + 8;
#pragma unroll
        for (int nt = 0; nt < 4; nt++) {
            int col = nb + nt * 8 + 2 * c;
            if (r0 < NN)
                *(float2*)&myart[(size_t)r0 * H + col] = make_float2(acc[mt][nt][0], acc[mt][nt][1]);
            if (r1 < NN)
                *(float2*)&myart[(size_t)r1 * H + col] = make_float2(acc[mt][nt][2], acc[mt][nt][3]);
        }
    }
}

// ---------------- reduce: out = leaky(Σ part + bx + cnt*bmx) [+resid] ----------------
__global__ void reduce_out(const float* __restrict__ part,
                           const float* __restrict__ bx, const float* __restrict__ bmx,
                           const float* __restrict__ cntf, const float* __restrict__ resid,
                           float* __restrict__ xout)
{
    int idx = blockIdx.x * blockDim.x + threadIdx.x;   // over NN*H/4
    if (idx >= NN * (H / 4)) return;
    int n = idx >> 5;                                   // 32 float4 per row
    int c4 = (idx & 31) << 2;
    float cf = cntf[n];
    float4 p0 = ((const float4*)part)[idx];
    float4 p1 = ((const float4*)(part + (size_t)NN * H))[idx];
    float4 p2 = ((const float4*)(part + (size_t)2 * NN * H))[idx];
    float4 p3 = ((const float4*)(part + (size_t)3 * NN * H))[idx];
    float4 b  = *(const float4*)&bx[c4];
    float4 bm = *(const float4*)&bmx[c4];
    float4 o;
    o.x = leaky((p0.x + p1.x) + (p2.x + p3.x) + b.x + cf * bm.x);
    o.y = leaky((p0.y + p1.y) + (p2.y + p3.y) + b.y + cf * bm.y);
    o.z = leaky((p0.z + p1.z) + (p2.z + p3.z) + b.z + cf * bm.z);
    o.w = leaky((p0.w + p1.w) + (p2.w + p3.w) + b.w + cf * bm.w);
    if (resid) {
        float4 r = ((const float4*)resid)[idx];
        o.x = leaky(r.x + o.x); o.y = leaky(r.y + o.y);
        o.z = leaky(r.z + o.z); o.w = leaky(r.w + o.w);
    }
    ((float4*)xout)[idx] = o;
}

// ---------------- launch ----------------
extern "C" void kernel_launch(void* const* d_in, const int* in_sizes, int n_in,
                              void* d_out, int out_size) {
    const float* x   = (const float*)d_in[0];
    const float* pos = (const float*)d_in[1];
    const int*   ei  = (const int*)d_in[2];
    const float* ea  = (const float*)d_in[3];
    const float* Wm  = (const float*)d_in[4];
    const float* bm  = (const float*)d_in[5];
    // d_in[6] = Wp, d_in[7] = bp : dead code (alpha unused)
    const float* Wx  = (const float*)d_in[8];
    const float* bx  = (const float*)d_in[9];
    float* out = (float*)d_out;

    float *F, *xb, *pb, *part, *cntf, *Wsp, *bmx;
    int *cnt, *rowbeg, *cursor, *colj, *eid, *total;
    cudaGetSymbolAddress((void**)&F,      g_F);
    cudaGetSymbolAddress((void**)&xb,     g_xbuf);
    cudaGetSymbolAddress((void**)&pb,     g_posbuf);
    cudaGetSymbolAddress((void**)&part,   g_part);
    cudaGetSymbolAddress((void**)&cnt,    g_cnt);
    cudaGetSymbolAddress((void**)&rowbeg, g_rowbeg);
    cudaGetSymbolAddress((void**)&cursor, g_cursor);
    cudaGetSymbolAddress((void**)&colj,   g_colj);
    cudaGetSymbolAddress((void**)&eid,    g_eid);
    cudaGetSymbolAddress((void**)&cntf,   g_cntf);
    cudaGetSymbolAddress((void**)&total,  g_total);
    cudaGetSymbolAddress((void**)&Wsp,    g_Wsplit);
    cudaGetSymbolAddress((void**)&bmx,    g_bmx);

    cnt_hist<<<(NE + 255) / 256, 256>>>(ei, cnt);
    alloc_rows<<<(NN + 255) / 256, 256>>>(cnt, rowbeg, cursor, cntf, total);
    build_csr<<<(NE + 255) / 256, 256>>>(ei, cursor, colj, eid, total);

    const size_t WLS = (size_t)NKT * 4 * 1024;
    const float* curx = x;
    const float* curp = pos;
    for (int l = 0; l < NLAYER; l++) {
        bool last = (l == NLAYER - 1);
        float* nx = last ? out : xb + (size_t)(l & 1) * NN * H;
        float* np = last ? out + (size_t)NN * H : pb + (size_t)(l & 1) * NN * 3;

        csr_layer<<<(NN * 32 + 127) / 128, 128>>>(curx, curp, rowbeg, colj, cntf, F, np);
        if (l == 0) {
            ea_csr<<<(NN * 16 + 255) / 256, 256>>>(rowbeg, cntf, eid, ea, F);
            dim3 gp(NLAYER, KA + 1);
            prep_weights<<<gp, 128>>>(Wm, bm, Wx, Wsp, bmx);
        }
        dim3 gg((NN + 63) / 64, NSPLIT);
        fused_layer_gemm<<<gg, 256>>>(curx, F, Wsp + (size_t)l * WLS, part);
        reduce_out<<<(NN * (H / 4) + 255) / 256, 256>>>(part, bx + (size_t)l * H,
                                                        bmx + l * H, cntf,
                                                        last ? x : nullptr, nx);
        curx = nx;
        curp = np;
    }
}

// round 16
// speedup vs baseline: 1.8892x; 1.0113x over previous
#include <cuda_runtime.h>
#include <cstdint>

#define NN     10000
#define NE     320000
#define H      128
#define HID    256
#define KM     336   // 2*H + 64 + 16  (F row width)
#define KX     384   // H + HID
#define KA     464   // H + KM         (fused GEMM K)
#define NSTEP  64
#define NLAYER 4
#define NKT    29    // KA/16
#define NSPLIT 4     // split-K factor

// ---------------- static device scratch ----------------
__device__ float g_F[(size_t)NN * KM];             // [cnt*x | Σx_j | Σsoh | Σea]
__device__ float g_xbuf[2][(size_t)NN * H];
__device__ float g_posbuf[2][(size_t)NN * 3];
__device__ float g_part[NSPLIT][(size_t)NN * H];   // split-K partials
__device__ int   g_cnt[NN];
__device__ int   g_rowbeg[NN];
__device__ int   g_cursor[NN];
__device__ int   g_colj[NE];
__device__ int   g_eid[NE];
__device__ float g_cntf[NN];
__device__ int   g_total[1];
__device__ float g_Wsplit[(size_t)NLAYER * NKT * 4 * 1024];
__device__ float g_bmx[NLAYER * H];                // bm @ Wx2

__constant__ int c_kt0[NSPLIT + 1] = {0, 8, 15, 22, 29};

typedef unsigned long long u64w;
__device__ __forceinline__ float leaky(float v) { return v > 0.f ? v : 0.01f * v; }
__device__ __forceinline__ float tf32_rna(float x) {
    float r; asm("cvt.rna.tf32.f32 %0, %1;" : "=f"(r) : "f"(x)); return r;
}
// ---- packed f32x2 (sm_103a) ----
__device__ __forceinline__ u64w fma_x2(u64w a, u64w b, u64w c) {
    u64w r; asm("fma.rn.f32x2 %0, %1, %2, %3;" : "=l"(r) : "l"(a), "l"(b), "l"(c)); return r;
}
__device__ __forceinline__ u64w mul_x2(u64w a, u64w b) {
    u64w r; asm("mul.rn.f32x2 %0, %1, %2;" : "=l"(r) : "l"(a), "l"(b)); return r;
}
__device__ __forceinline__ u64w add_x2(u64w a, u64w b) {
    u64w r; asm("add.rn.f32x2 %0, %1, %2;" : "=l"(r) : "l"(a), "l"(b)); return r;
}
__device__ __forceinline__ u64w pk2(float lo, float hi) {
    u64w r; asm("mov.b64 %0, {%1, %2};" : "=l"(r) : "f"(lo), "f"(hi)); return r;
}
__device__ __forceinline__ float2 unpk(u64w v) {
    float lo, hi; asm("mov.b64 {%0, %1}, %2;" : "=f"(lo), "=f"(hi) : "l"(v));
    return make_float2(lo, hi);
}
__device__ __forceinline__ void mma8(float* d, const uint32_t* a, const uint32_t* b) {
    asm volatile(
        "mma.sync.aligned.m16n8k8.row.col.f32.tf32.tf32.f32 "
        "{%0,%1,%2,%3}, {%4,%5,%6,%7}, {%8,%9}, {%0,%1,%2,%3};"
        : "+f"(d[0]), "+f"(d[1]), "+f"(d[2]), "+f"(d[3])
        : "r"(a[0]), "r"(a[1]), "r"(a[2]), "r"(a[3]), "r"(b[0]), "r"(b[1]));
}
__device__ __forceinline__ void cp16(uint32_t smem, const float* gmem) {
    asm volatile("cp.async.cg.shared.global [%0], [%1], 16;" :: "r"(smem), "l"(gmem) : "memory");
}
__device__ __forceinline__ void cp_commit() {
    asm volatile("cp.async.commit_group;" ::: "memory");
}
__device__ __forceinline__ void cp_wait0() {
    asm volatile("cp.async.wait_group 0;" ::: "memory");
}

// ---------------- preamble kernels ----------------
__global__ void cnt_hist(const int* __restrict__ ei, int* __restrict__ cnt) {
    int e = blockIdx.x * blockDim.x + threadIdx.x;
    if (e < NE) atomicAdd(&cnt[ei[e]], 1);
}

__global__ void alloc_rows(int* __restrict__ cnt, int* __restrict__ rowbeg,
                           int* __restrict__ cursor, float* __restrict__ cntf,
                           int* __restrict__ total) {
    int n = blockIdx.x * blockDim.x + threadIdx.x;
    int lane = threadIdx.x & 31;
    int v = (n < NN) ? cnt[n] : 0;
    int sc = v;
#pragma unroll
    for (int o = 1; o < 32; o <<= 1) {
        int u = __shfl_up_sync(0xffffffffu, sc, o);
        if (lane >= o) sc += u;
    }
    int wsum = __shfl_sync(0xffffffffu, sc, 31);
    int base = 0;
    if (lane == 0) base = atomicAdd(total, wsum);
    base = __shfl_sync(0xffffffffu, base, 0);
    int beg = base + sc - v;
    if (n < NN) {
        rowbeg[n] = beg; cursor[n] = beg; cntf[n] = (float)v;
        cnt[n] = 0;                                  // self-clean
    }
}

__global__ void build_csr(const int* __restrict__ ei, int* __restrict__ cursor,
                          int* __restrict__ colj, int* __restrict__ eid,
                          int* __restrict__ total) {
    int e = blockIdx.x * blockDim.x + threadIdx.x;
    if (e == 0) total[0] = 0;
    if (e < NE) {
        int p = atomicAdd(&cursor[ei[e]], 1);
        colj[p] = ei[NE + e];
        eid[p] = e;
    }
}

__global__ void ea_csr(const int* __restrict__ rowbeg, const float* __restrict__ cntf,
                       const int* __restrict__ eid, const float* __restrict__ ea,
                       float* __restrict__ F) {
    int gw = (blockIdx.x * blockDim.x + threadIdx.x) >> 4;
    int l = threadIdx.x & 15;
    if (gw >= NN) return;
    int beg = rowbeg[gw], end = beg + (int)cntf[gw];
    float s = 0.f;
    float v0 = 0.f, v1 = 0.f;
    if (beg < end)     v0 = ea[(size_t)eid[beg] * 16 + l];
    if (beg + 1 < end) v1 = ea[(size_t)eid[beg + 1] * 16 + l];
    for (int k = beg; k < end; k++) {
        float v = v0;
        v0 = v1;
        v1 = (k + 2 < end) ? ea[(size_t)eid[k + 2] * 16 + l] : 0.f;
        s += v;
    }
    F[(size_t)gw * KM + 320 + l] = s;
}

__global__ void prep_weights(const float* __restrict__ Wm, const float* __restrict__ bm,
                             const float* __restrict__ Wx,
                             float* __restrict__ Wsplit, float* __restrict__ bmx) {
    int l = blockIdx.x, y = blockIdx.y, n = threadIdx.x;
    const float* WxL = Wx + (size_t)l * KX * H;
    if (y < KA) {
        float w;
        if (y < H) {
            w = WxL[(size_t)y * H + n];
        } else {
            int r = y - H;
            const float* wm = Wm + (size_t)l * KM * HID + (size_t)r * HID;
            float s = 0.f;
#pragma unroll 8
            for (int h = 0; h < HID; h++) s += wm[h] * WxL[(size_t)(H + h) * H + n];
            w = s;
        }
        float hi = tf32_rna(w);
        float lo = tf32_rna(w - hi);
        int kt = y >> 4, kin = y & 15;
        int ks = kin >> 3, kk = kin & 7;
        int lane = ((n & 7) << 2) | (kk & 3);
        int reg = kk >> 2;
        int nt = n >> 3;
        size_t base = (((size_t)l * NKT + kt) * 4 + ks) * 1024 + nt * 64 + lane * 2 + reg;
        Wsplit[base] = hi;
        Wsplit[base + 2048] = lo;
    } else {
        const float* bmL = bm + (size_t)l * HID;
        float s = 0.f;
#pragma unroll 8
        for (int h = 0; h < HID; h++) s += bmL[h] * WxL[(size_t)(H + h) * H + n];
        bmx[l * H + n] = s;
    }
}

// ---------------- per-layer CSR kernel: packed f32x2 arithmetic ----------------
__global__ __launch_bounds__(128) void csr_layer(
    const float* __restrict__ x, const float* __restrict__ pos,
    const int* __restrict__ rowbeg, const int* __restrict__ colj,
    const float* __restrict__ cntf, float* __restrict__ F, float* __restrict__ npos)
{
    int w = (blockIdx.x * blockDim.x + threadIdx.x) >> 5;
    int lane = threadIdx.x & 31;
    if (w >= NN) return;
    int beg = rowbeg[w];
    float cf = cntf[w];
    int end = beg + (int)cf;
    float4 xi = ((const float4*)(x + (size_t)w * H))[lane];
    u64w xi01 = pk2(xi.x, xi.y), xi23 = pk2(xi.z, xi.w);
    const u64w NEG1 = pk2(-1.f, -1.f);
    u64w xs01 = pk2(0.f, 0.f), xs23 = pk2(0.f, 0.f);
    float s0 = 0.f, s1 = 0.f, ps = 0.f;
    const float step = 10.f / 63.f;
    float c0 = (2 * lane) * step, c1 = (2 * lane + 1) * step;

    int kend2 = beg + (((end - beg) >> 1) << 1);

    ulonglong2 van = make_ulonglong2(0ull, 0ull), vbn = van;
    float pan = 0.f, pbn = 0.f;
    if (beg < kend2) {
        int j0 = colj[beg], j1 = colj[beg + 1];
        van = ((const ulonglong2*)(x + (size_t)j0 * H))[lane];
        vbn = ((const ulonglong2*)(x + (size_t)j1 * H))[lane];
        if (lane < 3) { pan = pos[j0 * 3 + lane]; pbn = pos[j1 * 3 + lane]; }
    }

    for (int k = beg; k < kend2; k += 2) {
        ulonglong2 va = van, vb = vbn;
        float pa = pan, pb = pbn;
        if (k + 2 < kend2) {
            int j0 = colj[k + 2], j1 = colj[k + 3];
            van = ((const ulonglong2*)(x + (size_t)j0 * H))[lane];
            vbn = ((const ulonglong2*)(x + (size_t)j1 * H))[lane];
            if (lane < 3) { pan = pos[j0 * 3 + lane]; pbn = pos[j1 * 3 + lane]; }
        }
        // packed diff + square-sum, two independent chains
        u64w da01 = fma_x2(xi01, NEG1, va.x);
        u64w da23 = fma_x2(xi23, NEG1, va.y);
        u64w db01 = fma_x2(xi01, NEG1, vb.x);
        u64w db23 = fma_x2(xi23, NEG1, vb.y);
        u64w qa = mul_x2(da01, da01); qa = fma_x2(da23, da23, qa);
        u64w qb = mul_x2(db01, db01); qb = fma_x2(db23, db23, qb);
        float2 fa = unpk(qa), fb = unpk(qb);
        float e0 = fa.x + fa.y;
        float e1 = fb.x + fb.y;
        // 7-shfl cross-half shared reduction
        e0 += __shfl_xor_sync(0xffffffffu, e0, 16);
        e1 += __shfl_xor_sync(0xffffffffu, e1, 16);
        float v = (lane & 16) ? e1 : e0;
        v += __shfl_xor_sync(0xffffffffu, v, 8);
        v += __shfl_xor_sync(0xffffffffu, v, 4);
        v += __shfl_xor_sync(0xffffffffu, v, 2);
        v += __shfl_xor_sync(0xffffffffu, v, 1);
        float vo = __shfl_xor_sync(0xffffffffu, v, 16);
        float sum0 = (lane & 16) ? vo : v;
        float sum1 = (lane & 16) ? v : vo;
        float r0 = sqrtf(sum0), r1 = sqrtf(sum1);
        float u0 = r0 - c0, u1 = r0 - c1, v0 = r1 - c0, v1 = r1 - c1;
        s0 += __expf(-10.f * u0 * u0) + __expf(-10.f * v0 * v0);
        s1 += __expf(-10.f * u1 * u1) + __expf(-10.f * v1 * v1);
        // packed xs accumulation
        xs01 = add_x2(xs01, add_x2(va.x, vb.x));
        xs23 = add_x2(xs23, add_x2(va.y, vb.y));
        ps += pa + pb;
    }
    if (kend2 < end) {                                 // odd tail (packed too)
        int j0 = colj[kend2];
        ulonglong2 va = ((const ulonglong2*)(x + (size_t)j0 * H))[lane];
        float pa = 0.f;
        if (lane < 3) pa = pos[j0 * 3 + lane];
        u64w da01 = fma_x2(xi01, NEG1, va.x);
        u64w da23 = fma_x2(xi23, NEG1, va.y);
        u64w qa = mul_x2(da01, da01); qa = fma_x2(da23, da23, qa);
        float2 fa = unpk(qa);
        float e0 = fa.x + fa.y;
#pragma unroll
        for (int o = 16; o; o >>= 1) e0 += __shfl_xor_sync(0xffffffffu, e0, o);
        float r0 = sqrtf(e0);
        float u0 = r0 - c0, u1 = r0 - c1;
        s0 += __expf(-10.f * u0 * u0);
        s1 += __expf(-10.f * u1 * u1);
        xs01 = add_x2(xs01, va.x);
        xs23 = add_x2(xs23, va.y);
        ps += pa;
    }

    float2 xsa = unpk(xs01), xsb = unpk(xs23);
    float* Fr = F + (size_t)w * KM;
    ((float4*)Fr)[lane]           = make_float4(cf * xi.x, cf * xi.y, cf * xi.z, cf * xi.w);
    ((float4*)(Fr + H))[lane]     = make_float4(xsa.x, xsa.y, xsb.x, xsb.y);
    ((float2*)(Fr + 2 * H))[lane] = make_float2(s0, s1);
    if (lane < 3) {
        float p = pos[w * 3 + lane];
        npos[w * 3 + lane] = p + (cf * p - ps) / fmaxf(cf, 1.f);
    }
}

// ---------------- fused layer GEMM (measured-good R15 form, untouched) ----------------
#define AIDX(buf,ks,mt,rp,lane,sub) ((((((buf)*2+(ks))*4+(mt))*2+(rp))*33 + (lane))*2 + (sub))
#define BIDX2(buf,ks,nt,lane,reg)   ((((buf)*2+(ks))*16+(nt))*68 + (lane)*2 + (reg))
__global__ __launch_bounds__(256, 2) void fused_layer_gemm(
    const float* __restrict__ x, const float* __restrict__ F,
    const float* __restrict__ Wsp, float* __restrict__ part)
{
    __shared__ __align__(16) float AH[2 * 2 * 4 * 2 * 33 * 2], AL[2 * 2 * 4 * 2 * 33 * 2];
    __shared__ __align__(16) float BH[2 * 2 * 16 * 68],        BL[2 * 2 * 16 * 68];

    int t = threadIdx.x;
    int m0 = blockIdx.x * 64;
    int ktb = blockIdx.y;
    int kt0 = c_kt0[ktb];
    int nkt = c_kt0[ktb + 1] - kt0;
    float* myart = part + (size_t)ktb * NN * H;

    int wid = t >> 5, lane = t & 31;
    int mtg0 = (wid >> 2) * 2;
    int ntg0 = (wid & 3) * 4;

    int am = t & 63, akq = (t >> 6) << 2;
    int aks = akq >> 3, arp = (akq >> 2) & 1;
    int amt = am >> 4, asub = (am >> 3) & 1, alb = (am & 7) << 2;
    int mm = m0 + am; if (mm >= NN) mm = NN - 1;
    const float* rowx = x + (size_t)mm * H;
    const float* rowF = F + (size_t)mm * KM - H;

    int bnt = (t >> 4) & 15, bpair = t & 15;
    uint32_t sBH = (uint32_t)__cvta_generic_to_shared(BH);
    uint32_t sBL = (uint32_t)__cvta_generic_to_shared(BL);
    uint32_t smo[2][2];
#pragma unroll
    for (int ks = 0; ks < 2; ks++)
#pragma unroll
        for (int b = 0; b < 2; b++)
            smo[ks][b] = (uint32_t)(BIDX2(b, ks, bnt, bpair * 2, 0) * 4);
    int gbase = bnt * 64 + bpair * 4;

    float acc[2][4][4];
#pragma unroll
    for (int i = 0; i < 2; i++)
#pragma unroll
        for (int j = 0; j < 4; j++)
#pragma unroll
            for (int q = 0; q < 4; q++) acc[i][j][q] = 0.f;

    float4 aR;
    {
        cp16(sBH + smo[0][0], Wsp + (kt0 * 4 + 0) * 1024 + gbase);
        cp16(sBH + smo[1][0], Wsp + (kt0 * 4 + 1) * 1024 + gbase);
        cp16(sBL + smo[0][0], Wsp + (kt0 * 4 + 2) * 1024 + gbase);
        cp16(sBL + smo[1][0], Wsp + (kt0 * 4 + 3) * 1024 + gbase);
        cp_commit();
        int k = kt0 * 16 + akq;
        aR = *(const float4*)((k < H ? rowx : rowF) + k);
        int ab = AIDX(0, aks, amt, arp, alb, asub);
        float h0 = tf32_rna(aR.x), h1 = tf32_rna(aR.y), h2 = tf32_rna(aR.z), h3 = tf32_rna(aR.w);
        AH[ab + 0] = h0; AH[ab + 2] = h1; AH[ab + 4] = h2; AH[ab + 6] = h3;
        AL[ab + 0] = tf32_rna(aR.x - h0); AL[ab + 2] = tf32_rna(aR.y - h1);
        AL[ab + 4] = tf32_rna(aR.z - h2); AL[ab + 6] = tf32_rna(aR.w - h3);
        cp_wait0();
    }
    __syncthreads();

    for (int it = 0; it < nkt; it++) {
        int cur = it & 1;
        if (it + 1 < nkt) {
            int nxt = cur ^ 1;
            int kt = kt0 + it + 1;
            cp16(sBH + smo[0][nxt], Wsp + (kt * 4 + 0) * 1024 + gbase);
            cp16(sBH + smo[1][nxt], Wsp + (kt * 4 + 1) * 1024 + gbase);
            cp16(sBL + smo[0][nxt], Wsp + (kt * 4 + 2) * 1024 + gbase);
            cp16(sBL + smo[1][nxt], Wsp + (kt * 4 + 3) * 1024 + gbase);
            cp_commit();
            int k = kt * 16 + akq;
            aR = *(const float4*)((k < H ? rowx : rowF) + k);
        }

#pragma unroll
        for (int ks = 0; ks < 2; ks++) {
            uint32_t ah[2][4], al[2][4], bh[4][2], bl[4][2];
#pragma unroll
            for (int mt = 0; mt < 2; mt++) {
                float2 h0 = *(const float2*)&AH[AIDX(cur, ks, mtg0 + mt, 0, lane, 0)];
                float2 h1 = *(const float2*)&AH[AIDX(cur, ks, mtg0 + mt, 1, lane, 0)];
                float2 l0 = *(const float2*)&AL[AIDX(cur, ks, mtg0 + mt, 0, lane, 0)];
                float2 l1 = *(const float2*)&AL[AIDX(cur, ks, mtg0 + mt, 1, lane, 0)];
                ah[mt][0] = __float_as_uint(h0.x); ah[mt][1] = __float_as_uint(h0.y);
                ah[mt][2] = __float_as_uint(h1.x); ah[mt][3] = __float_as_uint(h1.y);
                al[mt][0] = __float_as_uint(l0.x); al[mt][1] = __float_as_uint(l0.y);
                al[mt][2] = __float_as_uint(l1.x); al[mt][3] = __float_as_uint(l1.y);
            }
#pragma unroll
            for (int nt = 0; nt < 4; nt++) {
                float2 wh = *(const float2*)&BH[BIDX2(cur, ks, ntg0 + nt, lane, 0)];
                float2 wl = *(const float2*)&BL[BIDX2(cur, ks, ntg0 + nt, lane, 0)];
                bh[nt][0] = __float_as_uint(wh.x); bh[nt][1] = __float_as_uint(wh.y);
                bl[nt][0] = __float_as_uint(wl.x); bl[nt][1] = __float_as_uint(wl.y);
            }
#pragma unroll
            for (int mt = 0; mt < 2; mt++)
#pragma unroll
                for (int nt = 0; nt < 4; nt++) {
                    mma8(acc[mt][nt], al[mt], bh[nt]);
                    mma8(acc[mt][nt], ah[mt], bl[nt]);
                    mma8(acc[mt][nt], ah[mt], bh[nt]);
                }
        }

        if (it + 1 < nkt) {
            int nxt = cur ^ 1;
            int ab = AIDX(nxt, aks, amt, arp, alb, asub);
            float h0 = tf32_rna(aR.x), h1 = tf32_rna(aR.y), h2 = tf32_rna(aR.z), h3 = tf32_rna(aR.w);
            AH[ab + 0] = h0; AH[ab + 2] = h1; AH[ab + 4] = h2; AH[ab + 6] = h3;
            AL[ab + 0] = tf32_rna(aR.x - h0); AL[ab + 2] = tf32_rna(aR.y - h1);
            AL[ab + 4] = tf32_rna(aR.z - h2); AL[ab + 6] = tf32_rna(aR.w - h3);
            cp_wait0();
            __syncthreads();
        }
    }

    int g = lane >> 2, c = lane & 3;
    int mb = (wid >> 2) * 32, nb = (wid & 3) * 32;
#pragma unroll
    for (int mt = 0; mt < 2; mt++) {
        int r0 = m0 + mb + mt * 16 + g;
        int r1 = r0 + 8;
#pragma unroll
        for (int nt = 0; nt < 4; nt++) {
            int col = nb + nt * 8 + 2 * c;
            if (r0 < NN)
                *(float2*)&myart[(size_t)r0 * H + col] = make_float2(acc[mt][nt][0], acc[mt][nt][1]);
            if (r1 < NN)
                *(float2*)&myart[(size_t)r1 * H + col] = make_float2(acc[mt][nt][2], acc[mt][nt][3]);
        }
    }
}

// ---------------- reduce: out = leaky(Σ part + bx + cnt*bmx) [+resid] ----------------
__global__ void reduce_out(const float* __restrict__ part,
                           const float* __restrict__ bx, const float* __restrict__ bmx,
                           const float* __restrict__ cntf, const float* __restrict__ resid,
                           float* __restrict__ xout)
{
    int idx = blockIdx.x * blockDim.x + threadIdx.x;
    if (idx >= NN * (H / 4)) return;
    int n = idx >> 5;
    int c4 = (idx & 31) << 2;
    float cf = cntf[n];
    float4 p0 = ((const float4*)part)[idx];
    float4 p1 = ((const float4*)(part + (size_t)NN * H))[idx];
    float4 p2 = ((const float4*)(part + (size_t)2 * NN * H))[idx];
    float4 p3 = ((const float4*)(part + (size_t)3 * NN * H))[idx];
    float4 b  = *(const float4*)&bx[c4];
    float4 bm = *(const float4*)&bmx[c4];
    float4 o;
    o.x = leaky((p0.x + p1.x) + (p2.x + p3.x) + b.x + cf * bm.x);
    o.y = leaky((p0.y + p1.y) + (p2.y + p3.y) + b.y + cf * bm.y);
    o.z = leaky((p0.z + p1.z) + (p2.z + p3.z) + b.z + cf * bm.z);
    o.w = leaky((p0.w + p1.w) + (p2.w + p3.w) + b.w + cf * bm.w);
    if (resid) {
        float4 r = ((const float4*)resid)[idx];
        o.x = leaky(r.x + o.x); o.y = leaky(r.y + o.y);
        o.z = leaky(r.z + o.z); o.w = leaky(r.w + o.w);
    }
    ((float4*)xout)[idx] = o;
}

// ---------------- launch ----------------
extern "C" void kernel_launch(void* const* d_in, const int* in_sizes, int n_in,
                              void* d_out, int out_size) {
    const float* x   = (const float*)d_in[0];
    const float* pos = (const float*)d_in[1];
    const int*   ei  = (const int*)d_in[2];
    const float* ea  = (const float*)d_in[3];
    const float* Wm  = (const float*)d_in[4];
    const float* bm  = (const float*)d_in[5];
    // d_in[6] = Wp, d_in[7] = bp : dead code (alpha unused)
    const float* Wx  = (const float*)d_in[8];
    const float* bx  = (const float*)d_in[9];
    float* out = (float*)d_out;

    float *F, *xb, *pb, *part, *cntf, *Wsp, *bmx;
    int *cnt, *rowbeg, *cursor, *colj, *eid, *total;
    cudaGetSymbolAddress((void**)&F,      g_F);
    cudaGetSymbolAddress((void**)&xb,     g_xbuf);
    cudaGetSymbolAddress((void**)&pb,     g_posbuf);
    cudaGetSymbolAddress((void**)&part,   g_part);
    cudaGetSymbolAddress((void**)&cnt,    g_cnt);
    cudaGetSymbolAddress((void**)&rowbeg, g_rowbeg);
    cudaGetSymbolAddress((void**)&cursor, g_cursor);
    cudaGetSymbolAddress((void**)&colj,   g_colj);
    cudaGetSymbolAddress((void**)&eid,    g_eid);
    cudaGetSymbolAddress((void**)&cntf,   g_cntf);
    cudaGetSymbolAddress((void**)&total,  g_total);
    cudaGetSymbolAddress((void**)&Wsp,    g_Wsplit);
    cudaGetSymbolAddress((void**)&bmx,    g_bmx);

    cnt_hist<<<(NE + 255) / 256, 256>>>(ei, cnt);
    alloc_rows<<<(NN + 255) / 256, 256>>>(cnt, rowbeg, cursor, cntf, total);
    build_csr<<<(NE + 255) / 256, 256>>>(ei, cursor, colj, eid, total);

    const size_t WLS = (size_t)NKT * 4 * 1024;
    const float* curx = x;
    const float* curp = pos;
    for (int l = 0; l < NLAYER; l++) {
        bool last = (l == NLAYER - 1);
        float* nx = last ? out : xb + (size_t)(l & 1) * NN * H;
        float* np = last ? out + (size_t)NN * H : pb + (size_t)(l & 1) * NN * 3;

        csr_layer<<<(NN * 32 + 127) / 128, 128>>>(curx, curp, rowbeg, colj, cntf, F, np);
        if (l == 0) {
            ea_csr<<<(NN * 16 + 255) / 256, 256>>>(rowbeg, cntf, eid, ea, F);
            dim3 gp(NLAYER, KA + 1);
            prep_weights<<<gp, 128>>>(Wm, bm, Wx, Wsp, bmx);
        }
        dim3 gg((NN + 63) / 64, NSPLIT);
        fused_layer_gemm<<<gg, 256>>>(curx, F, Wsp + (size_t)l * WLS, part);
        reduce_out<<<(NN * (H / 4) + 255) / 256, 256>>>(part, bx + (size_t)l * H,
                                                        bmx + l * H, cntf,
                                                        last ? x : nullptr, nx);
        curx = nx;
        curp = np;
    }
}

// round 17
// speedup vs baseline: 2.0567x; 1.0887x over previous
#include <cuda_runtime.h>
#include <cstdint>

#define NN     10000
#define NE     320000
#define H      128
#define HID    256
#define KM     336   // 2*H + 64 + 16  (F row width)
#define KX     384   // H + HID
#define KA     464   // H + KM         (fused GEMM K)
#define NSTEP  64
#define NLAYER 4
#define NKT    29    // KA/16
#define NSPLIT 4     // split-K factor
#define FAR2   171.61f   // (13.1)^2 : beyond this, all soh underflow to 0

// ---------------- static device scratch ----------------
__device__ float g_F[(size_t)NN * KM];             // [cnt*x | Σx_j | Σsoh | Σea]
__device__ float g_xbuf[2][(size_t)NN * H];
__device__ float g_posbuf[2][(size_t)NN * 3];
__device__ float g_part[NSPLIT][(size_t)NN * H];   // split-K partials
__device__ int   g_cnt[NN];
__device__ int   g_rowbeg[NN];
__device__ int   g_cursor[NN];
__device__ int   g_colj[NE];
__device__ int   g_eid[NE];
__device__ float g_cntf[NN];
__device__ int   g_total[1];
__device__ float g_Wsplit[(size_t)NLAYER * NKT * 4 * 1024];
__device__ float g_bmx[NLAYER * H];                // bm @ Wx2

__constant__ int c_kt0[NSPLIT + 1] = {0, 8, 15, 22, 29};

typedef unsigned long long u64w;
__device__ __forceinline__ float leaky(float v) { return v > 0.f ? v : 0.01f * v; }
__device__ __forceinline__ float tf32_rna(float x) {
    float r; asm("cvt.rna.tf32.f32 %0, %1;" : "=f"(r) : "f"(x)); return r;
}
// ---- packed f32x2 (sm_103a) ----
__device__ __forceinline__ u64w fma_x2(u64w a, u64w b, u64w c) {
    u64w r; asm("fma.rn.f32x2 %0, %1, %2, %3;" : "=l"(r) : "l"(a), "l"(b), "l"(c)); return r;
}
__device__ __forceinline__ u64w mul_x2(u64w a, u64w b) {
    u64w r; asm("mul.rn.f32x2 %0, %1, %2;" : "=l"(r) : "l"(a), "l"(b)); return r;
}
__device__ __forceinline__ u64w add_x2(u64w a, u64w b) {
    u64w r; asm("add.rn.f32x2 %0, %1, %2;" : "=l"(r) : "l"(a), "l"(b)); return r;
}
__device__ __forceinline__ u64w pk2(float lo, float hi) {
    u64w r; asm("mov.b64 %0, {%1, %2};" : "=l"(r) : "f"(lo), "f"(hi)); return r;
}
__device__ __forceinline__ float2 unpk(u64w v) {
    float lo, hi; asm("mov.b64 {%0, %1}, %2;" : "=f"(lo), "=f"(hi) : "l"(v));
    return make_float2(lo, hi);
}
__device__ __forceinline__ void mma8(float* d, const uint32_t* a, const uint32_t* b) {
    asm volatile(
        "mma.sync.aligned.m16n8k8.row.col.f32.tf32.tf32.f32 "
        "{%0,%1,%2,%3}, {%4,%5,%6,%7}, {%8,%9}, {%0,%1,%2,%3};"
        : "+f"(d[0]), "+f"(d[1]), "+f"(d[2]), "+f"(d[3])
        : "r"(a[0]), "r"(a[1]), "r"(a[2]), "r"(a[3]), "r"(b[0]), "r"(b[1]));
}
__device__ __forceinline__ void cp16(uint32_t smem, const float* gmem) {
    asm volatile("cp.async.cg.shared.global [%0], [%1], 16;" :: "r"(smem), "l"(gmem) : "memory");
}
__device__ __forceinline__ void cp_commit() {
    asm volatile("cp.async.commit_group;" ::: "memory");
}
__device__ __forceinline__ void cp_wait0() {
    asm volatile("cp.async.wait_group 0;" ::: "memory");
}

// ---------------- preamble kernels ----------------
__global__ void cnt_hist(const int* __restrict__ ei, int* __restrict__ cnt) {
    int e = blockIdx.x * blockDim.x + threadIdx.x;
    if (e < NE) atomicAdd(&cnt[ei[e]], 1);
}

__global__ void alloc_rows(int* __restrict__ cnt, int* __restrict__ rowbeg,
                           int* __restrict__ cursor, float* __restrict__ cntf,
                           int* __restrict__ total) {
    int n = blockIdx.x * blockDim.x + threadIdx.x;
    int lane = threadIdx.x & 31;
    int v = (n < NN) ? cnt[n] : 0;
    int sc = v;
#pragma unroll
    for (int o = 1; o < 32; o <<= 1) {
        int u = __shfl_up_sync(0xffffffffu, sc, o);
        if (lane >= o) sc += u;
    }
    int wsum = __shfl_sync(0xffffffffu, sc, 31);
    int base = 0;
    if (lane == 0) base = atomicAdd(total, wsum);
    base = __shfl_sync(0xffffffffu, base, 0);
    int beg = base + sc - v;
    if (n < NN) {
        rowbeg[n] = beg; cursor[n] = beg; cntf[n] = (float)v;
        cnt[n] = 0;                                  // self-clean
    }
}

__global__ void build_csr(const int* __restrict__ ei, int* __restrict__ cursor,
                          int* __restrict__ colj, int* __restrict__ eid,
                          int* __restrict__ total) {
    int e = blockIdx.x * blockDim.x + threadIdx.x;
    if (e == 0) total[0] = 0;
    if (e < NE) {
        int p = atomicAdd(&cursor[ei[e]], 1);
        colj[p] = ei[NE + e];
        eid[p] = e;
    }
}

__global__ void ea_csr(const int* __restrict__ rowbeg, const float* __restrict__ cntf,
                       const int* __restrict__ eid, const float* __restrict__ ea,
                       float* __restrict__ F) {
    int gw = (blockIdx.x * blockDim.x + threadIdx.x) >> 4;
    int l = threadIdx.x & 15;
    if (gw >= NN) return;
    int beg = rowbeg[gw], end = beg + (int)cntf[gw];
    float s = 0.f;
    float v0 = 0.f, v1 = 0.f;
    if (beg < end)     v0 = ea[(size_t)eid[beg] * 16 + l];
    if (beg + 1 < end) v1 = ea[(size_t)eid[beg + 1] * 16 + l];
    for (int k = beg; k < end; k++) {
        float v = v0;
        v0 = v1;
        v1 = (k + 2 < end) ? ea[(size_t)eid[k + 2] * 16 + l] : 0.f;
        s += v;
    }
    F[(size_t)gw * KM + 320 + l] = s;
}

__global__ void prep_weights(const float* __restrict__ Wm, const float* __restrict__ bm,
                             const float* __restrict__ Wx,
                             float* __restrict__ Wsplit, float* __restrict__ bmx) {
    int l = blockIdx.x, y = blockIdx.y, n = threadIdx.x;
    const float* WxL = Wx + (size_t)l * KX * H;
    if (y < KA) {
        float w;
        if (y < H) {
            w = WxL[(size_t)y * H + n];
        } else {
            int r = y - H;
            const float* wm = Wm + (size_t)l * KM * HID + (size_t)r * HID;
            float s = 0.f;
#pragma unroll 8
            for (int h = 0; h < HID; h++) s += wm[h] * WxL[(size_t)(H + h) * H + n];
            w = s;
        }
        float hi = tf32_rna(w);
        float lo = tf32_rna(w - hi);
        int kt = y >> 4, kin = y & 15;
        int ks = kin >> 3, kk = kin & 7;
        int lane = ((n & 7) << 2) | (kk & 3);
        int reg = kk >> 2;
        int nt = n >> 3;
        size_t base = (((size_t)l * NKT + kt) * 4 + ks) * 1024 + nt * 64 + lane * 2 + reg;
        Wsplit[base] = hi;
        Wsplit[base + 2048] = lo;
    } else {
        const float* bmL = bm + (size_t)l * HID;
        float s = 0.f;
#pragma unroll 8
        for (int h = 0; h < HID; h++) s += bmL[h] * WxL[(size_t)(H + h) * H + n];
        bmx[l * H + n] = s;
    }
}

// ---------------- per-layer CSR kernel: packed f32x2 + warp-uniform far-skip ----------------
__global__ __launch_bounds__(128) void csr_layer(
    const float* __restrict__ x, const float* __restrict__ pos,
    const int* __restrict__ rowbeg, const int* __restrict__ colj,
    const float* __restrict__ cntf, float* __restrict__ F, float* __restrict__ npos)
{
    int w = (blockIdx.x * blockDim.x + threadIdx.x) >> 5;
    int lane = threadIdx.x & 31;
    if (w >= NN) return;
    int beg = rowbeg[w];
    float cf = cntf[w];
    int end = beg + (int)cf;
    float4 xi = ((const float4*)(x + (size_t)w * H))[lane];
    u64w xi01 = pk2(xi.x, xi.y), xi23 = pk2(xi.z, xi.w);
    const u64w NEG1 = pk2(-1.f, -1.f);
    u64w xs01 = pk2(0.f, 0.f), xs23 = pk2(0.f, 0.f);
    float s0 = 0.f, s1 = 0.f, ps = 0.f;
    const float step = 10.f / 63.f;
    float c0 = (2 * lane) * step, c1 = (2 * lane + 1) * step;

    int kend2 = beg + (((end - beg) >> 1) << 1);

    ulonglong2 van = make_ulonglong2(0ull, 0ull), vbn = van;
    float pan = 0.f, pbn = 0.f;
    if (beg < kend2) {
        int j0 = colj[beg], j1 = colj[beg + 1];
        van = ((const ulonglong2*)(x + (size_t)j0 * H))[lane];
        vbn = ((const ulonglong2*)(x + (size_t)j1 * H))[lane];
        if (lane < 3) { pan = pos[j0 * 3 + lane]; pbn = pos[j1 * 3 + lane]; }
    }

    for (int k = beg; k < kend2; k += 2) {
        ulonglong2 va = van, vb = vbn;
        float pa = pan, pb = pbn;
        if (k + 2 < kend2) {
            int j0 = colj[k + 2], j1 = colj[k + 3];
            van = ((const ulonglong2*)(x + (size_t)j0 * H))[lane];
            vbn = ((const ulonglong2*)(x + (size_t)j1 * H))[lane];
            if (lane < 3) { pan = pos[j0 * 3 + lane]; pbn = pos[j1 * 3 + lane]; }
        }
        u64w da01 = fma_x2(xi01, NEG1, va.x);
        u64w da23 = fma_x2(xi23, NEG1, va.y);
        u64w db01 = fma_x2(xi01, NEG1, vb.x);
        u64w db23 = fma_x2(xi23, NEG1, vb.y);
        u64w qa = mul_x2(da01, da01); qa = fma_x2(da23, da23, qa);
        u64w qb = mul_x2(db01, db01); qb = fma_x2(db23, db23, qb);
        float2 fa = unpk(qa), fb = unpk(qb);
        float e0 = fa.x + fa.y;
        float e1 = fb.x + fb.y;
        e0 += __shfl_xor_sync(0xffffffffu, e0, 16);
        e1 += __shfl_xor_sync(0xffffffffu, e1, 16);
        float v = (lane & 16) ? e1 : e0;
        v += __shfl_xor_sync(0xffffffffu, v, 8);
        v += __shfl_xor_sync(0xffffffffu, v, 4);
        v += __shfl_xor_sync(0xffffffffu, v, 2);
        v += __shfl_xor_sync(0xffffffffu, v, 1);
        float vo = __shfl_xor_sync(0xffffffffu, v, 16);
        float sum0 = (lane & 16) ? vo : v;
        float sum1 = (lane & 16) ? v : vo;
        // warp-uniform far-skip: soh underflows to 0 beyond FAR2
        if (sum0 < FAR2) {
            float r0 = sqrtf(sum0);
            float u0 = r0 - c0, u1 = r0 - c1;
            s0 += __expf(-10.f * u0 * u0);
            s1 += __expf(-10.f * u1 * u1);
        }
        if (sum1 < FAR2) {
            float r1 = sqrtf(sum1);
            float v0 = r1 - c0, v1 = r1 - c1;
            s0 += __expf(-10.f * v0 * v0);
            s1 += __expf(-10.f * v1 * v1);
        }
        xs01 = add_x2(xs01, add_x2(va.x, vb.x));
        xs23 = add_x2(xs23, add_x2(va.y, vb.y));
        ps += pa + pb;
    }
    if (kend2 < end) {                                 // odd tail
        int j0 = colj[kend2];
        ulonglong2 va = ((const ulonglong2*)(x + (size_t)j0 * H))[lane];
        float pa = 0.f;
        if (lane < 3) pa = pos[j0 * 3 + lane];
        u64w da01 = fma_x2(xi01, NEG1, va.x);
        u64w da23 = fma_x2(xi23, NEG1, va.y);
        u64w qa = mul_x2(da01, da01); qa = fma_x2(da23, da23, qa);
        float2 fa = unpk(qa);
        float e0 = fa.x + fa.y;
#pragma unroll
        for (int o = 16; o; o >>= 1) e0 += __shfl_xor_sync(0xffffffffu, e0, o);
        if (e0 < FAR2) {
            float r0 = sqrtf(e0);
            float u0 = r0 - c0, u1 = r0 - c1;
            s0 += __expf(-10.f * u0 * u0);
            s1 += __expf(-10.f * u1 * u1);
        }
        xs01 = add_x2(xs01, va.x);
        xs23 = add_x2(xs23, va.y);
        ps += pa;
    }

    float2 xsa = unpk(xs01), xsb = unpk(xs23);
    float* Fr = F + (size_t)w * KM;
    ((float4*)Fr)[lane]           = make_float4(cf * xi.x, cf * xi.y, cf * xi.z, cf * xi.w);
    ((float4*)(Fr + H))[lane]     = make_float4(xsa.x, xsa.y, xsb.x, xsb.y);
    ((float2*)(Fr + 2 * H))[lane] = make_float2(s0, s1);
    if (lane < 3) {
        float p = pos[w * 3 + lane];
        npos[w * 3 + lane] = p + (cf * p - ps) / fmaxf(cf, 1.f);
    }
}

// ---------------- fused layer GEMM (measured-good R15 form, untouched) ----------------
#define AIDX(buf,ks,mt,rp,lane,sub) ((((((buf)*2+(ks))*4+(mt))*2+(rp))*33 + (lane))*2 + (sub))
#define BIDX2(buf,ks,nt,lane,reg)   ((((buf)*2+(ks))*16+(nt))*68 + (lane)*2 + (reg))
__global__ __launch_bounds__(256, 2) void fused_layer_gemm(
    const float* __restrict__ x, const float* __restrict__ F,
    const float* __restrict__ Wsp, float* __restrict__ part)
{
    __shared__ __align__(16) float AH[2 * 2 * 4 * 2 * 33 * 2], AL[2 * 2 * 4 * 2 * 33 * 2];
    __shared__ __align__(16) float BH[2 * 2 * 16 * 68],        BL[2 * 2 * 16 * 68];

    int t = threadIdx.x;
    int m0 = blockIdx.x * 64;
    int ktb = blockIdx.y;
    int kt0 = c_kt0[ktb];
    int nkt = c_kt0[ktb + 1] - kt0;
    float* myart = part + (size_t)ktb * NN * H;

    int wid = t >> 5, lane = t & 31;
    int mtg0 = (wid >> 2) * 2;
    int ntg0 = (wid & 3) * 4;

    int am = t & 63, akq = (t >> 6) << 2;
    int aks = akq >> 3, arp = (akq >> 2) & 1;
    int amt = am >> 4, asub = (am >> 3) & 1, alb = (am & 7) << 2;
    int mm = m0 + am; if (mm >= NN) mm = NN - 1;
    const float* rowx = x + (size_t)mm * H;
    const float* rowF = F + (size_t)mm * KM - H;

    int bnt = (t >> 4) & 15, bpair = t & 15;
    uint32_t sBH = (uint32_t)__cvta_generic_to_shared(BH);
    uint32_t sBL = (uint32_t)__cvta_generic_to_shared(BL);
    uint32_t smo[2][2];
#pragma unroll
    for (int ks = 0; ks < 2; ks++)
#pragma unroll
        for (int b = 0; b < 2; b++)
            smo[ks][b] = (uint32_t)(BIDX2(b, ks, bnt, bpair * 2, 0) * 4);
    int gbase = bnt * 64 + bpair * 4;

    float acc[2][4][4];
#pragma unroll
    for (int i = 0; i < 2; i++)
#pragma unroll
        for (int j = 0; j < 4; j++)
#pragma unroll
            for (int q = 0; q < 4; q++) acc[i][j][q] = 0.f;

    float4 aR;
    {
        cp16(sBH + smo[0][0], Wsp + (kt0 * 4 + 0) * 1024 + gbase);
        cp16(sBH + smo[1][0], Wsp + (kt0 * 4 + 1) * 1024 + gbase);
        cp16(sBL + smo[0][0], Wsp + (kt0 * 4 + 2) * 1024 + gbase);
        cp16(sBL + smo[1][0], Wsp + (kt0 * 4 + 3) * 1024 + gbase);
        cp_commit();
        int k = kt0 * 16 + akq;
        aR = *(const float4*)((k < H ? rowx : rowF) + k);
        int ab = AIDX(0, aks, amt, arp, alb, asub);
        float h0 = tf32_rna(aR.x), h1 = tf32_rna(aR.y), h2 = tf32_rna(aR.z), h3 = tf32_rna(aR.w);
        AH[ab + 0] = h0; AH[ab + 2] = h1; AH[ab + 4] = h2; AH[ab + 6] = h3;
        AL[ab + 0] = tf32_rna(aR.x - h0); AL[ab + 2] = tf32_rna(aR.y - h1);
        AL[ab + 4] = tf32_rna(aR.z - h2); AL[ab + 6] = tf32_rna(aR.w - h3);
        cp_wait0();
    }
    __syncthreads();

    for (int it = 0; it < nkt; it++) {
        int cur = it & 1;
        if (it + 1 < nkt) {
            int nxt = cur ^ 1;
            int kt = kt0 + it + 1;
            cp16(sBH + smo[0][nxt], Wsp + (kt * 4 + 0) * 1024 + gbase);
            cp16(sBH + smo[1][nxt], Wsp + (kt * 4 + 1) * 1024 + gbase);
            cp16(sBL + smo[0][nxt], Wsp + (kt * 4 + 2) * 1024 + gbase);
            cp16(sBL + smo[1][nxt], Wsp + (kt * 4 + 3) * 1024 + gbase);
            cp_commit();
            int k = kt * 16 + akq;
            aR = *(const float4*)((k < H ? rowx : rowF) + k);
        }

#pragma unroll
        for (int ks = 0; ks < 2; ks++) {
            uint32_t ah[2][4], al[2][4], bh[4][2], bl[4][2];
#pragma unroll
            for (int mt = 0; mt < 2; mt++) {
                float2 h0 = *(const float2*)&AH[AIDX(cur, ks, mtg0 + mt, 0, lane, 0)];
                float2 h1 = *(const float2*)&AH[AIDX(cur, ks, mtg0 + mt, 1, lane, 0)];
                float2 l0 = *(const float2*)&AL[AIDX(cur, ks, mtg0 + mt, 0, lane, 0)];
                float2 l1 = *(const float2*)&AL[AIDX(cur, ks, mtg0 + mt, 1, lane, 0)];
                ah[mt][0] = __float_as_uint(h0.x); ah[mt][1] = __float_as_uint(h0.y);
                ah[mt][2] = __float_as_uint(h1.x); ah[mt][3] = __float_as_uint(h1.y);
                al[mt][0] = __float_as_uint(l0.x); al[mt][1] = __float_as_uint(l0.y);
                al[mt][2] = __float_as_uint(l1.x); al[mt][3] = __float_as_uint(l1.y);
            }
#pragma unroll
            for (int nt = 0; nt < 4; nt++) {
                float2 wh = *(const float2*)&BH[BIDX2(cur, ks, ntg0 + nt, lane, 0)];
                float2 wl = *(const float2*)&BL[BIDX2(cur, ks, ntg0 + nt, lane, 0)];
                bh[nt][0] = __float_as_uint(wh.x); bh[nt][1] = __float_as_uint(wh.y);
                bl[nt][0] = __float_as_uint(wl.x); bl[nt][1] = __float_as_uint(wl.y);
            }
#pragma unroll
            for (int mt = 0; mt < 2; mt++)
#pragma unroll
                for (int nt = 0; nt < 4; nt++) {
                    mma8(acc[mt][nt], al[mt], bh[nt]);
                    mma8(acc[mt][nt], ah[mt], bl[nt]);
                    mma8(acc[mt][nt], ah[mt], bh[nt]);
                }
        }

        if (it + 1 < nkt) {
            int nxt = cur ^ 1;
            int ab = AIDX(nxt, aks, amt, arp, alb, asub);
            float h0 = tf32_rna(aR.x), h1 = tf32_rna(aR.y), h2 = tf32_rna(aR.z), h3 = tf32_rna(aR.w);
            AH[ab + 0] = h0; AH[ab + 2] = h1; AH[ab + 4] = h2; AH[ab + 6] = h3;
            AL[ab + 0] = tf32_rna(aR.x - h0); AL[ab + 2] = tf32_rna(aR.y - h1);
            AL[ab + 4] = tf32_rna(aR.z - h2); AL[ab + 6] = tf32_rna(aR.w - h3);
            cp_wait0();
            __syncthreads();
        }
    }

    int g = lane >> 2, c = lane & 3;
    int mb = (wid >> 2) * 32, nb = (wid & 3) * 32;
#pragma unroll
    for (int mt = 0; mt < 2; mt++) {
        int r0 = m0 + mb + mt * 16 + g;
        int r1 = r0 + 8;
#pragma unroll
        for (int nt = 0; nt < 4; nt++) {
            int col = nb + nt * 8 + 2 * c;
            if (r0 < NN)
                *(float2*)&myart[(size_t)r0 * H + col] = make_float2(acc[mt][nt][0], acc[mt][nt][1]);
            if (r1 < NN)
                *(float2*)&myart[(size_t)r1 * H + col] = make_float2(acc[mt][nt][2], acc[mt][nt][3]);
        }
    }
}

// ---------------- reduce: out = leaky(Σ part + bx + cnt*bmx) [+resid] ----------------
__global__ void reduce_out(const float* __restrict__ part,
                           const float* __restrict__ bx, const float* __restrict__ bmx,
                           const float* __restrict__ cntf, const float* __restrict__ resid,
                           float* __restrict__ xout)
{
    int idx = blockIdx.x * blockDim.x + threadIdx.x;
    if (idx >= NN * (H / 4)) return;
    int n = idx >> 5;
    int c4 = (idx & 31) << 2;
    float cf = cntf[n];
    float4 p0 = ((const float4*)part)[idx];
    float4 p1 = ((const float4*)(part + (size_t)NN * H))[idx];
    float4 p2 = ((const float4*)(part + (size_t)2 * NN * H))[idx];
    float4 p3 = ((const float4*)(part + (size_t)3 * NN * H))[idx];
    float4 b  = *(const float4*)&bx[c4];
    float4 bm = *(const float4*)&bmx[c4];
    float4 o;
    o.x = leaky((p0.x + p1.x) + (p2.x + p3.x) + b.x + cf * bm.x);
    o.y = leaky((p0.y + p1.y) + (p2.y + p3.y) + b.y + cf * bm.y);
    o.z = leaky((p0.z + p1.z) + (p2.z + p3.z) + b.z + cf * bm.z);
    o.w = leaky((p0.w + p1.w) + (p2.w + p3.w) + b.w + cf * bm.w);
    if (resid) {
        float4 r = ((const float4*)resid)[idx];
        o.x = leaky(r.x + o.x); o.y = leaky(r.y + o.y);
        o.z = leaky(r.z + o.z); o.w = leaky(r.w + o.w);
    }
    ((float4*)xout)[idx] = o;
}

// ---------------- launch ----------------
extern "C" void kernel_launch(void* const* d_in, const int* in_sizes, int n_in,
                              void* d_out, int out_size) {
    const float* x   = (const float*)d_in[0];
    const float* pos = (const float*)d_in[1];
    const int*   ei  = (const int*)d_in[2];
    const float* ea  = (const float*)d_in[3];
    const float* Wm  = (const float*)d_in[4];
    const float* bm  = (const float*)d_in[5];
    // d_in[6] = Wp, d_in[7] = bp : dead code (alpha unused)
    const float* Wx  = (const float*)d_in[8];
    const float* bx  = (const float*)d_in[9];
    float* out = (float*)d_out;

    float *F, *xb, *pb, *part, *cntf, *Wsp, *bmx;
    int *cnt, *rowbeg, *cursor, *colj, *eid, *total;
    cudaGetSymbolAddress((void**)&F,      g_F);
    cudaGetSymbolAddress((void**)&xb,     g_xbuf);
    cudaGetSymbolAddress((void**)&pb,     g_posbuf);
    cudaGetSymbolAddress((void**)&part,   g_part);
    cudaGetSymbolAddress((void**)&cnt,    g_cnt);
    cudaGetSymbolAddress((void**)&rowbeg, g_rowbeg);
    cudaGetSymbolAddress((void**)&cursor, g_cursor);
    cudaGetSymbolAddress((void**)&colj,   g_colj);
    cudaGetSymbolAddress((void**)&eid,    g_eid);
    cudaGetSymbolAddress((void**)&cntf,   g_cntf);
    cudaGetSymbolAddress((void**)&total,  g_total);
    cudaGetSymbolAddress((void**)&Wsp,    g_Wsplit);
    cudaGetSymbolAddress((void**)&bmx,    g_bmx);

    cnt_hist<<<(NE + 255) / 256, 256>>>(ei, cnt);
    alloc_rows<<<(NN + 255) / 256, 256>>>(cnt, rowbeg, cursor, cntf, total);
    build_csr<<<(NE + 255) / 256, 256>>>(ei, cursor, colj, eid, total);

    const size_t WLS = (size_t)NKT * 4 * 1024;
    const float* curx = x;
    const float* curp = pos;
    for (int l = 0; l < NLAYER; l++) {
        bool last = (l == NLAYER - 1);
        float* nx = last ? out : xb + (size_t)(l & 1) * NN * H;
        float* np = last ? out + (size_t)NN * H : pb + (size_t)(l & 1) * NN * 3;

        csr_layer<<<(NN * 32 + 127) / 128, 128>>>(curx, curp, rowbeg, colj, cntf, F, np);
        if (l == 0) {
            ea_csr<<<(NN * 16 + 255) / 256, 256>>>(rowbeg, cntf, eid, ea, F);
            dim3 gp(NLAYER, KA + 1);
            prep_weights<<<gp, 128>>>(Wm, bm, Wx, Wsp, bmx);
        }
        dim3 gg((NN + 63) / 64, NSPLIT);
        fused_layer_gemm<<<gg, 256>>>(curx, F, Wsp + (size_t)l * WLS, part);
        reduce_out<<<(NN * (H / 4) + 255) / 256, 256>>>(part, bx + (size_t)l * H,
                                                        bmx + l * H, cntf,
                                                        last ? x : nullptr, nx);
        curx = nx;
        curp = np;
    }
}